// round 2
// baseline (speedup 1.0000x reference)
#include <cuda_runtime.h>
#include <cstdint>

#define Bb 8
#define Tt 1024
#define Uu 1024
#define Hh 8
#define Dd 128
#define NEGV  -4294967295.0f
#define NEGI  -3.0e38f
#define SCALE 0.08838834764831845f  /* 1/sqrt(128) */

// ---------------- scratch (static device memory; no allocations) ----------------
__device__ float g_Q[Bb * Tt * Uu];
__device__ float g_K[Bb * Tt * Uu];
__device__ float g_V[Bb * Tt * Uu];
__device__ float g_AO[Bb * Tt * Uu];
__device__ float g_qmask[Bb * Tt];
__device__ float g_kmask[Bb * Tt];

// ---------------- 128x128x8 SGEMM + bias + ReLU --------------------------------
// C[m][n] = relu(A[m][k] @ W[k][n] + bias[n]);  M=8192, N=K=1024
__global__ void __launch_bounds__(256) gemm_relu_kernel(
    const float* __restrict__ A, const float* __restrict__ W,
    const float* __restrict__ bias, int which) {
    float* C = (which == 0) ? g_Q : (which == 1) ? g_K : g_V;

    __shared__ float As[8][128];
    __shared__ float Bs[8][128];
    const int tid = threadIdx.x;
    const int m0 = blockIdx.x * 128, n0 = blockIdx.y * 128;
    const int tx = tid & 15, ty = tid >> 4;
    const int aRow = tid >> 1, aCol = (tid & 1) * 4;
    const int bRow = tid >> 5, bCol = (tid & 31) * 4;

    float acc[8][8] = {};
    for (int k0 = 0; k0 < 1024; k0 += 8) {
        float4 av = *(const float4*)(A + (size_t)(m0 + aRow) * 1024 + k0 + aCol);
        As[aCol + 0][aRow] = av.x;
        As[aCol + 1][aRow] = av.y;
        As[aCol + 2][aRow] = av.z;
        As[aCol + 3][aRow] = av.w;
        *(float4*)&Bs[bRow][bCol] =
            *(const float4*)(W + (size_t)(k0 + bRow) * 1024 + n0 + bCol);
        __syncthreads();
#pragma unroll
        for (int kk = 0; kk < 8; kk++) {
            float a[8], bb[8];
            *(float4*)&a[0]  = *(float4*)&As[kk][ty * 8];
            *(float4*)&a[4]  = *(float4*)&As[kk][ty * 8 + 4];
            *(float4*)&bb[0] = *(float4*)&Bs[kk][tx * 8];
            *(float4*)&bb[4] = *(float4*)&Bs[kk][tx * 8 + 4];
#pragma unroll
            for (int i = 0; i < 8; i++)
#pragma unroll
                for (int j = 0; j < 8; j++)
                    acc[i][j] += a[i] * bb[j];
        }
        __syncthreads();
    }
#pragma unroll
    for (int i = 0; i < 8; i++) {
        float* Cp = C + (size_t)(m0 + ty * 8 + i) * 1024 + n0 + tx * 8;
#pragma unroll
        for (int j = 0; j < 8; j += 4) {
            float4 bv = *(const float4*)(bias + n0 + tx * 8 + j);
            float4 o;
            o.x = fmaxf(acc[i][j + 0] + bv.x, 0.0f);
            o.y = fmaxf(acc[i][j + 1] + bv.y, 0.0f);
            o.z = fmaxf(acc[i][j + 2] + bv.z, 0.0f);
            o.w = fmaxf(acc[i][j + 3] + bv.w, 0.0f);
            *(float4*)(Cp + j) = o;
        }
    }
}

// ---------------- mask row sums: sign(abs(rowsum)) ------------------------------
__global__ void __launch_bounds__(256) mask_kernel(
    const float* __restrict__ queries, const float* __restrict__ keys) {
    __shared__ float red[8];
    const int row = blockIdx.x;
    const float* src = (blockIdx.y == 0) ? queries : keys;
    float* dst = (blockIdx.y == 0) ? g_qmask : g_kmask;
    const int tid = threadIdx.x;
    float4 v = ((const float4*)(src + (size_t)row * 1024))[tid];
    float s = v.x + v.y + v.z + v.w;
#pragma unroll
    for (int off = 16; off; off >>= 1) s += __shfl_xor_sync(0xffffffffu, s, off);
    if ((tid & 31) == 0) red[tid >> 5] = s;
    __syncthreads();
    if (tid == 0) {
        float t = 0.f;
#pragma unroll
        for (int w = 0; w < 8; w++) t += red[w];
        dst[row] = (t != 0.0f) ? 1.0f : 0.0f;
    }
}

// ---------------- fused causal flash attention (fp32) ---------------------------
// grid (Tq/64, B, H), 256 threads. warp owns 8 S-rows; lane owns S-cols {lane, lane+32}
// and O-cols {4*lane..4*lane+3}.
struct ASmem {
    float Qs[64][132];
    float Ks[64][132];
    float Vs[64][132];
    float Ps[64][65];
};

__global__ void __launch_bounds__(256, 1) attn_kernel() {
    extern __shared__ char raw[];
    ASmem& sm = *(ASmem*)raw;
    const int qt = blockIdx.x, b = blockIdx.y, h = blockIdx.z;
    const int tid = threadIdx.x;
    const int warp = tid >> 5, lane = tid & 31;

    const float* Qg = g_Q + ((size_t)b * Tt + qt * 64) * Uu + h * Dd;
    const float* Kg = g_K + (size_t)b * Tt * Uu + h * Dd;
    const float* Vg = g_V + (size_t)b * Tt * Uu + h * Dd;
    const float* km = g_kmask + b * Tt;

    // load Q tile (64 rows x 128 cols)
    for (int idx = tid; idx < 64 * 32; idx += 256) {
        int r = idx >> 5, c4 = (idx & 31) * 4;
        *(float4*)&sm.Qs[r][c4] = *(const float4*)(Qg + (size_t)r * Uu + c4);
    }

    float Oc[8][4] = {};
    float mrow[8], lrow[8];
#pragma unroll
    for (int i = 0; i < 8; i++) { mrow[i] = NEGI; lrow[i] = 0.0f; }

    for (int kt = 0; kt <= qt; kt++) {
        __syncthreads();
        for (int idx = tid; idx < 64 * 32; idx += 256) {
            int r = idx >> 5, c4 = (idx & 31) * 4;
            *(float4*)&sm.Ks[r][c4] = *(const float4*)(Kg + (size_t)(kt * 64 + r) * Uu + c4);
            *(float4*)&sm.Vs[r][c4] = *(const float4*)(Vg + (size_t)(kt * 64 + r) * Uu + c4);
        }
        __syncthreads();

        // S = Q @ K^T  (rows 8*warp+i, cols lane and lane+32; conflict-free LDS phases)
        float s[8][2] = {};
#pragma unroll 4
        for (int kk = 0; kk < 128; kk += 4) {
            float4 b0 = *(float4*)&sm.Ks[lane][kk];
            float4 b1 = *(float4*)&sm.Ks[lane + 32][kk];
#pragma unroll
            for (int i = 0; i < 8; i++) {
                float4 a = *(float4*)&sm.Qs[8 * warp + i][kk];
                s[i][0] += a.x * b0.x + a.y * b0.y + a.z * b0.z + a.w * b0.w;
                s[i][1] += a.x * b1.x + a.y * b1.y + a.z * b1.z + a.w * b1.w;
            }
        }

        // scale + key mask + causal mask
        const int kg0 = kt * 64 + lane;
        const int kg1 = kg0 + 32;
        const float km0 = km[kg0], km1 = km[kg1];
#pragma unroll
        for (int i = 0; i < 8; i++) {
            const int qg = qt * 64 + 8 * warp + i;
            float v0 = s[i][0] * SCALE;
            float v1 = s[i][1] * SCALE;
            if (km0 == 0.0f || kg0 > qg) v0 = NEGV;
            if (km1 == 0.0f || kg1 > qg) v1 = NEGV;
            s[i][0] = v0; s[i][1] = v1;
        }

        // online softmax per row (full-warp butterfly; all lanes get the result)
#pragma unroll
        for (int i = 0; i < 8; i++) {
            float mx = fmaxf(s[i][0], s[i][1]);
#pragma unroll
            for (int off = 16; off; off >>= 1)
                mx = fmaxf(mx, __shfl_xor_sync(0xffffffffu, mx, off));
            float mnew = fmaxf(mrow[i], mx);
            float alpha = __expf(mrow[i] - mnew);
            float p0 = __expf(s[i][0] - mnew);
            float p1 = __expf(s[i][1] - mnew);
            float ps = p0 + p1;
#pragma unroll
            for (int off = 16; off; off >>= 1)
                ps += __shfl_xor_sync(0xffffffffu, ps, off);
            lrow[i] = lrow[i] * alpha + ps;
            mrow[i] = mnew;
            sm.Ps[8 * warp + i][lane]      = p0;
            sm.Ps[8 * warp + i][lane + 32] = p1;
#pragma unroll
            for (int j = 0; j < 4; j++) Oc[i][j] *= alpha;
        }
        __syncthreads();

        // O += P @ V  (O cols 4*lane+j; conflict-free)
#pragma unroll 4
        for (int kk = 0; kk < 64; kk++) {
            float4 v = *(float4*)&sm.Vs[kk][4 * lane];
#pragma unroll
            for (int i = 0; i < 8; i++) {
                float p = sm.Ps[8 * warp + i][kk];
                Oc[i][0] += p * v.x;
                Oc[i][1] += p * v.y;
                Oc[i][2] += p * v.z;
                Oc[i][3] += p * v.w;
            }
        }
    }

    // normalize, query mask, store
    float* AOg = g_AO + ((size_t)b * Tt + qt * 64) * Uu + h * Dd;
#pragma unroll
    for (int i = 0; i < 8; i++) {
        const int qg = qt * 64 + 8 * warp + i;
        const float inv = g_qmask[b * Tt + qg] / lrow[i];
        float4 o;
        o.x = Oc[i][0] * inv;
        o.y = Oc[i][1] * inv;
        o.z = Oc[i][2] * inv;
        o.w = Oc[i][3] * inv;
        *(float4*)(AOg + (size_t)(8 * warp + i) * Uu + 4 * lane) = o;
    }
}

// ---------------- residual + LayerNorm ------------------------------------------
__global__ void __launch_bounds__(256) ln_kernel(
    const float* __restrict__ Qin, const float* __restrict__ gamma,
    const float* __restrict__ beta, float* __restrict__ out) {
    __shared__ float red[2][8];
    const int row = blockIdx.x, tid = threadIdx.x;
    float4 a = ((const float4*)(g_AO + (size_t)row * 1024))[tid];
    float4 q = ((const float4*)(Qin + (size_t)row * 1024))[tid];
    float4 x;
    x.x = a.x + q.x; x.y = a.y + q.y; x.z = a.z + q.z; x.w = a.w + q.w;
    float s  = x.x + x.y + x.z + x.w;
    float ss = x.x * x.x + x.y * x.y + x.z * x.z + x.w * x.w;
#pragma unroll
    for (int off = 16; off; off >>= 1) {
        s  += __shfl_xor_sync(0xffffffffu, s, off);
        ss += __shfl_xor_sync(0xffffffffu, ss, off);
    }
    if ((tid & 31) == 0) { red[0][tid >> 5] = s; red[1][tid >> 5] = ss; }
    __syncthreads();
    s = 0.f; ss = 0.f;
#pragma unroll
    for (int w = 0; w < 8; w++) { s += red[0][w]; ss += red[1][w]; }
    const float mu = s * (1.0f / 1024.0f);
    const float var = ss * (1.0f / 1024.0f) - mu * mu;
    const float rstd = rsqrtf(var + 1e-5f);
    float4 g  = ((const float4*)gamma)[tid];
    float4 be = ((const float4*)beta)[tid];
    float4 o;
    o.x = (x.x - mu) * rstd * g.x + be.x;
    o.y = (x.y - mu) * rstd * g.y + be.y;
    o.z = (x.z - mu) * rstd * g.z + be.z;
    o.w = (x.w - mu) * rstd * g.w + be.w;
    ((float4*)(out + (size_t)row * 1024))[tid] = o;
}

// ---------------- launch ---------------------------------------------------------
extern "C" void kernel_launch(void* const* d_in, const int* in_sizes, int n_in,
                              void* d_out, int out_size) {
    const float* queries = (const float*)d_in[0];
    const float* keys    = (const float*)d_in[1];
    const float* values  = (const float*)d_in[2];
    const float* Wq = (const float*)d_in[3];
    const float* bq = (const float*)d_in[4];
    const float* Wk = (const float*)d_in[5];
    const float* bk = (const float*)d_in[6];
    const float* Wv = (const float*)d_in[7];
    const float* bv = (const float*)d_in[8];
    const float* gamma = (const float*)d_in[9];
    const float* beta  = (const float*)d_in[10];
    float* out = (float*)d_out;

    // opt-in to >48KB dynamic smem for the attention kernel (idempotent, capture-safe:
    // not a stream-ordered call, does not enqueue work)
    cudaFuncSetAttribute(attn_kernel, cudaFuncAttributeMaxDynamicSharedMemorySize,
                         (int)sizeof(ASmem));

    dim3 ggrid(Bb * Tt / 128, Uu / 128);
    gemm_relu_kernel<<<ggrid, 256>>>(queries, Wq, bq, 0);
    gemm_relu_kernel<<<ggrid, 256>>>(keys,    Wk, bk, 1);
    gemm_relu_kernel<<<ggrid, 256>>>(values,  Wv, bv, 2);

    mask_kernel<<<dim3(Bb * Tt, 2), 256>>>(queries, keys);

    attn_kernel<<<dim3(Tt / 64, Bb, Hh), 256, sizeof(ASmem)>>>();

    ln_kernel<<<Bb * Tt, 256>>>(queries, gamma, beta, out);
}

// round 4
// speedup vs baseline: 1.8436x; 1.8436x over previous
#include <cuda_runtime.h>
#include <cstdint>

#define Bb 8
#define Tt 1024
#define Uu 1024
#define Hh 8
#define Dd 128
#define NEGV  -4294967295.0f
#define NEGI  -3.0e38f
#define SCALE 0.08838834764831845f  /* 1/sqrt(128) */

// ---------------- scratch (static device memory; no allocations) ----------------
__device__ float g_Q[Bb * Tt * Uu];
__device__ float g_K[Bb * Tt * Uu];
__device__ float g_V[Bb * Tt * Uu];
__device__ float g_AO[Bb * Tt * Uu];
__device__ float g_qmask[Bb * Tt];
__device__ float g_kmask[Bb * Tt];

// ================= helpers =======================================================
__device__ __forceinline__ uint32_t f2tf32(float f) {
    uint32_t r;
    asm("cvt.rn.tf32.f32 %0, %1;" : "=r"(r) : "f"(f));
    return r;
}
__device__ __forceinline__ void mma16n8k8(float* d, const uint32_t* a, const uint32_t* b) {
    asm volatile(
        "mma.sync.aligned.m16n8k8.row.col.f32.tf32.tf32.f32 "
        "{%0,%1,%2,%3}, {%4,%5,%6,%7}, {%8,%9}, {%0,%1,%2,%3};"
        : "+f"(d[0]), "+f"(d[1]), "+f"(d[2]), "+f"(d[3])
        : "r"(a[0]), "r"(a[1]), "r"(a[2]), "r"(a[3]), "r"(b[0]), "r"(b[1]));
}

// ---------------- mma.sync tf32 GEMM + bias + ReLU -------------------------------
// C[m][n] = relu(A[8192,1024] @ W[1024,1024] + bias[n])
// CTA tile 128x128, warp tile 64x32 (2x4 warp grid), K-block 32.
#define KB 32
#define APAD 36    /* bank = (36*m + k) % 32 = 4m + k : conflict-free */
#define BPAD 136   /* bank = (136*k + n) % 32 = 8k + n : conflict-free */

__global__ void __launch_bounds__(256, 2) gemm_mma_kernel(
    const float* __restrict__ A, const float* __restrict__ W,
    const float* __restrict__ bias, int which) {
    float* C = (which == 0) ? g_Q : (which == 1) ? g_K : g_V;

    __shared__ uint32_t As[128][APAD];   // [m][k]
    __shared__ uint32_t Bs[KB][BPAD];    // [k][n]

    const int tid = threadIdx.x;
    const int warp = tid >> 5, lane = tid & 31;
    const int g = lane >> 2, t = lane & 3;
    const int warpM = (warp >> 2) * 64, warpN = (warp & 3) * 32;
    const int n0 = blockIdx.x * 128, m0 = blockIdx.y * 128;

    // global-load indices: A tile 128x32 (8 thr/row), B tile 32x128 (32 thr/row)
    const int ar = tid >> 3, ac4 = (tid & 7) * 4;
    const int br = tid >> 5, bc4 = (tid & 31) * 4;

    float acc[4][4][4] = {};

    for (int kb = 0; kb < Uu; kb += KB) {
        __syncthreads();
        // A: 16 floats/thread
#pragma unroll
        for (int i = 0; i < 4; i++) {
            const int r = ar + i * 32;
            float4 v = *(const float4*)(A + (size_t)(m0 + r) * Uu + kb + ac4);
            As[r][ac4 + 0] = f2tf32(v.x);
            As[r][ac4 + 1] = f2tf32(v.y);
            As[r][ac4 + 2] = f2tf32(v.z);
            As[r][ac4 + 3] = f2tf32(v.w);
        }
        // B: 16 floats/thread
#pragma unroll
        for (int i = 0; i < 4; i++) {
            const int r = br + i * 8;
            float4 v = *(const float4*)(W + (size_t)(kb + r) * Uu + n0 + bc4);
            Bs[r][bc4 + 0] = f2tf32(v.x);
            Bs[r][bc4 + 1] = f2tf32(v.y);
            Bs[r][bc4 + 2] = f2tf32(v.z);
            Bs[r][bc4 + 3] = f2tf32(v.w);
        }
        __syncthreads();

#pragma unroll
        for (int ks = 0; ks < KB; ks += 8) {
            uint32_t af[4][4], bf[4][2];
#pragma unroll
            for (int mi = 0; mi < 4; mi++) {
                const int mr = warpM + mi * 16 + g;
                af[mi][0] = As[mr][ks + t];
                af[mi][1] = As[mr + 8][ks + t];
                af[mi][2] = As[mr][ks + t + 4];
                af[mi][3] = As[mr + 8][ks + t + 4];
            }
#pragma unroll
            for (int ni = 0; ni < 4; ni++) {
                const int nc = warpN + ni * 8 + g;
                bf[ni][0] = Bs[ks + t][nc];
                bf[ni][1] = Bs[ks + t + 4][nc];
            }
#pragma unroll
            for (int mi = 0; mi < 4; mi++)
#pragma unroll
                for (int ni = 0; ni < 4; ni++)
                    mma16n8k8(acc[mi][ni], af[mi], bf[ni]);
        }
    }

    // epilogue: bias + relu, float2 stores
#pragma unroll
    for (int mi = 0; mi < 4; mi++) {
        const int r0 = m0 + warpM + mi * 16 + g;
#pragma unroll
        for (int ni = 0; ni < 4; ni++) {
            const int cc = n0 + warpN + ni * 8 + 2 * t;
            const float b0 = bias[cc], b1 = bias[cc + 1];
            float2 o0, o1;
            o0.x = fmaxf(acc[mi][ni][0] + b0, 0.0f);
            o0.y = fmaxf(acc[mi][ni][1] + b1, 0.0f);
            o1.x = fmaxf(acc[mi][ni][2] + b0, 0.0f);
            o1.y = fmaxf(acc[mi][ni][3] + b1, 0.0f);
            *(float2*)(C + (size_t)r0 * Uu + cc)       = o0;
            *(float2*)(C + (size_t)(r0 + 8) * Uu + cc) = o1;
        }
    }
}

// ---------------- mask row sums: sign(abs(rowsum)) ------------------------------
__global__ void __launch_bounds__(256) mask_kernel(
    const float* __restrict__ queries, const float* __restrict__ keys) {
    __shared__ float red[8];
    const int row = blockIdx.x;
    const float* src = (blockIdx.y == 0) ? queries : keys;
    float* dst = (blockIdx.y == 0) ? g_qmask : g_kmask;
    const int tid = threadIdx.x;
    float4 v = ((const float4*)(src + (size_t)row * 1024))[tid];
    float s = v.x + v.y + v.z + v.w;
#pragma unroll
    for (int off = 16; off; off >>= 1) s += __shfl_xor_sync(0xffffffffu, s, off);
    if ((tid & 31) == 0) red[tid >> 5] = s;
    __syncthreads();
    if (tid == 0) {
        float t = 0.f;
#pragma unroll
        for (int w = 0; w < 8; w++) t += red[w];
        dst[row] = (t != 0.0f) ? 1.0f : 0.0f;
    }
}

// ---------------- fused causal flash attention (fp32) ---------------------------
struct ASmem {
    float Qs[64][132];
    float Ks[64][132];
    float Vs[64][132];
    float Ps[64][65];
};

__global__ void __launch_bounds__(256, 1) attn_kernel() {
    extern __shared__ char raw[];
    ASmem& sm = *(ASmem*)raw;
    const int qt = blockIdx.x, b = blockIdx.y, h = blockIdx.z;
    const int tid = threadIdx.x;
    const int warp = tid >> 5, lane = tid & 31;

    const float* Qg = g_Q + ((size_t)b * Tt + qt * 64) * Uu + h * Dd;
    const float* Kg = g_K + (size_t)b * Tt * Uu + h * Dd;
    const float* Vg = g_V + (size_t)b * Tt * Uu + h * Dd;
    const float* km = g_kmask + b * Tt;

    for (int idx = tid; idx < 64 * 32; idx += 256) {
        int r = idx >> 5, c4 = (idx & 31) * 4;
        *(float4*)&sm.Qs[r][c4] = *(const float4*)(Qg + (size_t)r * Uu + c4);
    }

    float Oc[8][4] = {};
    float mrow[8], lrow[8];
#pragma unroll
    for (int i = 0; i < 8; i++) { mrow[i] = NEGI; lrow[i] = 0.0f; }

    for (int kt = 0; kt <= qt; kt++) {
        __syncthreads();
        for (int idx = tid; idx < 64 * 32; idx += 256) {
            int r = idx >> 5, c4 = (idx & 31) * 4;
            *(float4*)&sm.Ks[r][c4] = *(const float4*)(Kg + (size_t)(kt * 64 + r) * Uu + c4);
            *(float4*)&sm.Vs[r][c4] = *(const float4*)(Vg + (size_t)(kt * 64 + r) * Uu + c4);
        }
        __syncthreads();

        float s[8][2] = {};
#pragma unroll 4
        for (int kk = 0; kk < 128; kk += 4) {
            float4 b0 = *(float4*)&sm.Ks[lane][kk];
            float4 b1 = *(float4*)&sm.Ks[lane + 32][kk];
#pragma unroll
            for (int i = 0; i < 8; i++) {
                float4 a = *(float4*)&sm.Qs[8 * warp + i][kk];
                s[i][0] += a.x * b0.x + a.y * b0.y + a.z * b0.z + a.w * b0.w;
                s[i][1] += a.x * b1.x + a.y * b1.y + a.z * b1.z + a.w * b1.w;
            }
        }

        const int kg0 = kt * 64 + lane;
        const int kg1 = kg0 + 32;
        const float km0 = km[kg0], km1 = km[kg1];
#pragma unroll
        for (int i = 0; i < 8; i++) {
            const int qg = qt * 64 + 8 * warp + i;
            float v0 = s[i][0] * SCALE;
            float v1 = s[i][1] * SCALE;
            if (km0 == 0.0f || kg0 > qg) v0 = NEGV;
            if (km1 == 0.0f || kg1 > qg) v1 = NEGV;
            s[i][0] = v0; s[i][1] = v1;
        }

#pragma unroll
        for (int i = 0; i < 8; i++) {
            float mx = fmaxf(s[i][0], s[i][1]);
#pragma unroll
            for (int off = 16; off; off >>= 1)
                mx = fmaxf(mx, __shfl_xor_sync(0xffffffffu, mx, off));
            float mnew = fmaxf(mrow[i], mx);
            float alpha = __expf(mrow[i] - mnew);
            float p0 = __expf(s[i][0] - mnew);
            float p1 = __expf(s[i][1] - mnew);
            float ps = p0 + p1;
#pragma unroll
            for (int off = 16; off; off >>= 1)
                ps += __shfl_xor_sync(0xffffffffu, ps, off);
            lrow[i] = lrow[i] * alpha + ps;
            mrow[i] = mnew;
            sm.Ps[8 * warp + i][lane]      = p0;
            sm.Ps[8 * warp + i][lane + 32] = p1;
#pragma unroll
            for (int j = 0; j < 4; j++) Oc[i][j] *= alpha;
        }
        __syncthreads();

#pragma unroll 4
        for (int kk = 0; kk < 64; kk++) {
            float4 v = *(float4*)&sm.Vs[kk][4 * lane];
#pragma unroll
            for (int i = 0; i < 8; i++) {
                float p = sm.Ps[8 * warp + i][kk];
                Oc[i][0] += p * v.x;
                Oc[i][1] += p * v.y;
                Oc[i][2] += p * v.z;
                Oc[i][3] += p * v.w;
            }
        }
    }

    float* AOg = g_AO + ((size_t)b * Tt + qt * 64) * Uu + h * Dd;
#pragma unroll
    for (int i = 0; i < 8; i++) {
        const int qg = qt * 64 + 8 * warp + i;
        const float inv = g_qmask[b * Tt + qg] / lrow[i];
        float4 o;
        o.x = Oc[i][0] * inv;
        o.y = Oc[i][1] * inv;
        o.z = Oc[i][2] * inv;
        o.w = Oc[i][3] * inv;
        *(float4*)(AOg + (size_t)(8 * warp + i) * Uu + 4 * lane) = o;
    }
}

// ---------------- residual + LayerNorm ------------------------------------------
__global__ void __launch_bounds__(256) ln_kernel(
    const float* __restrict__ Qin, const float* __restrict__ gamma,
    const float* __restrict__ beta, float* __restrict__ out) {
    __shared__ float red[2][8];
    const int row = blockIdx.x, tid = threadIdx.x;
    float4 a = ((const float4*)(g_AO + (size_t)row * 1024))[tid];
    float4 q = ((const float4*)(Qin + (size_t)row * 1024))[tid];
    float4 x;
    x.x = a.x + q.x; x.y = a.y + q.y; x.z = a.z + q.z; x.w = a.w + q.w;
    float s  = x.x + x.y + x.z + x.w;
    float ss = x.x * x.x + x.y * x.y + x.z * x.z + x.w * x.w;
#pragma unroll
    for (int off = 16; off; off >>= 1) {
        s  += __shfl_xor_sync(0xffffffffu, s, off);
        ss += __shfl_xor_sync(0xffffffffu, ss, off);
    }
    if ((tid & 31) == 0) { red[0][tid >> 5] = s; red[1][tid >> 5] = ss; }
    __syncthreads();
    s = 0.f; ss = 0.f;
#pragma unroll
    for (int w = 0; w < 8; w++) { s += red[0][w]; ss += red[1][w]; }
    const float mu = s * (1.0f / 1024.0f);
    const float var = ss * (1.0f / 1024.0f) - mu * mu;
    const float rstd = rsqrtf(var + 1e-5f);
    float4 g  = ((const float4*)gamma)[tid];
    float4 be = ((const float4*)beta)[tid];
    float4 o;
    o.x = (x.x - mu) * rstd * g.x + be.x;
    o.y = (x.y - mu) * rstd * g.y + be.y;
    o.z = (x.z - mu) * rstd * g.z + be.z;
    o.w = (x.w - mu) * rstd * g.w + be.w;
    ((float4*)(out + (size_t)row * 1024))[tid] = o;
}

// ---------------- launch ---------------------------------------------------------
extern "C" void kernel_launch(void* const* d_in, const int* in_sizes, int n_in,
                              void* d_out, int out_size) {
    const float* queries = (const float*)d_in[0];
    const float* keys    = (const float*)d_in[1];
    const float* values  = (const float*)d_in[2];
    const float* Wq = (const float*)d_in[3];
    const float* bq = (const float*)d_in[4];
    const float* Wk = (const float*)d_in[5];
    const float* bk = (const float*)d_in[6];
    const float* Wv = (const float*)d_in[7];
    const float* bv = (const float*)d_in[8];
    const float* gamma = (const float*)d_in[9];
    const float* beta  = (const float*)d_in[10];
    float* out = (float*)d_out;

    cudaFuncSetAttribute(attn_kernel, cudaFuncAttributeMaxDynamicSharedMemorySize,
                         (int)sizeof(ASmem));

    dim3 ggrid(Uu / 128, Bb * Tt / 128);  // x = N-tiles (8), y = M-tiles (64)
    gemm_mma_kernel<<<ggrid, 256>>>(queries, Wq, bq, 0);
    gemm_mma_kernel<<<ggrid, 256>>>(keys,    Wk, bk, 1);
    gemm_mma_kernel<<<ggrid, 256>>>(values,  Wv, bv, 2);

    mask_kernel<<<dim3(Bb * Tt, 2), 256>>>(queries, keys);

    attn_kernel<<<dim3(Tt / 64, Bb, Hh), 256, sizeof(ASmem)>>>();

    ln_kernel<<<Bb * Tt, 256>>>(queries, gamma, beta, out);
}

// round 5
// speedup vs baseline: 2.8291x; 1.5346x over previous
#include <cuda_runtime.h>
#include <cstdint>

#define Bb 8
#define Tt 1024
#define Uu 1024
#define Hh 8
#define Dd 128
#define NEGV  -4294967295.0f
#define NEGI  -3.0e38f
#define SCALE 0.08838834764831845f  /* 1/sqrt(128) */

// ---------------- scratch (static device memory; no allocations) ----------------
__device__ float g_Q[Bb * Tt * Uu];
__device__ float g_K[Bb * Tt * Uu];
__device__ float g_Vt[Bb * Hh * Dd * Tt];   // V transposed per (b,h): [d][token]
__device__ float g_AO[Bb * Tt * Uu];
__device__ float g_qmask[Bb * Tt];
__device__ float g_kmask[Bb * Tt];

// ================= helpers =======================================================
__device__ __forceinline__ uint32_t f2tf32(float f) {
    uint32_t r;
    asm("cvt.rn.tf32.f32 %0, %1;" : "=r"(r) : "f"(f));
    return r;
}
__device__ __forceinline__ void mma16n8k8(float* d, const uint32_t* a, const uint32_t* b) {
    asm volatile(
        "mma.sync.aligned.m16n8k8.row.col.f32.tf32.tf32.f32 "
        "{%0,%1,%2,%3}, {%4,%5,%6,%7}, {%8,%9}, {%0,%1,%2,%3};"
        : "+f"(d[0]), "+f"(d[1]), "+f"(d[2]), "+f"(d[3])
        : "r"(a[0]), "r"(a[1]), "r"(a[2]), "r"(a[3]), "r"(b[0]), "r"(b[1]));
}

// ---------------- mma.sync tf32 GEMM + bias + ReLU -------------------------------
// C[m][n] = relu(A[8192,1024] @ W[1024,1024] + bias[n])
// which==2 (V): output written TRANSPOSED into g_Vt[b][h][d][token].
#define KB 32
#define APAD 36
#define BPAD 136

__global__ void __launch_bounds__(256, 2) gemm_mma_kernel(
    const float* __restrict__ A, const float* __restrict__ W,
    const float* __restrict__ bias, int which) {
    float* C = (which == 0) ? g_Q : g_K;

    __shared__ uint32_t As[128][APAD];   // [m][k]
    __shared__ uint32_t Bs[KB][BPAD];    // [k][n]

    const int tid = threadIdx.x;
    const int warp = tid >> 5, lane = tid & 31;
    const int g = lane >> 2, t = lane & 3;
    const int warpM = (warp >> 2) * 64, warpN = (warp & 3) * 32;
    const int n0 = blockIdx.x * 128, m0 = blockIdx.y * 128;

    const int ar = tid >> 3, ac4 = (tid & 7) * 4;
    const int br = tid >> 5, bc4 = (tid & 31) * 4;

    float acc[4][4][4] = {};

    for (int kb = 0; kb < Uu; kb += KB) {
        __syncthreads();
#pragma unroll
        for (int i = 0; i < 4; i++) {
            const int r = ar + i * 32;
            float4 v = *(const float4*)(A + (size_t)(m0 + r) * Uu + kb + ac4);
            As[r][ac4 + 0] = f2tf32(v.x);
            As[r][ac4 + 1] = f2tf32(v.y);
            As[r][ac4 + 2] = f2tf32(v.z);
            As[r][ac4 + 3] = f2tf32(v.w);
        }
#pragma unroll
        for (int i = 0; i < 4; i++) {
            const int r = br + i * 8;
            float4 v = *(const float4*)(W + (size_t)(kb + r) * Uu + n0 + bc4);
            Bs[r][bc4 + 0] = f2tf32(v.x);
            Bs[r][bc4 + 1] = f2tf32(v.y);
            Bs[r][bc4 + 2] = f2tf32(v.z);
            Bs[r][bc4 + 3] = f2tf32(v.w);
        }
        __syncthreads();

#pragma unroll
        for (int ks = 0; ks < KB; ks += 8) {
            uint32_t af[4][4], bf[4][2];
#pragma unroll
            for (int mi = 0; mi < 4; mi++) {
                const int mr = warpM + mi * 16 + g;
                af[mi][0] = As[mr][ks + t];
                af[mi][1] = As[mr + 8][ks + t];
                af[mi][2] = As[mr][ks + t + 4];
                af[mi][3] = As[mr + 8][ks + t + 4];
            }
#pragma unroll
            for (int ni = 0; ni < 4; ni++) {
                const int nc = warpN + ni * 8 + g;
                bf[ni][0] = Bs[ks + t][nc];
                bf[ni][1] = Bs[ks + t + 4][nc];
            }
#pragma unroll
            for (int mi = 0; mi < 4; mi++)
#pragma unroll
                for (int ni = 0; ni < 4; ni++)
                    mma16n8k8(acc[mi][ni], af[mi], bf[ni]);
        }
    }

    if (which != 2) {
        // normal epilogue: bias + relu, float2 stores
#pragma unroll
        for (int mi = 0; mi < 4; mi++) {
            const int r0 = m0 + warpM + mi * 16 + g;
#pragma unroll
            for (int ni = 0; ni < 4; ni++) {
                const int cc = n0 + warpN + ni * 8 + 2 * t;
                const float b0 = bias[cc], b1 = bias[cc + 1];
                float2 o0, o1;
                o0.x = fmaxf(acc[mi][ni][0] + b0, 0.0f);
                o0.y = fmaxf(acc[mi][ni][1] + b1, 0.0f);
                o1.x = fmaxf(acc[mi][ni][2] + b0, 0.0f);
                o1.y = fmaxf(acc[mi][ni][3] + b1, 0.0f);
                *(float2*)(C + (size_t)r0 * Uu + cc)       = o0;
                *(float2*)(C + (size_t)(r0 + 8) * Uu + cc) = o1;
            }
        }
    } else {
        // V epilogue: bias + relu, TRANSPOSED store to g_Vt[b][h][d][token]
#pragma unroll
        for (int mi = 0; mi < 4; mi++) {
            const int r0 = m0 + warpM + mi * 16 + g;   // global token index (b*1024+tok)
#pragma unroll
            for (int ni = 0; ni < 4; ni++) {
                const int cc = n0 + warpN + ni * 8 + 2 * t;  // global U col (h*128+d)
                const float b0 = bias[cc], b1 = bias[cc + 1];
                float v00 = fmaxf(acc[mi][ni][0] + b0, 0.0f);
                float v01 = fmaxf(acc[mi][ni][1] + b1, 0.0f);
                float v10 = fmaxf(acc[mi][ni][2] + b0, 0.0f);
                float v11 = fmaxf(acc[mi][ni][3] + b1, 0.0f);
                const int bq = r0 >> 10, tok = r0 & 1023;
                const int hh = cc >> 7, dd = cc & 127;
                float* base = g_Vt + (((size_t)bq * Hh + hh) * Dd) * Tt;
                base[(size_t)dd * Tt + tok]           = v00;
                base[(size_t)(dd + 1) * Tt + tok]     = v01;
                base[(size_t)dd * Tt + tok + 8]       = v10;
                base[(size_t)(dd + 1) * Tt + tok + 8] = v11;
            }
        }
    }
}

// ---------------- mask row sums: sign(abs(rowsum)) ------------------------------
__global__ void __launch_bounds__(256) mask_kernel(
    const float* __restrict__ queries, const float* __restrict__ keys) {
    __shared__ float red[8];
    const int row = blockIdx.x;
    const float* src = (blockIdx.y == 0) ? queries : keys;
    float* dst = (blockIdx.y == 0) ? g_qmask : g_kmask;
    const int tid = threadIdx.x;
    float4 v = ((const float4*)(src + (size_t)row * 1024))[tid];
    float s = v.x + v.y + v.z + v.w;
#pragma unroll
    for (int off = 16; off; off >>= 1) s += __shfl_xor_sync(0xffffffffu, s, off);
    if ((tid & 31) == 0) red[tid >> 5] = s;
    __syncthreads();
    if (tid == 0) {
        float t = 0.f;
#pragma unroll
        for (int w = 0; w < 8; w++) t += red[w];
        dst[row] = (t != 0.0f) ? 1.0f : 0.0f;
    }
}

// ---------------- flash attention via mma.sync tf32 ------------------------------
// Q tile 128 rows x d=128; K/V chunks of 64 keys. 8 warps, each owns 16 full S rows
// (1 m-frag x 8 n-frags) -> softmax reduces within a lane quad only.
#define PADQ 132   /* %32 = 4 : frag loads bank 4g+t, conflict-free */
#define PADV 68    /* %32 = 4 : frag loads bank 4g+t, conflict-free */
struct ASmem {
    uint32_t Qs[128][PADQ];
    uint32_t Ks[64][PADQ];
    uint32_t Vts[128][PADV];   // [d][key] (B operand, col-major for PV)
    uint32_t Ps[128][PADV];    // [row][key] tf32 probs
    float kms[64];
};

__global__ void __launch_bounds__(256, 1) attn_kernel() {
    extern __shared__ char raw[];
    ASmem& sm = *(ASmem*)raw;
    const int qt = blockIdx.x, b = blockIdx.y, h = blockIdx.z;
    const int tid = threadIdx.x;
    const int warp = tid >> 5, lane = tid & 31;
    const int g = lane >> 2, t = lane & 3;

    const float* Qg  = g_Q + ((size_t)b * Tt + qt * 128) * Uu + h * Dd;
    const float* Kg  = g_K + (size_t)b * Tt * Uu + h * Dd;
    const float* Vtg = g_Vt + ((size_t)b * Hh + h) * Dd * Tt;
    const float* km  = g_kmask + b * Tt;

    // load Q tile (128 x 128) -> tf32
    for (int idx = tid; idx < 128 * 32; idx += 256) {
        int r = idx >> 5, c4 = (idx & 31) * 4;
        float4 v = *(const float4*)(Qg + (size_t)r * Uu + c4);
        sm.Qs[r][c4 + 0] = f2tf32(v.x);
        sm.Qs[r][c4 + 1] = f2tf32(v.y);
        sm.Qs[r][c4 + 2] = f2tf32(v.z);
        sm.Qs[r][c4 + 3] = f2tf32(v.w);
    }

    float oacc[16][4] = {};
    float mrow0 = NEGI, mrow1 = NEGI, lrow0 = 0.0f, lrow1 = 0.0f;
    const int qrow0 = qt * 128 + 16 * warp + g;

    const int ktmax = 2 * qt + 1;
    for (int kt = 0; kt <= ktmax; kt++) {
        __syncthreads();
        // K chunk (64 x 128)
        for (int idx = tid; idx < 64 * 32; idx += 256) {
            int r = idx >> 5, c4 = (idx & 31) * 4;
            float4 v = *(const float4*)(Kg + (size_t)(kt * 64 + r) * Uu + c4);
            sm.Ks[r][c4 + 0] = f2tf32(v.x);
            sm.Ks[r][c4 + 1] = f2tf32(v.y);
            sm.Ks[r][c4 + 2] = f2tf32(v.z);
            sm.Ks[r][c4 + 3] = f2tf32(v.w);
        }
        // Vt chunk (128 x 64)
        for (int idx = tid; idx < 128 * 16; idx += 256) {
            int r = idx >> 4, c4 = (idx & 15) * 4;
            float4 v = *(const float4*)(Vtg + (size_t)r * Tt + kt * 64 + c4);
            sm.Vts[r][c4 + 0] = f2tf32(v.x);
            sm.Vts[r][c4 + 1] = f2tf32(v.y);
            sm.Vts[r][c4 + 2] = f2tf32(v.z);
            sm.Vts[r][c4 + 3] = f2tf32(v.w);
        }
        if (tid < 64) sm.kms[tid] = km[kt * 64 + tid];
        __syncthreads();

        // S = Q @ K^T : per warp 16 rows x 64 cols
        float sc[8][4] = {};
#pragma unroll
        for (int ks = 0; ks < 16; ks++) {
            uint32_t af[4];
            af[0] = sm.Qs[16 * warp + g][8 * ks + t];
            af[1] = sm.Qs[16 * warp + g + 8][8 * ks + t];
            af[2] = sm.Qs[16 * warp + g][8 * ks + t + 4];
            af[3] = sm.Qs[16 * warp + g + 8][8 * ks + t + 4];
#pragma unroll
            for (int ni = 0; ni < 8; ni++) {
                uint32_t bf[2];
                bf[0] = sm.Ks[8 * ni + g][8 * ks + t];
                bf[1] = sm.Ks[8 * ni + g][8 * ks + t + 4];
                mma16n8k8(sc[ni], af, bf);
            }
        }

        // scale + key mask + causal mask, track row max
        float mx0 = NEGI, mx1 = NEGI;
#pragma unroll
        for (int ni = 0; ni < 8; ni++) {
            const int kk = kt * 64 + 8 * ni + 2 * t;
            const float km0 = sm.kms[8 * ni + 2 * t];
            const float km1 = sm.kms[8 * ni + 2 * t + 1];
            float v;
            v = sc[ni][0] * SCALE; if (km0 == 0.f || kk     > qrow0)     v = NEGV; sc[ni][0] = v; mx0 = fmaxf(mx0, v);
            v = sc[ni][1] * SCALE; if (km1 == 0.f || kk + 1 > qrow0)     v = NEGV; sc[ni][1] = v; mx0 = fmaxf(mx0, v);
            v = sc[ni][2] * SCALE; if (km0 == 0.f || kk     > qrow0 + 8) v = NEGV; sc[ni][2] = v; mx1 = fmaxf(mx1, v);
            v = sc[ni][3] * SCALE; if (km1 == 0.f || kk + 1 > qrow0 + 8) v = NEGV; sc[ni][3] = v; mx1 = fmaxf(mx1, v);
        }
        mx0 = fmaxf(mx0, __shfl_xor_sync(0xffffffffu, mx0, 1));
        mx0 = fmaxf(mx0, __shfl_xor_sync(0xffffffffu, mx0, 2));
        mx1 = fmaxf(mx1, __shfl_xor_sync(0xffffffffu, mx1, 1));
        mx1 = fmaxf(mx1, __shfl_xor_sync(0xffffffffu, mx1, 2));

        const float mn0 = fmaxf(mrow0, mx0), mn1 = fmaxf(mrow1, mx1);
        const float al0 = __expf(mrow0 - mn0), al1 = __expf(mrow1 - mn1);
        float ps0 = 0.0f, ps1 = 0.0f;
#pragma unroll
        for (int ni = 0; ni < 8; ni++) {
            float p0 = __expf(sc[ni][0] - mn0);
            float p1 = __expf(sc[ni][1] - mn0);
            float p2 = __expf(sc[ni][2] - mn1);
            float p3 = __expf(sc[ni][3] - mn1);
            ps0 += p0 + p1;
            ps1 += p2 + p3;
            sm.Ps[16 * warp + g][8 * ni + 2 * t]         = f2tf32(p0);
            sm.Ps[16 * warp + g][8 * ni + 2 * t + 1]     = f2tf32(p1);
            sm.Ps[16 * warp + g + 8][8 * ni + 2 * t]     = f2tf32(p2);
            sm.Ps[16 * warp + g + 8][8 * ni + 2 * t + 1] = f2tf32(p3);
        }
        ps0 += __shfl_xor_sync(0xffffffffu, ps0, 1);
        ps0 += __shfl_xor_sync(0xffffffffu, ps0, 2);
        ps1 += __shfl_xor_sync(0xffffffffu, ps1, 1);
        ps1 += __shfl_xor_sync(0xffffffffu, ps1, 2);
        lrow0 = lrow0 * al0 + ps0;
        lrow1 = lrow1 * al1 + ps1;
        mrow0 = mn0; mrow1 = mn1;
#pragma unroll
        for (int ni = 0; ni < 16; ni++) {
            oacc[ni][0] *= al0; oacc[ni][1] *= al0;
            oacc[ni][2] *= al1; oacc[ni][3] *= al1;
        }
        __syncwarp();   // order Ps cross-lane STS -> LDS (warp-private rows)

        // O += P @ V  (B = Vt[d][key])
#pragma unroll
        for (int ks = 0; ks < 8; ks++) {
            uint32_t af[4];
            af[0] = sm.Ps[16 * warp + g][8 * ks + t];
            af[1] = sm.Ps[16 * warp + g + 8][8 * ks + t];
            af[2] = sm.Ps[16 * warp + g][8 * ks + t + 4];
            af[3] = sm.Ps[16 * warp + g + 8][8 * ks + t + 4];
#pragma unroll
            for (int ni = 0; ni < 16; ni++) {
                uint32_t bf[2];
                bf[0] = sm.Vts[8 * ni + g][8 * ks + t];
                bf[1] = sm.Vts[8 * ni + g][8 * ks + t + 4];
                mma16n8k8(oacc[ni], af, bf);
            }
        }
    }

    // normalize, query mask, store
    const float inv0 = g_qmask[b * Tt + qrow0] / lrow0;
    const float inv1 = g_qmask[b * Tt + qrow0 + 8] / lrow1;
    float* AOg = g_AO + ((size_t)b * Tt + qrow0) * Uu + h * Dd;
#pragma unroll
    for (int ni = 0; ni < 16; ni++) {
        const int cc = 8 * ni + 2 * t;
        float2 o0, o1;
        o0.x = oacc[ni][0] * inv0; o0.y = oacc[ni][1] * inv0;
        o1.x = oacc[ni][2] * inv1; o1.y = oacc[ni][3] * inv1;
        *(float2*)(AOg + cc)                  = o0;
        *(float2*)(AOg + (size_t)8 * Uu + cc) = o1;
    }
}

// ---------------- residual + LayerNorm ------------------------------------------
__global__ void __launch_bounds__(256) ln_kernel(
    const float* __restrict__ Qin, const float* __restrict__ gamma,
    const float* __restrict__ beta, float* __restrict__ out) {
    __shared__ float red[2][8];
    const int row = blockIdx.x, tid = threadIdx.x;
    float4 a = ((const float4*)(g_AO + (size_t)row * 1024))[tid];
    float4 q = ((const float4*)(Qin + (size_t)row * 1024))[tid];
    float4 x;
    x.x = a.x + q.x; x.y = a.y + q.y; x.z = a.z + q.z; x.w = a.w + q.w;
    float s  = x.x + x.y + x.z + x.w;
    float ss = x.x * x.x + x.y * x.y + x.z * x.z + x.w * x.w;
#pragma unroll
    for (int off = 16; off; off >>= 1) {
        s  += __shfl_xor_sync(0xffffffffu, s, off);
        ss += __shfl_xor_sync(0xffffffffu, ss, off);
    }
    if ((tid & 31) == 0) { red[0][tid >> 5] = s; red[1][tid >> 5] = ss; }
    __syncthreads();
    s = 0.f; ss = 0.f;
#pragma unroll
    for (int w = 0; w < 8; w++) { s += red[0][w]; ss += red[1][w]; }
    const float mu = s * (1.0f / 1024.0f);
    const float var = ss * (1.0f / 1024.0f) - mu * mu;
    const float rstd = rsqrtf(var + 1e-5f);
    float4 g  = ((const float4*)gamma)[tid];
    float4 be = ((const float4*)beta)[tid];
    float4 o;
    o.x = (x.x - mu) * rstd * g.x + be.x;
    o.y = (x.y - mu) * rstd * g.y + be.y;
    o.z = (x.z - mu) * rstd * g.z + be.z;
    o.w = (x.w - mu) * rstd * g.w + be.w;
    ((float4*)(out + (size_t)row * 1024))[tid] = o;
}

// ---------------- launch ---------------------------------------------------------
extern "C" void kernel_launch(void* const* d_in, const int* in_sizes, int n_in,
                              void* d_out, int out_size) {
    const float* queries = (const float*)d_in[0];
    const float* keys    = (const float*)d_in[1];
    const float* values  = (const float*)d_in[2];
    const float* Wq = (const float*)d_in[3];
    const float* bq = (const float*)d_in[4];
    const float* Wk = (const float*)d_in[5];
    const float* bk = (const float*)d_in[6];
    const float* Wv = (const float*)d_in[7];
    const float* bv = (const float*)d_in[8];
    const float* gamma = (const float*)d_in[9];
    const float* beta  = (const float*)d_in[10];
    float* out = (float*)d_out;

    cudaFuncSetAttribute(attn_kernel, cudaFuncAttributeMaxDynamicSharedMemorySize,
                         (int)sizeof(ASmem));

    dim3 ggrid(Uu / 128, Bb * Tt / 128);  // x = N-tiles (8), y = M-tiles (64)
    gemm_mma_kernel<<<ggrid, 256>>>(queries, Wq, bq, 0);
    gemm_mma_kernel<<<ggrid, 256>>>(keys,    Wk, bk, 1);
    gemm_mma_kernel<<<ggrid, 256>>>(values,  Wv, bv, 2);

    mask_kernel<<<dim3(Bb * Tt, 2), 256>>>(queries, keys);

    attn_kernel<<<dim3(Tt / 128, Bb, Hh), 256, sizeof(ASmem)>>>();

    ln_kernel<<<Bb * Tt, 256>>>(queries, gamma, beta, out);
}

// round 6
// speedup vs baseline: 3.5423x; 1.2521x over previous
#include <cuda_runtime.h>
#include <cstdint>

#define Bb 8
#define Tt 1024
#define Uu 1024
#define Hh 8
#define Dd 128
#define NEGV  -4294967295.0f
#define NEGI  -3.0e38f
#define SCALE 0.08838834764831845f  /* 1/sqrt(128) */

// ---------------- scratch (static device memory; no allocations) ----------------
__device__ float g_Q[Bb * Tt * Uu];
__device__ float g_K[Bb * Tt * Uu];
__device__ float g_Vt[Bb * Hh * Dd * Tt];   // V transposed per (b,h): [d][token]
__device__ float g_AO[Bb * Tt * Uu];
__device__ float g_qmask[Bb * Tt];
__device__ float g_kmask[Bb * Tt];

// ================= helpers =======================================================
__device__ __forceinline__ void mma16n8k8(float* d, const uint32_t* a, const uint32_t* b) {
    asm volatile(
        "mma.sync.aligned.m16n8k8.row.col.f32.tf32.tf32.f32 "
        "{%0,%1,%2,%3}, {%4,%5,%6,%7}, {%8,%9}, {%0,%1,%2,%3};"
        : "+f"(d[0]), "+f"(d[1]), "+f"(d[2]), "+f"(d[3])
        : "r"(a[0]), "r"(a[1]), "r"(a[2]), "r"(a[3]), "r"(b[0]), "r"(b[1]));
}
__device__ __forceinline__ void cp16(void* s, const void* g) {
    uint32_t sa = (uint32_t)__cvta_generic_to_shared(s);
    asm volatile("cp.async.cg.shared.global [%0], [%1], 16;" :: "r"(sa), "l"(g) : "memory");
}
#define CP_COMMIT() asm volatile("cp.async.commit_group;" ::: "memory")
#define CP_WAIT0()  asm volatile("cp.async.wait_group 0;" ::: "memory")
#define CP_WAIT1()  asm volatile("cp.async.wait_group 1;" ::: "memory")

// ---------------- mma.sync tf32 GEMM + bias + ReLU, cp.async double-buffered -----
// C[m][n] = relu(A[8192,1024] @ W[1024,1024] + bias[n]);  grid (8, 64, 3)
// z==2 (V): output transposed into g_Vt[b][h][d][token] via SMEM staging.
#define KB 32
#define APAD 36
#define BPAD 136
#define ABYTES (2 * 128 * APAD * 4)             /* 36864 */
#define BBYTES (2 * KB * BPAD * 4)              /* 34816 */
#define GEMM_SMEM (ABYTES + BBYTES)             /* 71680; > 128*132*4 = 67584 for V stage */

__global__ void __launch_bounds__(256, 2) gemm_mma_kernel(
    const float* __restrict__ A0, const float* __restrict__ A1, const float* __restrict__ A2,
    const float* __restrict__ W0, const float* __restrict__ W1, const float* __restrict__ W2,
    const float* __restrict__ bi0, const float* __restrict__ bi1, const float* __restrict__ bi2) {
    extern __shared__ __align__(16) char gsm[];
    uint32_t (*As)[128][APAD] = reinterpret_cast<uint32_t(*)[128][APAD]>(gsm);
    uint32_t (*Bs)[KB][BPAD]  = reinterpret_cast<uint32_t(*)[KB][BPAD]>(gsm + ABYTES);

    const int which = blockIdx.z;
    const float* A    = (which == 0) ? A0  : (which == 1) ? A1  : A2;
    const float* W    = (which == 0) ? W0  : (which == 1) ? W1  : W2;
    const float* bias = (which == 0) ? bi0 : (which == 1) ? bi1 : bi2;
    float* C = (which == 0) ? g_Q : g_K;

    const int tid = threadIdx.x;
    const int warp = tid >> 5, lane = tid & 31;
    const int g = lane >> 2, t = lane & 3;
    const int warpM = (warp >> 2) * 64, warpN = (warp & 3) * 32;
    const int n0 = blockIdx.x * 128, m0 = blockIdx.y * 128;

    const int ar = tid >> 3, ac4 = (tid & 7) * 4;
    const int br = tid >> 5, bc4 = (tid & 31) * 4;

    float acc[4][4][4] = {};

    // async tile loader (raw fp32 bytes; mma truncates to tf32)
    auto load_tiles = [&](int kb, int buf) {
#pragma unroll
        for (int i = 0; i < 4; i++) {
            const int r = ar + i * 32;
            cp16(&As[buf][r][ac4], A + (size_t)(m0 + r) * Uu + kb + ac4);
        }
#pragma unroll
        for (int i = 0; i < 4; i++) {
            const int r = br + i * 8;
            cp16(&Bs[buf][r][bc4], W + (size_t)(kb + r) * Uu + n0 + bc4);
        }
        CP_COMMIT();
    };

    load_tiles(0, 0);
#pragma unroll 1
    for (int it = 0; it < Uu / KB; ++it) {
        const int buf = it & 1;
        if (it + 1 < Uu / KB) { load_tiles((it + 1) * KB, buf ^ 1); CP_WAIT1(); }
        else                  { CP_WAIT0(); }
        __syncthreads();

#pragma unroll
        for (int ks = 0; ks < KB; ks += 8) {
            uint32_t af[4][4], bf[4][2];
#pragma unroll
            for (int mi = 0; mi < 4; mi++) {
                const int mr = warpM + mi * 16 + g;
                af[mi][0] = As[buf][mr][ks + t];
                af[mi][1] = As[buf][mr + 8][ks + t];
                af[mi][2] = As[buf][mr][ks + t + 4];
                af[mi][3] = As[buf][mr + 8][ks + t + 4];
            }
#pragma unroll
            for (int ni = 0; ni < 4; ni++) {
                const int nc = warpN + ni * 8 + g;
                bf[ni][0] = Bs[buf][ks + t][nc];
                bf[ni][1] = Bs[buf][ks + t + 4][nc];
            }
#pragma unroll
            for (int mi = 0; mi < 4; mi++)
#pragma unroll
                for (int ni = 0; ni < 4; ni++)
                    mma16n8k8(acc[mi][ni], af[mi], bf[ni]);
        }
        __syncthreads();
    }

    if (which != 2) {
        // direct epilogue: bias + relu, float2 stores
#pragma unroll
        for (int mi = 0; mi < 4; mi++) {
            const int r0 = m0 + warpM + mi * 16 + g;
#pragma unroll
            for (int ni = 0; ni < 4; ni++) {
                const int cc = n0 + warpN + ni * 8 + 2 * t;
                const float b0 = bias[cc], b1 = bias[cc + 1];
                float2 o0, o1;
                o0.x = fmaxf(acc[mi][ni][0] + b0, 0.0f);
                o0.y = fmaxf(acc[mi][ni][1] + b1, 0.0f);
                o1.x = fmaxf(acc[mi][ni][2] + b0, 0.0f);
                o1.y = fmaxf(acc[mi][ni][3] + b1, 0.0f);
                *(float2*)(C + (size_t)r0 * Uu + cc)       = o0;
                *(float2*)(C + (size_t)(r0 + 8) * Uu + cc) = o1;
            }
        }
    } else {
        // V epilogue: stage transposed tile[n][m] in SMEM, then coalesced stores
        float (*tile)[132] = reinterpret_cast<float(*)[132]>(gsm);
#pragma unroll
        for (int mi = 0; mi < 4; mi++) {
            const int rl = warpM + mi * 16 + g;      // local m
#pragma unroll
            for (int ni = 0; ni < 4; ni++) {
                const int cl = warpN + ni * 8 + 2 * t;  // local n
                const float b0 = bias[n0 + cl], b1 = bias[n0 + cl + 1];
                tile[cl][rl]         = fmaxf(acc[mi][ni][0] + b0, 0.0f);
                tile[cl + 1][rl]     = fmaxf(acc[mi][ni][1] + b1, 0.0f);
                tile[cl][rl + 8]     = fmaxf(acc[mi][ni][2] + b0, 0.0f);
                tile[cl + 1][rl + 8] = fmaxf(acc[mi][ni][3] + b1, 0.0f);
            }
        }
        __syncthreads();
        const int bq = m0 >> 10, tok0 = m0 & 1023, hh = n0 >> 7;
        float* base = g_Vt + (((size_t)bq * Hh + hh) * Dd) * Tt + tok0;
#pragma unroll
        for (int i = 0; i < 16; i++) {
            const int idx = tid + i * 256;
            const int r = idx >> 5, c4 = (idx & 31) * 4;   // r: local d, c4: local token
            float4 v = *(float4*)&tile[r][c4];
            *(float4*)(base + (size_t)r * Tt + c4) = v;
        }
    }
}

// ---------------- mask row sums: sign(abs(rowsum)) ------------------------------
__global__ void __launch_bounds__(256) mask_kernel(
    const float* __restrict__ queries, const float* __restrict__ keys) {
    __shared__ float red[8];
    const int row = blockIdx.x;
    const float* src = (blockIdx.y == 0) ? queries : keys;
    float* dst = (blockIdx.y == 0) ? g_qmask : g_kmask;
    const int tid = threadIdx.x;
    float4 v = ((const float4*)(src + (size_t)row * 1024))[tid];
    float s = v.x + v.y + v.z + v.w;
#pragma unroll
    for (int off = 16; off; off >>= 1) s += __shfl_xor_sync(0xffffffffu, s, off);
    if ((tid & 31) == 0) red[tid >> 5] = s;
    __syncthreads();
    if (tid == 0) {
        float t = 0.f;
#pragma unroll
        for (int w = 0; w < 8; w++) t += red[w];
        dst[row] = (t != 0.0f) ? 1.0f : 0.0f;
    }
}

// ---------------- flash attention via mma.sync tf32 ------------------------------
#define PADQ 132
#define PADV 68
struct ASmem {
    uint32_t Qs[128][PADQ];
    uint32_t Ks[64][PADQ];
    uint32_t Vts[128][PADV];   // [d][key]
    uint32_t Ps[128][PADV];    // [row][key]
    float kms[64];
};

__global__ void __launch_bounds__(256, 1) attn_kernel() {
    extern __shared__ char raw[];
    ASmem& sm = *(ASmem*)raw;
    const int qt = blockIdx.x, b = blockIdx.y, h = blockIdx.z;
    const int tid = threadIdx.x;
    const int warp = tid >> 5, lane = tid & 31;
    const int g = lane >> 2, t = lane & 3;

    const float* Qg  = g_Q + ((size_t)b * Tt + qt * 128) * Uu + h * Dd;
    const float* Kg  = g_K + (size_t)b * Tt * Uu + h * Dd;
    const float* Vtg = g_Vt + ((size_t)b * Hh + h) * Dd * Tt;
    const float* km  = g_kmask + b * Tt;

    // async Q tile load (raw fp32 bits)
#pragma unroll
    for (int i = 0; i < 16; i++) {
        const int idx = tid + i * 256;
        const int r = idx >> 5, c4 = (idx & 31) * 4;
        cp16(&sm.Qs[r][c4], Qg + (size_t)r * Uu + c4);
    }
    CP_COMMIT();

    float oacc[16][4] = {};
    float mrow0 = NEGI, mrow1 = NEGI, lrow0 = 0.0f, lrow1 = 0.0f;
    const int qrow0 = qt * 128 + 16 * warp + g;

    const int ktmax = 2 * qt + 1;
    for (int kt = 0; kt <= ktmax; kt++) {
        __syncthreads();
#pragma unroll
        for (int i = 0; i < 8; i++) {   // K chunk 64 x 128
            const int idx = tid + i * 256;
            const int r = idx >> 5, c4 = (idx & 31) * 4;
            cp16(&sm.Ks[r][c4], Kg + (size_t)(kt * 64 + r) * Uu + c4);
        }
#pragma unroll
        for (int i = 0; i < 8; i++) {   // Vt chunk 128 x 64
            const int idx = tid + i * 256;
            const int r = idx >> 4, c4 = (idx & 15) * 4;
            cp16(&sm.Vts[r][c4], Vtg + (size_t)r * Tt + kt * 64 + c4);
        }
        if (tid < 16) cp16(&sm.kms[tid * 4], km + kt * 64 + tid * 4);
        CP_COMMIT();
        CP_WAIT0();
        __syncthreads();

        // S = Q @ K^T : per warp 16 rows x 64 cols
        float sc[8][4] = {};
#pragma unroll
        for (int ks = 0; ks < 16; ks++) {
            uint32_t af[4];
            af[0] = sm.Qs[16 * warp + g][8 * ks + t];
            af[1] = sm.Qs[16 * warp + g + 8][8 * ks + t];
            af[2] = sm.Qs[16 * warp + g][8 * ks + t + 4];
            af[3] = sm.Qs[16 * warp + g + 8][8 * ks + t + 4];
#pragma unroll
            for (int ni = 0; ni < 8; ni++) {
                uint32_t bf[2];
                bf[0] = sm.Ks[8 * ni + g][8 * ks + t];
                bf[1] = sm.Ks[8 * ni + g][8 * ks + t + 4];
                mma16n8k8(sc[ni], af, bf);
            }
        }

        // scale + key mask + causal mask, track row max
        float mx0 = NEGI, mx1 = NEGI;
#pragma unroll
        for (int ni = 0; ni < 8; ni++) {
            const int kk = kt * 64 + 8 * ni + 2 * t;
            const float km0 = sm.kms[8 * ni + 2 * t];
            const float km1 = sm.kms[8 * ni + 2 * t + 1];
            float v;
            v = sc[ni][0] * SCALE; if (km0 == 0.f || kk     > qrow0)     v = NEGV; sc[ni][0] = v; mx0 = fmaxf(mx0, v);
            v = sc[ni][1] * SCALE; if (km1 == 0.f || kk + 1 > qrow0)     v = NEGV; sc[ni][1] = v; mx0 = fmaxf(mx0, v);
            v = sc[ni][2] * SCALE; if (km0 == 0.f || kk     > qrow0 + 8) v = NEGV; sc[ni][2] = v; mx1 = fmaxf(mx1, v);
            v = sc[ni][3] * SCALE; if (km1 == 0.f || kk + 1 > qrow0 + 8) v = NEGV; sc[ni][3] = v; mx1 = fmaxf(mx1, v);
        }
        mx0 = fmaxf(mx0, __shfl_xor_sync(0xffffffffu, mx0, 1));
        mx0 = fmaxf(mx0, __shfl_xor_sync(0xffffffffu, mx0, 2));
        mx1 = fmaxf(mx1, __shfl_xor_sync(0xffffffffu, mx1, 1));
        mx1 = fmaxf(mx1, __shfl_xor_sync(0xffffffffu, mx1, 2));

        const float mn0 = fmaxf(mrow0, mx0), mn1 = fmaxf(mrow1, mx1);
        const float al0 = __expf(mrow0 - mn0), al1 = __expf(mrow1 - mn1);
        float ps0 = 0.0f, ps1 = 0.0f;
#pragma unroll
        for (int ni = 0; ni < 8; ni++) {
            float p0 = __expf(sc[ni][0] - mn0);
            float p1 = __expf(sc[ni][1] - mn0);
            float p2 = __expf(sc[ni][2] - mn1);
            float p3 = __expf(sc[ni][3] - mn1);
            ps0 += p0 + p1;
            ps1 += p2 + p3;
            sm.Ps[16 * warp + g][8 * ni + 2 * t]         = __float_as_uint(p0);
            sm.Ps[16 * warp + g][8 * ni + 2 * t + 1]     = __float_as_uint(p1);
            sm.Ps[16 * warp + g + 8][8 * ni + 2 * t]     = __float_as_uint(p2);
            sm.Ps[16 * warp + g + 8][8 * ni + 2 * t + 1] = __float_as_uint(p3);
        }
        ps0 += __shfl_xor_sync(0xffffffffu, ps0, 1);
        ps0 += __shfl_xor_sync(0xffffffffu, ps0, 2);
        ps1 += __shfl_xor_sync(0xffffffffu, ps1, 1);
        ps1 += __shfl_xor_sync(0xffffffffu, ps1, 2);
        lrow0 = lrow0 * al0 + ps0;
        lrow1 = lrow1 * al1 + ps1;
        mrow0 = mn0; mrow1 = mn1;
#pragma unroll
        for (int ni = 0; ni < 16; ni++) {
            oacc[ni][0] *= al0; oacc[ni][1] *= al0;
            oacc[ni][2] *= al1; oacc[ni][3] *= al1;
        }
        __syncwarp();   // order Ps cross-lane STS -> LDS (warp-private rows)

        // O += P @ V  (B = Vt[d][key])
#pragma unroll
        for (int ks = 0; ks < 8; ks++) {
            uint32_t af[4];
            af[0] = sm.Ps[16 * warp + g][8 * ks + t];
            af[1] = sm.Ps[16 * warp + g + 8][8 * ks + t];
            af[2] = sm.Ps[16 * warp + g][8 * ks + t + 4];
            af[3] = sm.Ps[16 * warp + g + 8][8 * ks + t + 4];
#pragma unroll
            for (int ni = 0; ni < 16; ni++) {
                uint32_t bf[2];
                bf[0] = sm.Vts[8 * ni + g][8 * ks + t];
                bf[1] = sm.Vts[8 * ni + g][8 * ks + t + 4];
                mma16n8k8(oacc[ni], af, bf);
            }
        }
    }

    // normalize, query mask, store
    const float inv0 = g_qmask[b * Tt + qrow0] / lrow0;
    const float inv1 = g_qmask[b * Tt + qrow0 + 8] / lrow1;
    float* AOg = g_AO + ((size_t)b * Tt + qrow0) * Uu + h * Dd;
#pragma unroll
    for (int ni = 0; ni < 16; ni++) {
        const int cc = 8 * ni + 2 * t;
        float2 o0, o1;
        o0.x = oacc[ni][0] * inv0; o0.y = oacc[ni][1] * inv0;
        o1.x = oacc[ni][2] * inv1; o1.y = oacc[ni][3] * inv1;
        *(float2*)(AOg + cc)                  = o0;
        *(float2*)(AOg + (size_t)8 * Uu + cc) = o1;
    }
}

// ---------------- residual + LayerNorm ------------------------------------------
__global__ void __launch_bounds__(256) ln_kernel(
    const float* __restrict__ Qin, const float* __restrict__ gamma,
    const float* __restrict__ beta, float* __restrict__ out) {
    __shared__ float red[2][8];
    const int row = blockIdx.x, tid = threadIdx.x;
    float4 a = ((const float4*)(g_AO + (size_t)row * 1024))[tid];
    float4 q = ((const float4*)(Qin + (size_t)row * 1024))[tid];
    float4 x;
    x.x = a.x + q.x; x.y = a.y + q.y; x.z = a.z + q.z; x.w = a.w + q.w;
    float s  = x.x + x.y + x.z + x.w;
    float ss = x.x * x.x + x.y * x.y + x.z * x.z + x.w * x.w;
#pragma unroll
    for (int off = 16; off; off >>= 1) {
        s  += __shfl_xor_sync(0xffffffffu, s, off);
        ss += __shfl_xor_sync(0xffffffffu, ss, off);
    }
    if ((tid & 31) == 0) { red[0][tid >> 5] = s; red[1][tid >> 5] = ss; }
    __syncthreads();
    s = 0.f; ss = 0.f;
#pragma unroll
    for (int w = 0; w < 8; w++) { s += red[0][w]; ss += red[1][w]; }
    const float mu = s * (1.0f / 1024.0f);
    const float var = ss * (1.0f / 1024.0f) - mu * mu;
    const float rstd = rsqrtf(var + 1e-5f);
    float4 g  = ((const float4*)gamma)[tid];
    float4 be = ((const float4*)beta)[tid];
    float4 o;
    o.x = (x.x - mu) * rstd * g.x + be.x;
    o.y = (x.y - mu) * rstd * g.y + be.y;
    o.z = (x.z - mu) * rstd * g.z + be.z;
    o.w = (x.w - mu) * rstd * g.w + be.w;
    ((float4*)(out + (size_t)row * 1024))[tid] = o;
}

// ---------------- launch ---------------------------------------------------------
extern "C" void kernel_launch(void* const* d_in, const int* in_sizes, int n_in,
                              void* d_out, int out_size) {
    const float* queries = (const float*)d_in[0];
    const float* keys    = (const float*)d_in[1];
    const float* values  = (const float*)d_in[2];
    const float* Wq = (const float*)d_in[3];
    const float* bq = (const float*)d_in[4];
    const float* Wk = (const float*)d_in[5];
    const float* bk = (const float*)d_in[6];
    const float* Wv = (const float*)d_in[7];
    const float* bv = (const float*)d_in[8];
    const float* gamma = (const float*)d_in[9];
    const float* beta  = (const float*)d_in[10];
    float* out = (float*)d_out;

    cudaFuncSetAttribute(attn_kernel, cudaFuncAttributeMaxDynamicSharedMemorySize,
                         (int)sizeof(ASmem));
    cudaFuncSetAttribute(gemm_mma_kernel, cudaFuncAttributeMaxDynamicSharedMemorySize,
                         GEMM_SMEM);

    gemm_mma_kernel<<<dim3(8, 64, 3), 256, GEMM_SMEM>>>(
        queries, keys, values, Wq, Wk, Wv, bq, bk, bv);

    mask_kernel<<<dim3(Bb * Tt, 2), 256>>>(queries, keys);

    attn_kernel<<<dim3(Tt / 128, Bb, Hh), 256, sizeof(ASmem)>>>();

    ln_kernel<<<Bb * Tt, 256>>>(queries, gamma, beta, out);
}

// round 7
// speedup vs baseline: 3.7393x; 1.0556x over previous
#include <cuda_runtime.h>
#include <cstdint>

#define Bb 8
#define Tt 1024
#define Uu 1024
#define Hh 8
#define Dd 128
#define NEGV  -4294967295.0f
#define NEGI  -3.0e38f
#define SCALE 0.08838834764831845f  /* 1/sqrt(128) */

// ---------------- scratch (static device memory; no allocations) ----------------
__device__ float g_Q[Bb * Tt * Uu];
__device__ float g_K[Bb * Tt * Uu];
__device__ float g_Vt[Bb * Hh * Dd * Tt];   // V transposed per (b,h): [d][token]
__device__ float g_AO[Bb * Tt * Uu];
__device__ float g_qmask[Bb * Tt];
__device__ float g_kmask[Bb * Tt];

// ================= helpers =======================================================
__device__ __forceinline__ void mma16n8k8(float* d, const uint32_t* a, const uint32_t* b) {
    asm volatile(
        "mma.sync.aligned.m16n8k8.row.col.f32.tf32.tf32.f32 "
        "{%0,%1,%2,%3}, {%4,%5,%6,%7}, {%8,%9}, {%0,%1,%2,%3};"
        : "+f"(d[0]), "+f"(d[1]), "+f"(d[2]), "+f"(d[3])
        : "r"(a[0]), "r"(a[1]), "r"(a[2]), "r"(a[3]), "r"(b[0]), "r"(b[1]));
}
__device__ __forceinline__ void cp16(void* s, const void* g) {
    uint32_t sa = (uint32_t)__cvta_generic_to_shared(s);
    asm volatile("cp.async.cg.shared.global [%0], [%1], 16;" :: "r"(sa), "l"(g) : "memory");
}
#define CP_COMMIT() asm volatile("cp.async.commit_group;" ::: "memory")
#define CP_WAIT0()  asm volatile("cp.async.wait_group 0;" ::: "memory")
#define CP_WAIT1()  asm volatile("cp.async.wait_group 1;" ::: "memory")

// ---------------- mma.sync tf32 GEMM + bias + ReLU, cp.async double-buffered -----
// C[m][n] = relu(A[8192,1024] @ W[1024,1024] + bias[n]);  grid (8, 64, 3)
// z==2 (V): output transposed into g_Vt[b][h][d][token] via SMEM staging.
#define KB 32
#define APAD 36
#define BPAD 136
#define ABYTES (2 * 128 * APAD * 4)             /* 36864 */
#define BBYTES (2 * KB * BPAD * 4)              /* 34816 */
#define GEMM_SMEM (ABYTES + BBYTES)             /* 71680 */

__global__ void __launch_bounds__(256, 2) gemm_mma_kernel(
    const float* __restrict__ A0, const float* __restrict__ A1, const float* __restrict__ A2,
    const float* __restrict__ W0, const float* __restrict__ W1, const float* __restrict__ W2,
    const float* __restrict__ bi0, const float* __restrict__ bi1, const float* __restrict__ bi2) {
    extern __shared__ __align__(16) char gsm[];
    uint32_t (*As)[128][APAD] = reinterpret_cast<uint32_t(*)[128][APAD]>(gsm);
    uint32_t (*Bs)[KB][BPAD]  = reinterpret_cast<uint32_t(*)[KB][BPAD]>(gsm + ABYTES);

    const int which = blockIdx.z;
    const float* A    = (which == 0) ? A0  : (which == 1) ? A1  : A2;
    const float* W    = (which == 0) ? W0  : (which == 1) ? W1  : W2;
    const float* bias = (which == 0) ? bi0 : (which == 1) ? bi1 : bi2;
    float* C = (which == 0) ? g_Q : g_K;

    const int tid = threadIdx.x;
    const int warp = tid >> 5, lane = tid & 31;
    const int g = lane >> 2, t = lane & 3;
    const int warpM = (warp >> 2) * 64, warpN = (warp & 3) * 32;
    const int n0 = blockIdx.x * 128, m0 = blockIdx.y * 128;

    const int ar = tid >> 3, ac4 = (tid & 7) * 4;
    const int br = tid >> 5, bc4 = (tid & 31) * 4;

    float acc[4][4][4] = {};

    auto load_tiles = [&](int kb, int buf) {
#pragma unroll
        for (int i = 0; i < 4; i++) {
            const int r = ar + i * 32;
            cp16(&As[buf][r][ac4], A + (size_t)(m0 + r) * Uu + kb + ac4);
        }
#pragma unroll
        for (int i = 0; i < 4; i++) {
            const int r = br + i * 8;
            cp16(&Bs[buf][r][bc4], W + (size_t)(kb + r) * Uu + n0 + bc4);
        }
        CP_COMMIT();
    };

    load_tiles(0, 0);
#pragma unroll 1
    for (int it = 0; it < Uu / KB; ++it) {
        const int buf = it & 1;
        if (it + 1 < Uu / KB) { load_tiles((it + 1) * KB, buf ^ 1); CP_WAIT1(); }
        else                  { CP_WAIT0(); }
        __syncthreads();

#pragma unroll
        for (int ks = 0; ks < KB; ks += 8) {
            uint32_t af[4][4], bf[4][2];
#pragma unroll
            for (int mi = 0; mi < 4; mi++) {
                const int mr = warpM + mi * 16 + g;
                af[mi][0] = As[buf][mr][ks + t];
                af[mi][1] = As[buf][mr + 8][ks + t];
                af[mi][2] = As[buf][mr][ks + t + 4];
                af[mi][3] = As[buf][mr + 8][ks + t + 4];
            }
#pragma unroll
            for (int ni = 0; ni < 4; ni++) {
                const int nc = warpN + ni * 8 + g;
                bf[ni][0] = Bs[buf][ks + t][nc];
                bf[ni][1] = Bs[buf][ks + t + 4][nc];
            }
#pragma unroll
            for (int mi = 0; mi < 4; mi++)
#pragma unroll
                for (int ni = 0; ni < 4; ni++)
                    mma16n8k8(acc[mi][ni], af[mi], bf[ni]);
        }
        __syncthreads();
    }

    if (which != 2) {
#pragma unroll
        for (int mi = 0; mi < 4; mi++) {
            const int r0 = m0 + warpM + mi * 16 + g;
#pragma unroll
            for (int ni = 0; ni < 4; ni++) {
                const int cc = n0 + warpN + ni * 8 + 2 * t;
                const float b0 = bias[cc], b1 = bias[cc + 1];
                float2 o0, o1;
                o0.x = fmaxf(acc[mi][ni][0] + b0, 0.0f);
                o0.y = fmaxf(acc[mi][ni][1] + b1, 0.0f);
                o1.x = fmaxf(acc[mi][ni][2] + b0, 0.0f);
                o1.y = fmaxf(acc[mi][ni][3] + b1, 0.0f);
                *(float2*)(C + (size_t)r0 * Uu + cc)       = o0;
                *(float2*)(C + (size_t)(r0 + 8) * Uu + cc) = o1;
            }
        }
    } else {
        // V epilogue: stage transposed tile[n][m] in SMEM, then coalesced stores
        float (*tile)[132] = reinterpret_cast<float(*)[132]>(gsm);
#pragma unroll
        for (int mi = 0; mi < 4; mi++) {
            const int rl = warpM + mi * 16 + g;
#pragma unroll
            for (int ni = 0; ni < 4; ni++) {
                const int cl = warpN + ni * 8 + 2 * t;
                const float b0 = bias[n0 + cl], b1 = bias[n0 + cl + 1];
                tile[cl][rl]         = fmaxf(acc[mi][ni][0] + b0, 0.0f);
                tile[cl + 1][rl]     = fmaxf(acc[mi][ni][1] + b1, 0.0f);
                tile[cl][rl + 8]     = fmaxf(acc[mi][ni][2] + b0, 0.0f);
                tile[cl + 1][rl + 8] = fmaxf(acc[mi][ni][3] + b1, 0.0f);
            }
        }
        __syncthreads();
        const int bq = m0 >> 10, tok0 = m0 & 1023, hh = n0 >> 7;
        float* base = g_Vt + (((size_t)bq * Hh + hh) * Dd) * Tt + tok0;
#pragma unroll
        for (int i = 0; i < 16; i++) {
            const int idx = tid + i * 256;
            const int r = idx >> 5, c4 = (idx & 31) * 4;
            float4 v = *(float4*)&tile[r][c4];
            *(float4*)(base + (size_t)r * Tt + c4) = v;
        }
    }
}

// ---------------- mask row sums: sign(abs(rowsum)) ------------------------------
__global__ void __launch_bounds__(256) mask_kernel(
    const float* __restrict__ queries, const float* __restrict__ keys) {
    __shared__ float red[8];
    const int row = blockIdx.x;
    const float* src = (blockIdx.y == 0) ? queries : keys;
    float* dst = (blockIdx.y == 0) ? g_qmask : g_kmask;
    const int tid = threadIdx.x;
    float4 v = ((const float4*)(src + (size_t)row * 1024))[tid];
    float s = v.x + v.y + v.z + v.w;
#pragma unroll
    for (int off = 16; off; off >>= 1) s += __shfl_xor_sync(0xffffffffu, s, off);
    if ((tid & 31) == 0) red[tid >> 5] = s;
    __syncthreads();
    if (tid == 0) {
        float t = 0.f;
#pragma unroll
        for (int w = 0; w < 8; w++) t += red[w];
        dst[row] = (t != 0.0f) ? 1.0f : 0.0f;
    }
}

// ---------------- flash attention via mma.sync tf32, pipelined -------------------
// Q tile 128 x 128; K chunks 64 (single-buffered, prefetched post-QK barrier);
// V/kms double-buffered. Q frags hoisted to registers.
#define PADQ 132
#define PADV 68
struct ASmem {
    uint32_t Qs[128][PADQ];        // 67.6 KB
    uint32_t Ks[64][PADQ];         // 33.8 KB
    uint32_t Vts[2][128][PADV];    // 69.6 KB  [d][key]
    uint32_t Ps[128][PADV];        // 34.8 KB  [row][key]
    float kms[2][64];
};

__global__ void __launch_bounds__(256, 1) attn_kernel() {
    extern __shared__ char raw[];
    ASmem& sm = *(ASmem*)raw;
    const int qt = gridDim.x - 1 - blockIdx.x;   // long-first scheduling
    const int b = blockIdx.y, h = blockIdx.z;
    const int tid = threadIdx.x;
    const int warp = tid >> 5, lane = tid & 31;
    const int g = lane >> 2, t = lane & 3;

    const float* Qg  = g_Q + ((size_t)b * Tt + qt * 128) * Uu + h * Dd;
    const float* Kg  = g_K + (size_t)b * Tt * Uu + h * Dd;
    const float* Vtg = g_Vt + ((size_t)b * Hh + h) * Dd * Tt;
    const float* km  = g_kmask + b * Tt;

    auto load_k = [&](int kt) {
#pragma unroll
        for (int i = 0; i < 8; i++) {
            const int idx = tid + i * 256;
            const int r = idx >> 5, c4 = (idx & 31) * 4;
            cp16(&sm.Ks[r][c4], Kg + (size_t)(kt * 64 + r) * Uu + c4);
        }
    };
    auto load_v = [&](int kt, int buf) {
#pragma unroll
        for (int i = 0; i < 8; i++) {
            const int idx = tid + i * 256;
            const int r = idx >> 4, c4 = (idx & 15) * 4;
            cp16(&sm.Vts[buf][r][c4], Vtg + (size_t)r * Tt + kt * 64 + c4);
        }
        if (tid < 16) cp16(&sm.kms[buf][tid * 4], km + kt * 64 + tid * 4);
    };

    // prologue: Q tile + first K/V chunk in one group
#pragma unroll
    for (int i = 0; i < 16; i++) {
        const int idx = tid + i * 256;
        const int r = idx >> 5, c4 = (idx & 31) * 4;
        cp16(&sm.Qs[r][c4], Qg + (size_t)r * Uu + c4);
    }
    load_k(0);
    load_v(0, 0);
    CP_COMMIT();
    CP_WAIT0();
    __syncthreads();

    // hoist Q fragments (loop-invariant over kt)
    uint32_t qf[16][4];
#pragma unroll
    for (int ks = 0; ks < 16; ks++) {
        qf[ks][0] = sm.Qs[16 * warp + g][8 * ks + t];
        qf[ks][1] = sm.Qs[16 * warp + g + 8][8 * ks + t];
        qf[ks][2] = sm.Qs[16 * warp + g][8 * ks + t + 4];
        qf[ks][3] = sm.Qs[16 * warp + g + 8][8 * ks + t + 4];
    }

    float oacc[16][4] = {};
    float mrow0 = NEGI, mrow1 = NEGI, lrow0 = 0.0f, lrow1 = 0.0f;
    const int qrow0 = qt * 128 + 16 * warp + g;

    const int ktmax = 2 * qt + 1;
    for (int kt = 0; kt <= ktmax; kt++) {
        const int buf = kt & 1;

        // S = Q @ K^T : per warp 16 rows x 64 cols
        float sc[8][4] = {};
#pragma unroll
        for (int ks = 0; ks < 16; ks++) {
#pragma unroll
            for (int ni = 0; ni < 8; ni++) {
                uint32_t bf[2];
                bf[0] = sm.Ks[8 * ni + g][8 * ks + t];
                bf[1] = sm.Ks[8 * ni + g][8 * ks + t + 4];
                mma16n8k8(sc[ni], qf[ks], bf);
            }
        }
        __syncthreads();           // all warps done reading Ks

        // prefetch next chunk (K overwrites Ks; V/kms go to other buffer)
        if (kt < ktmax) {
            load_k(kt + 1);
            load_v(kt + 1, buf ^ 1);
            CP_COMMIT();
        }

        // scale + key mask + causal mask, track row max
        float mx0 = NEGI, mx1 = NEGI;
#pragma unroll
        for (int ni = 0; ni < 8; ni++) {
            const int kk = kt * 64 + 8 * ni + 2 * t;
            const float km0 = sm.kms[buf][8 * ni + 2 * t];
            const float km1 = sm.kms[buf][8 * ni + 2 * t + 1];
            float v;
            v = sc[ni][0] * SCALE; if (km0 == 0.f || kk     > qrow0)     v = NEGV; sc[ni][0] = v; mx0 = fmaxf(mx0, v);
            v = sc[ni][1] * SCALE; if (km1 == 0.f || kk + 1 > qrow0)     v = NEGV; sc[ni][1] = v; mx0 = fmaxf(mx0, v);
            v = sc[ni][2] * SCALE; if (km0 == 0.f || kk     > qrow0 + 8) v = NEGV; sc[ni][2] = v; mx1 = fmaxf(mx1, v);
            v = sc[ni][3] * SCALE; if (km1 == 0.f || kk + 1 > qrow0 + 8) v = NEGV; sc[ni][3] = v; mx1 = fmaxf(mx1, v);
        }
        mx0 = fmaxf(mx0, __shfl_xor_sync(0xffffffffu, mx0, 1));
        mx0 = fmaxf(mx0, __shfl_xor_sync(0xffffffffu, mx0, 2));
        mx1 = fmaxf(mx1, __shfl_xor_sync(0xffffffffu, mx1, 1));
        mx1 = fmaxf(mx1, __shfl_xor_sync(0xffffffffu, mx1, 2));

        const float mn0 = fmaxf(mrow0, mx0), mn1 = fmaxf(mrow1, mx1);
        const float al0 = __expf(mrow0 - mn0), al1 = __expf(mrow1 - mn1);
        float ps0 = 0.0f, ps1 = 0.0f;
#pragma unroll
        for (int ni = 0; ni < 8; ni++) {
            float p0 = __expf(sc[ni][0] - mn0);
            float p1 = __expf(sc[ni][1] - mn0);
            float p2 = __expf(sc[ni][2] - mn1);
            float p3 = __expf(sc[ni][3] - mn1);
            ps0 += p0 + p1;
            ps1 += p2 + p3;
            sm.Ps[16 * warp + g][8 * ni + 2 * t]         = __float_as_uint(p0);
            sm.Ps[16 * warp + g][8 * ni + 2 * t + 1]     = __float_as_uint(p1);
            sm.Ps[16 * warp + g + 8][8 * ni + 2 * t]     = __float_as_uint(p2);
            sm.Ps[16 * warp + g + 8][8 * ni + 2 * t + 1] = __float_as_uint(p3);
        }
        ps0 += __shfl_xor_sync(0xffffffffu, ps0, 1);
        ps0 += __shfl_xor_sync(0xffffffffu, ps0, 2);
        ps1 += __shfl_xor_sync(0xffffffffu, ps1, 1);
        ps1 += __shfl_xor_sync(0xffffffffu, ps1, 2);
        lrow0 = lrow0 * al0 + ps0;
        lrow1 = lrow1 * al1 + ps1;
        mrow0 = mn0; mrow1 = mn1;
#pragma unroll
        for (int ni = 0; ni < 16; ni++) {
            oacc[ni][0] *= al0; oacc[ni][1] *= al0;
            oacc[ni][2] *= al1; oacc[ni][3] *= al1;
        }
        __syncwarp();   // order Ps cross-lane STS -> LDS (warp-private rows)

        // O += P @ V  (B = Vt[d][key], current buffer)
#pragma unroll
        for (int ks = 0; ks < 8; ks++) {
            uint32_t af[4];
            af[0] = sm.Ps[16 * warp + g][8 * ks + t];
            af[1] = sm.Ps[16 * warp + g + 8][8 * ks + t];
            af[2] = sm.Ps[16 * warp + g][8 * ks + t + 4];
            af[3] = sm.Ps[16 * warp + g + 8][8 * ks + t + 4];
#pragma unroll
            for (int ni = 0; ni < 16; ni++) {
                uint32_t bf[2];
                bf[0] = sm.Vts[buf][8 * ni + g][8 * ks + t];
                bf[1] = sm.Vts[buf][8 * ni + g][8 * ks + t + 4];
                mma16n8k8(oacc[ni], af, bf);
            }
        }

        if (kt < ktmax) {
            CP_WAIT0();            // next K/V landed
            __syncthreads();       // visible to all warps before next QK
        }
    }

    // normalize, query mask, store
    const float inv0 = g_qmask[b * Tt + qrow0] / lrow0;
    const float inv1 = g_qmask[b * Tt + qrow0 + 8] / lrow1;
    float* AOg = g_AO + ((size_t)b * Tt + qrow0) * Uu + h * Dd;
#pragma unroll
    for (int ni = 0; ni < 16; ni++) {
        const int cc = 8 * ni + 2 * t;
        float2 o0, o1;
        o0.x = oacc[ni][0] * inv0; o0.y = oacc[ni][1] * inv0;
        o1.x = oacc[ni][2] * inv1; o1.y = oacc[ni][3] * inv1;
        *(float2*)(AOg + cc)                  = o0;
        *(float2*)(AOg + (size_t)8 * Uu + cc) = o1;
    }
}

// ---------------- residual + LayerNorm ------------------------------------------
__global__ void __launch_bounds__(256) ln_kernel(
    const float* __restrict__ Qin, const float* __restrict__ gamma,
    const float* __restrict__ beta, float* __restrict__ out) {
    __shared__ float red[2][8];
    const int row = blockIdx.x, tid = threadIdx.x;
    float4 a = ((const float4*)(g_AO + (size_t)row * 1024))[tid];
    float4 q = ((const float4*)(Qin + (size_t)row * 1024))[tid];
    float4 x;
    x.x = a.x + q.x; x.y = a.y + q.y; x.z = a.z + q.z; x.w = a.w + q.w;
    float s  = x.x + x.y + x.z + x.w;
    float ss = x.x * x.x + x.y * x.y + x.z * x.z + x.w * x.w;
#pragma unroll
    for (int off = 16; off; off >>= 1) {
        s  += __shfl_xor_sync(0xffffffffu, s, off);
        ss += __shfl_xor_sync(0xffffffffu, ss, off);
    }
    if ((tid & 31) == 0) { red[0][tid >> 5] = s; red[1][tid >> 5] = ss; }
    __syncthreads();
    s = 0.f; ss = 0.f;
#pragma unroll
    for (int w = 0; w < 8; w++) { s += red[0][w]; ss += red[1][w]; }
    const float mu = s * (1.0f / 1024.0f);
    const float var = ss * (1.0f / 1024.0f) - mu * mu;
    const float rstd = rsqrtf(var + 1e-5f);
    float4 g  = ((const float4*)gamma)[tid];
    float4 be = ((const float4*)beta)[tid];
    float4 o;
    o.x = (x.x - mu) * rstd * g.x + be.x;
    o.y = (x.y - mu) * rstd * g.y + be.y;
    o.z = (x.z - mu) * rstd * g.z + be.z;
    o.w = (x.w - mu) * rstd * g.w + be.w;
    ((float4*)(out + (size_t)row * 1024))[tid] = o;
}

// ---------------- launch ---------------------------------------------------------
extern "C" void kernel_launch(void* const* d_in, const int* in_sizes, int n_in,
                              void* d_out, int out_size) {
    const float* queries = (const float*)d_in[0];
    const float* keys    = (const float*)d_in[1];
    const float* values  = (const float*)d_in[2];
    const float* Wq = (const float*)d_in[3];
    const float* bq = (const float*)d_in[4];
    const float* Wk = (const float*)d_in[5];
    const float* bk = (const float*)d_in[6];
    const float* Wv = (const float*)d_in[7];
    const float* bv = (const float*)d_in[8];
    const float* gamma = (const float*)d_in[9];
    const float* beta  = (const float*)d_in[10];
    float* out = (float*)d_out;

    cudaFuncSetAttribute(attn_kernel, cudaFuncAttributeMaxDynamicSharedMemorySize,
                         (int)sizeof(ASmem));
    cudaFuncSetAttribute(gemm_mma_kernel, cudaFuncAttributeMaxDynamicSharedMemorySize,
                         GEMM_SMEM);

    gemm_mma_kernel<<<dim3(8, 64, 3), 256, GEMM_SMEM>>>(
        queries, keys, values, Wq, Wk, Wv, bq, bk, bv);

    mask_kernel<<<dim3(Bb * Tt, 2), 256>>>(queries, keys);

    attn_kernel<<<dim3(Tt / 128, Bb, Hh), 256, sizeof(ASmem)>>>();

    ln_kernel<<<Bb * Tt, 256>>>(queries, gamma, beta, out);
}

// round 8
// speedup vs baseline: 5.9380x; 1.5880x over previous
#include <cuda_runtime.h>
#include <cstdint>

#define Bb 8
#define Tt 1024
#define Uu 1024
#define Hh 8
#define Dd 128
#define NEGV  -4294967295.0f
#define NEGI  -3.0e38f
#define SCALE 0.08838834764831845f  /* 1/sqrt(128) */

// ---------------- scratch (static device memory; no allocations) ----------------
__device__ uint16_t g_Abf[3][Bb * Tt * Uu];      // bf16 inputs (queries/keys/values)
__device__ uint16_t g_WTbf[3][Uu * Uu];          // bf16 W^T  [n][k]
__device__ uint16_t g_Qbf[Bb * Tt * Uu];         // bf16 Q
__device__ uint16_t g_Kbf[Bb * Tt * Uu];         // bf16 K
__device__ uint16_t g_Vtbf[Bb * Hh * Dd * Tt];   // bf16 V^T per (b,h): [d][token]
__device__ float g_AO[Bb * Tt * Uu];
__device__ float g_qmask[Bb * Tt];
__device__ float g_kmask[Bb * Tt];

// ================= helpers =======================================================
__device__ __forceinline__ uint32_t packbf(float lo, float hi) {
    uint32_t r;
    asm("cvt.rn.bf16x2.f32 %0, %1, %2;" : "=r"(r) : "f"(hi), "f"(lo));
    return r;
}
__device__ __forceinline__ void mma16n8k16(float* d, const uint32_t* a, const uint32_t* b) {
    asm volatile(
        "mma.sync.aligned.m16n8k16.row.col.f32.bf16.bf16.f32 "
        "{%0,%1,%2,%3}, {%4,%5,%6,%7}, {%8,%9}, {%0,%1,%2,%3};"
        : "+f"(d[0]), "+f"(d[1]), "+f"(d[2]), "+f"(d[3])
        : "r"(a[0]), "r"(a[1]), "r"(a[2]), "r"(a[3]), "r"(b[0]), "r"(b[1]));
}
__device__ __forceinline__ void cp16(void* s, const void* g) {
    uint32_t sa = (uint32_t)__cvta_generic_to_shared(s);
    asm volatile("cp.async.cg.shared.global [%0], [%1], 16;" :: "r"(sa), "l"(g) : "memory");
}
#define CP_COMMIT() asm volatile("cp.async.commit_group;" ::: "memory")
#define CP_WAIT0()  asm volatile("cp.async.wait_group 0;" ::: "memory")
#define CP_WAIT1()  asm volatile("cp.async.wait_group 1;" ::: "memory")

// ---------------- input convert + row masks --------------------------------------
// grid (8192, 3): y=0 queries(+qmask), y=1 keys(+kmask), y=2 values
__global__ void __launch_bounds__(256) a_convert(
    const float* __restrict__ q, const float* __restrict__ k, const float* __restrict__ v) {
    __shared__ float red[8];
    const int y = blockIdx.y, row = blockIdx.x, tid = threadIdx.x;
    const float* src = (y == 0) ? q : (y == 1) ? k : v;
    float4 val = ((const float4*)(src + (size_t)row * 1024))[tid];
    uint2 p = { packbf(val.x, val.y), packbf(val.z, val.w) };
    ((uint2*)(g_Abf[y] + (size_t)row * 1024))[tid] = p;
    if (y < 2) {
        float s = val.x + val.y + val.z + val.w;
#pragma unroll
        for (int off = 16; off; off >>= 1) s += __shfl_xor_sync(0xffffffffu, s, off);
        if ((tid & 31) == 0) red[tid >> 5] = s;
        __syncthreads();
        if (tid == 0) {
            float t = 0.f;
#pragma unroll
            for (int w = 0; w < 8; w++) t += red[w];
            float* dst = (y == 0) ? g_qmask : g_kmask;
            dst[row] = (t != 0.0f) ? 1.0f : 0.0f;
        }
    }
}

// ---------------- W transpose + convert: W[k][n] fp32 -> WT[n][k] bf16 -----------
__global__ void __launch_bounds__(256) w_convert(
    const float* __restrict__ Wq, const float* __restrict__ Wk,
    const float* __restrict__ Wv) {
    __shared__ float t[32][33];
    const int which = blockIdx.z;
    const float* W = (which == 0) ? Wq : (which == 1) ? Wk : Wv;
    uint16_t* WT = g_WTbf[which];
    const int x0 = blockIdx.x * 32, y0 = blockIdx.y * 32;  // x: n, y: k
    const int tx = threadIdx.x & 31, ty = threadIdx.x >> 5;
#pragma unroll
    for (int r = ty; r < 32; r += 8)
        t[r][tx] = W[(size_t)(y0 + r) * Uu + x0 + tx];
    __syncthreads();
    const int wt = threadIdx.x & 15, rn0 = threadIdx.x >> 4;  // 16 k-words x 16 n-rows
#pragma unroll
    for (int rr = 0; rr < 2; rr++) {
        const int rn = rn0 + rr * 16;
        uint32_t pw = packbf(t[2 * wt][rn], t[2 * wt + 1][rn]);
        *(uint32_t*)(WT + (size_t)(x0 + rn) * Uu + y0 + 2 * wt) = pw;
    }
}

// ---------------- bf16 mma GEMM + bias + ReLU, cp.async double-buffered ----------
// C = relu(A @ W + bias); A,W^T pre-converted bf16. grid (8, 64, 3).
// z==0 -> g_Qbf, z==1 -> g_Kbf, z==2 -> g_Vtbf (transposed via SMEM staging).
#define KB2 64
#define AW 36                                    /* word pitch: bank 4*row+word */
#define ABYTES (2 * 128 * AW * 4)                /* 36864 */
#define GEMM_SMEM (2 * ABYTES)                   /* 73728; V stage 128*132*4=67584 fits */

__global__ void __launch_bounds__(256, 2) gemm_bf16_kernel(
    const float* __restrict__ bi0, const float* __restrict__ bi1,
    const float* __restrict__ bi2) {
    extern __shared__ __align__(16) char gsm[];
    uint32_t (*As)[128][AW] = reinterpret_cast<uint32_t(*)[128][AW]>(gsm);
    uint32_t (*Bs)[128][AW] = reinterpret_cast<uint32_t(*)[128][AW]>(gsm + ABYTES);

    const int which = blockIdx.z;
    const uint16_t* Abf  = g_Abf[which];
    const uint16_t* WTbf = g_WTbf[which];
    const float* bias = (which == 0) ? bi0 : (which == 1) ? bi1 : bi2;

    const int tid = threadIdx.x;
    const int warp = tid >> 5, lane = tid & 31;
    const int g = lane >> 2, t = lane & 3;
    const int warpM = (warp >> 2) * 64, warpN = (warp & 3) * 32;
    const int n0 = blockIdx.x * 128, m0 = blockIdx.y * 128;

    float acc[4][4][4] = {};

    auto load_tiles = [&](int kb, int buf) {
#pragma unroll
        for (int i = 0; i < 4; i++) {
            const int idx = tid + i * 256;
            const int r = idx >> 3, s = idx & 7;
            cp16(&As[buf][r][s * 4], Abf + (size_t)(m0 + r) * Uu + kb + s * 8);
        }
#pragma unroll
        for (int i = 0; i < 4; i++) {
            const int idx = tid + i * 256;
            const int r = idx >> 3, s = idx & 7;
            cp16(&Bs[buf][r][s * 4], WTbf + (size_t)(n0 + r) * Uu + kb + s * 8);
        }
        CP_COMMIT();
    };

    load_tiles(0, 0);
#pragma unroll 1
    for (int it = 0; it < Uu / KB2; ++it) {
        const int buf = it & 1;
        if (it + 1 < Uu / KB2) { load_tiles((it + 1) * KB2, buf ^ 1); CP_WAIT1(); }
        else                   { CP_WAIT0(); }
        __syncthreads();

#pragma unroll
        for (int ks = 0; ks < 4; ks++) {
            uint32_t af[4][4], bf[4][2];
#pragma unroll
            for (int mi = 0; mi < 4; mi++) {
                const int mr = warpM + mi * 16 + g;
                af[mi][0] = As[buf][mr][8 * ks + t];
                af[mi][1] = As[buf][mr + 8][8 * ks + t];
                af[mi][2] = As[buf][mr][8 * ks + t + 4];
                af[mi][3] = As[buf][mr + 8][8 * ks + t + 4];
            }
#pragma unroll
            for (int ni = 0; ni < 4; ni++) {
                const int nc = warpN + ni * 8 + g;
                bf[ni][0] = Bs[buf][nc][8 * ks + t];
                bf[ni][1] = Bs[buf][nc][8 * ks + t + 4];
            }
#pragma unroll
            for (int mi = 0; mi < 4; mi++)
#pragma unroll
                for (int ni = 0; ni < 4; ni++)
                    mma16n8k16(acc[mi][ni], af[mi], bf[ni]);
        }
        __syncthreads();
    }

    if (which != 2) {
        uint16_t* C = (which == 0) ? g_Qbf : g_Kbf;
#pragma unroll
        for (int mi = 0; mi < 4; mi++) {
            const int r0 = m0 + warpM + mi * 16 + g;
#pragma unroll
            for (int ni = 0; ni < 4; ni++) {
                const int cc = n0 + warpN + ni * 8 + 2 * t;
                const float b0 = bias[cc], b1 = bias[cc + 1];
                uint32_t p0 = packbf(fmaxf(acc[mi][ni][0] + b0, 0.0f),
                                     fmaxf(acc[mi][ni][1] + b1, 0.0f));
                uint32_t p1 = packbf(fmaxf(acc[mi][ni][2] + b0, 0.0f),
                                     fmaxf(acc[mi][ni][3] + b1, 0.0f));
                *(uint32_t*)(C + (size_t)r0 * Uu + cc)       = p0;
                *(uint32_t*)(C + (size_t)(r0 + 8) * Uu + cc) = p1;
            }
        }
    } else {
        // V epilogue: stage transposed fp32 tile[n][m], then packed bf16 stores
        float (*tile)[132] = reinterpret_cast<float(*)[132]>(gsm);
#pragma unroll
        for (int mi = 0; mi < 4; mi++) {
            const int rl = warpM + mi * 16 + g;
#pragma unroll
            for (int ni = 0; ni < 4; ni++) {
                const int cl = warpN + ni * 8 + 2 * t;
                const float b0 = bias[n0 + cl], b1 = bias[n0 + cl + 1];
                tile[cl][rl]         = fmaxf(acc[mi][ni][0] + b0, 0.0f);
                tile[cl + 1][rl]     = fmaxf(acc[mi][ni][1] + b1, 0.0f);
                tile[cl][rl + 8]     = fmaxf(acc[mi][ni][2] + b0, 0.0f);
                tile[cl + 1][rl + 8] = fmaxf(acc[mi][ni][3] + b1, 0.0f);
            }
        }
        __syncthreads();
        const int bq = m0 >> 10, tok0 = m0 & 1023, hh = n0 >> 7;
        uint16_t* base = g_Vtbf + (((size_t)bq * Hh + hh) * Dd) * Tt + tok0;
#pragma unroll
        for (int i = 0; i < 8; i++) {
            const int idx = tid + i * 256;
            const int r = idx >> 4, seg = idx & 15;      // r: local d, seg: 8 tokens
            float4 a = *(float4*)&tile[r][seg * 8];
            float4 c = *(float4*)&tile[r][seg * 8 + 4];
            uint4 o = { packbf(a.x, a.y), packbf(a.z, a.w),
                        packbf(c.x, c.y), packbf(c.z, c.w) };
            *(uint4*)(base + (size_t)r * Tt + seg * 8) = o;
        }
    }
}

// ---------------- flash attention via mma.sync bf16, pipelined -------------------
// Q tile 128 x 128; K chunks 64 (prefetched post-QK); V/kms double-buffered.
#define QW 68   /* Q/K word pitch (%32==4 -> conflict-free) */
#define VW 36   /* Vt/Ps word pitch */
struct ASmem {
    uint32_t Qs[128][QW];         // 34.8 KB (bf16 pairs)
    uint32_t Ks[64][QW];          // 17.4 KB
    uint32_t Vts[2][128][VW];     // 36.9 KB  [d][key]
    uint32_t Ps[128][VW];         // 18.4 KB  [row][key]
    float kms[2][64];
};

__global__ void __launch_bounds__(256, 1) attn_kernel() {
    extern __shared__ char raw[];
    ASmem& sm = *(ASmem*)raw;
    const int qt = gridDim.x - 1 - blockIdx.x;   // long-first scheduling
    const int b = blockIdx.y, h = blockIdx.z;
    const int tid = threadIdx.x;
    const int warp = tid >> 5, lane = tid & 31;
    const int g = lane >> 2, t = lane & 3;

    const uint16_t* Qg  = g_Qbf + ((size_t)b * Tt + qt * 128) * Uu + h * Dd;
    const uint16_t* Kg  = g_Kbf + (size_t)b * Tt * Uu + h * Dd;
    const uint16_t* Vtg = g_Vtbf + ((size_t)b * Hh + h) * Dd * Tt;
    const float* km  = g_kmask + b * Tt;

    auto load_k = [&](int kt) {
#pragma unroll
        for (int i = 0; i < 4; i++) {
            const int idx = tid + i * 256;
            const int r = idx >> 4, s = idx & 15;
            cp16(&sm.Ks[r][s * 4], Kg + (size_t)(kt * 64 + r) * Uu + s * 8);
        }
    };
    auto load_v = [&](int kt, int buf) {
#pragma unroll
        for (int i = 0; i < 4; i++) {
            const int idx = tid + i * 256;
            const int r = idx >> 3, s = idx & 7;
            cp16(&sm.Vts[buf][r][s * 4], Vtg + (size_t)r * Tt + kt * 64 + s * 8);
        }
        if (tid < 16) cp16(&sm.kms[buf][tid * 4], km + kt * 64 + tid * 4);
    };

    // prologue: Q tile + first K/V chunk
#pragma unroll
    for (int i = 0; i < 8; i++) {
        const int idx = tid + i * 256;
        const int r = idx >> 4, s = idx & 15;
        cp16(&sm.Qs[r][s * 4], Qg + (size_t)r * Uu + s * 8);
    }
    load_k(0);
    load_v(0, 0);
    CP_COMMIT();
    CP_WAIT0();
    __syncthreads();

    // hoist Q fragments (8 k-steps x 4 regs)
    uint32_t qf[8][4];
#pragma unroll
    for (int ks = 0; ks < 8; ks++) {
        qf[ks][0] = sm.Qs[16 * warp + g][8 * ks + t];
        qf[ks][1] = sm.Qs[16 * warp + g + 8][8 * ks + t];
        qf[ks][2] = sm.Qs[16 * warp + g][8 * ks + t + 4];
        qf[ks][3] = sm.Qs[16 * warp + g + 8][8 * ks + t + 4];
    }

    float oacc[16][4] = {};
    float mrow0 = NEGI, mrow1 = NEGI, lrow0 = 0.0f, lrow1 = 0.0f;
    const int qrow0 = qt * 128 + 16 * warp + g;

    const int ktmax = 2 * qt + 1;
    for (int kt = 0; kt <= ktmax; kt++) {
        const int buf = kt & 1;

        // S = Q @ K^T : per warp 16 rows x 64 cols (8 ks x 8 ni mma)
        float sc[8][4] = {};
#pragma unroll
        for (int ks = 0; ks < 8; ks++) {
#pragma unroll
            for (int ni = 0; ni < 8; ni++) {
                uint32_t bfr[2];
                bfr[0] = sm.Ks[8 * ni + g][8 * ks + t];
                bfr[1] = sm.Ks[8 * ni + g][8 * ks + t + 4];
                mma16n8k16(sc[ni], qf[ks], bfr);
            }
        }
        __syncthreads();           // all warps done reading Ks

        if (kt < ktmax) {          // prefetch next chunk
            load_k(kt + 1);
            load_v(kt + 1, buf ^ 1);
            CP_COMMIT();
        }

        // scale + key mask + causal mask, track row max
        float mx0 = NEGI, mx1 = NEGI;
#pragma unroll
        for (int ni = 0; ni < 8; ni++) {
            const int kk = kt * 64 + 8 * ni + 2 * t;
            const float km0 = sm.kms[buf][8 * ni + 2 * t];
            const float km1 = sm.kms[buf][8 * ni + 2 * t + 1];
            float v;
            v = sc[ni][0] * SCALE; if (km0 == 0.f || kk     > qrow0)     v = NEGV; sc[ni][0] = v; mx0 = fmaxf(mx0, v);
            v = sc[ni][1] * SCALE; if (km1 == 0.f || kk + 1 > qrow0)     v = NEGV; sc[ni][1] = v; mx0 = fmaxf(mx0, v);
            v = sc[ni][2] * SCALE; if (km0 == 0.f || kk     > qrow0 + 8) v = NEGV; sc[ni][2] = v; mx1 = fmaxf(mx1, v);
            v = sc[ni][3] * SCALE; if (km1 == 0.f || kk + 1 > qrow0 + 8) v = NEGV; sc[ni][3] = v; mx1 = fmaxf(mx1, v);
        }
        mx0 = fmaxf(mx0, __shfl_xor_sync(0xffffffffu, mx0, 1));
        mx0 = fmaxf(mx0, __shfl_xor_sync(0xffffffffu, mx0, 2));
        mx1 = fmaxf(mx1, __shfl_xor_sync(0xffffffffu, mx1, 1));
        mx1 = fmaxf(mx1, __shfl_xor_sync(0xffffffffu, mx1, 2));

        const float mn0 = fmaxf(mrow0, mx0), mn1 = fmaxf(mrow1, mx1);
        const float al0 = __expf(mrow0 - mn0), al1 = __expf(mrow1 - mn1);
        float ps0 = 0.0f, ps1 = 0.0f;
#pragma unroll
        for (int ni = 0; ni < 8; ni++) {
            float p0 = __expf(sc[ni][0] - mn0);
            float p1 = __expf(sc[ni][1] - mn0);
            float p2 = __expf(sc[ni][2] - mn1);
            float p3 = __expf(sc[ni][3] - mn1);
            ps0 += p0 + p1;
            ps1 += p2 + p3;
            sm.Ps[16 * warp + g][4 * ni + t]     = packbf(p0, p1);
            sm.Ps[16 * warp + g + 8][4 * ni + t] = packbf(p2, p3);
        }
        ps0 += __shfl_xor_sync(0xffffffffu, ps0, 1);
        ps0 += __shfl_xor_sync(0xffffffffu, ps0, 2);
        ps1 += __shfl_xor_sync(0xffffffffu, ps1, 1);
        ps1 += __shfl_xor_sync(0xffffffffu, ps1, 2);
        lrow0 = lrow0 * al0 + ps0;
        lrow1 = lrow1 * al1 + ps1;
        mrow0 = mn0; mrow1 = mn1;
#pragma unroll
        for (int ni = 0; ni < 16; ni++) {
            oacc[ni][0] *= al0; oacc[ni][1] *= al0;
            oacc[ni][2] *= al1; oacc[ni][3] *= al1;
        }
        __syncwarp();   // order Ps cross-lane STS -> LDS (warp-private rows)

        // O += P @ V  (4 ks x 16 ni mma; B = Vt[d][key], current buffer)
#pragma unroll
        for (int ks = 0; ks < 4; ks++) {
            uint32_t af[4];
            af[0] = sm.Ps[16 * warp + g][8 * ks + t];
            af[1] = sm.Ps[16 * warp + g + 8][8 * ks + t];
            af[2] = sm.Ps[16 * warp + g][8 * ks + t + 4];
            af[3] = sm.Ps[16 * warp + g + 8][8 * ks + t + 4];
#pragma unroll
            for (int ni = 0; ni < 16; ni++) {
                uint32_t bfr[2];
                bfr[0] = sm.Vts[buf][8 * ni + g][8 * ks + t];
                bfr[1] = sm.Vts[buf][8 * ni + g][8 * ks + t + 4];
                mma16n8k16(oacc[ni], af, bfr);
            }
        }

        if (kt < ktmax) {
            CP_WAIT0();
            __syncthreads();
        }
    }

    // normalize, query mask, store
    const float inv0 = g_qmask[b * Tt + qrow0] / lrow0;
    const float inv1 = g_qmask[b * Tt + qrow0 + 8] / lrow1;
    float* AOg = g_AO + ((size_t)b * Tt + qrow0) * Uu + h * Dd;
#pragma unroll
    for (int ni = 0; ni < 16; ni++) {
        const int cc = 8 * ni + 2 * t;
        float2 o0, o1;
        o0.x = oacc[ni][0] * inv0; o0.y = oacc[ni][1] * inv0;
        o1.x = oacc[ni][2] * inv1; o1.y = oacc[ni][3] * inv1;
        *(float2*)(AOg + cc)                  = o0;
        *(float2*)(AOg + (size_t)8 * Uu + cc) = o1;
    }
}

// ---------------- residual + LayerNorm ------------------------------------------
__global__ void __launch_bounds__(256) ln_kernel(
    const float* __restrict__ Qin, const float* __restrict__ gamma,
    const float* __restrict__ beta, float* __restrict__ out) {
    __shared__ float red[2][8];
    const int row = blockIdx.x, tid = threadIdx.x;
    float4 a = ((const float4*)(g_AO + (size_t)row * 1024))[tid];
    float4 q = ((const float4*)(Qin + (size_t)row * 1024))[tid];
    float4 x;
    x.x = a.x + q.x; x.y = a.y + q.y; x.z = a.z + q.z; x.w = a.w + q.w;
    float s  = x.x + x.y + x.z + x.w;
    float ss = x.x * x.x + x.y * x.y + x.z * x.z + x.w * x.w;
#pragma unroll
    for (int off = 16; off; off >>= 1) {
        s  += __shfl_xor_sync(0xffffffffu, s, off);
        ss += __shfl_xor_sync(0xffffffffu, ss, off);
    }
    if ((tid & 31) == 0) { red[0][tid >> 5] = s; red[1][tid >> 5] = ss; }
    __syncthreads();
    s = 0.f; ss = 0.f;
#pragma unroll
    for (int w = 0; w < 8; w++) { s += red[0][w]; ss += red[1][w]; }
    const float mu = s * (1.0f / 1024.0f);
    const float var = ss * (1.0f / 1024.0f) - mu * mu;
    const float rstd = rsqrtf(var + 1e-5f);
    float4 g  = ((const float4*)gamma)[tid];
    float4 be = ((const float4*)beta)[tid];
    float4 o;
    o.x = (x.x - mu) * rstd * g.x + be.x;
    o.y = (x.y - mu) * rstd * g.y + be.y;
    o.z = (x.z - mu) * rstd * g.z + be.z;
    o.w = (x.w - mu) * rstd * g.w + be.w;
    ((float4*)(out + (size_t)row * 1024))[tid] = o;
}

// ---------------- launch ---------------------------------------------------------
extern "C" void kernel_launch(void* const* d_in, const int* in_sizes, int n_in,
                              void* d_out, int out_size) {
    const float* queries = (const float*)d_in[0];
    const float* keys    = (const float*)d_in[1];
    const float* values  = (const float*)d_in[2];
    const float* Wq = (const float*)d_in[3];
    const float* bq = (const float*)d_in[4];
    const float* Wk = (const float*)d_in[5];
    const float* bk = (const float*)d_in[6];
    const float* Wv = (const float*)d_in[7];
    const float* bv = (const float*)d_in[8];
    const float* gamma = (const float*)d_in[9];
    const float* beta  = (const float*)d_in[10];
    float* out = (float*)d_out;

    cudaFuncSetAttribute(attn_kernel, cudaFuncAttributeMaxDynamicSharedMemorySize,
                         (int)sizeof(ASmem));
    cudaFuncSetAttribute(gemm_bf16_kernel, cudaFuncAttributeMaxDynamicSharedMemorySize,
                         GEMM_SMEM);

    w_convert<<<dim3(32, 32, 3), 256>>>(Wq, Wk, Wv);
    a_convert<<<dim3(Bb * Tt, 3), 256>>>(queries, keys, values);

    gemm_bf16_kernel<<<dim3(8, 64, 3), 256, GEMM_SMEM>>>(bq, bk, bv);

    attn_kernel<<<dim3(Tt / 128, Bb, Hh), 256, sizeof(ASmem)>>>();

    ln_kernel<<<Bb * Tt, 256>>>(queries, gamma, beta, out);
}

// round 9
// speedup vs baseline: 6.1876x; 1.0420x over previous
#include <cuda_runtime.h>
#include <cstdint>

#define Bb 8
#define Tt 1024
#define Uu 1024
#define Hh 8
#define Dd 128
#define NEGB  -6.0e9f    /* log2-domain "-inf" */
#define QSC   (0.08838834764831845f * 1.44269504088896341f)  /* 1/sqrt(128) * log2(e) */

// ---------------- scratch (static device memory; no allocations) ----------------
__device__ uint16_t g_Abf[3][Bb * Tt * Uu];      // bf16 inputs
__device__ uint16_t g_WTbf[3][Uu * Uu];          // bf16 W^T [n][k]
__device__ uint16_t g_Qbf[Bb * Tt * Uu];         // bf16 Q, pre-scaled by QSC
__device__ uint16_t g_Kbf[Bb * Tt * Uu];         // bf16 K
__device__ uint16_t g_Vtbf[Bb * Hh * Dd * Tt];   // bf16 V^T per (b,h): [d][token]
__device__ float g_AO[Bb * Tt * Uu];
__device__ float g_qmask[Bb * Tt];               // 1/0
__device__ float g_kbias[Bb * Tt];               // 0 or NEGB

// ================= helpers =======================================================
__device__ __forceinline__ uint32_t packbf(float lo, float hi) {
    uint32_t r;
    asm("cvt.rn.bf16x2.f32 %0, %1, %2;" : "=r"(r) : "f"(hi), "f"(lo));
    return r;
}
__device__ __forceinline__ float ex2(float x) {
    float r;
    asm("ex2.approx.ftz.f32 %0, %1;" : "=f"(r) : "f"(x));
    return r;
}
__device__ __forceinline__ void mma16n8k16(float* d, const uint32_t* a, const uint32_t* b) {
    asm volatile(
        "mma.sync.aligned.m16n8k16.row.col.f32.bf16.bf16.f32 "
        "{%0,%1,%2,%3}, {%4,%5,%6,%7}, {%8,%9}, {%0,%1,%2,%3};"
        : "+f"(d[0]), "+f"(d[1]), "+f"(d[2]), "+f"(d[3])
        : "r"(a[0]), "r"(a[1]), "r"(a[2]), "r"(a[3]), "r"(b[0]), "r"(b[1]));
}
__device__ __forceinline__ void cp16(void* s, const void* g) {
    uint32_t sa = (uint32_t)__cvta_generic_to_shared(s);
    asm volatile("cp.async.cg.shared.global [%0], [%1], 16;" :: "r"(sa), "l"(g) : "memory");
}
#define CP_COMMIT() asm volatile("cp.async.commit_group;" ::: "memory")
#define CP_WAIT0()  asm volatile("cp.async.wait_group 0;" ::: "memory")
#define CP_WAIT1()  asm volatile("cp.async.wait_group 1;" ::: "memory")

// ---------------- input convert + row masks --------------------------------------
// grid (8192, 3): y=0 queries(+qmask), y=1 keys(+kbias), y=2 values
__global__ void __launch_bounds__(256) a_convert(
    const float* __restrict__ q, const float* __restrict__ k, const float* __restrict__ v) {
    __shared__ float red[8];
    const int y = blockIdx.y, row = blockIdx.x, tid = threadIdx.x;
    const float* src = (y == 0) ? q : (y == 1) ? k : v;
    float4 val = ((const float4*)(src + (size_t)row * 1024))[tid];
    uint2 p = { packbf(val.x, val.y), packbf(val.z, val.w) };
    ((uint2*)(g_Abf[y] + (size_t)row * 1024))[tid] = p;
    if (y < 2) {
        float s = val.x + val.y + val.z + val.w;
#pragma unroll
        for (int off = 16; off; off >>= 1) s += __shfl_xor_sync(0xffffffffu, s, off);
        if ((tid & 31) == 0) red[tid >> 5] = s;
        __syncthreads();
        if (tid == 0) {
            float t = 0.f;
#pragma unroll
            for (int w = 0; w < 8; w++) t += red[w];
            if (y == 0) g_qmask[row] = (t != 0.0f) ? 1.0f : 0.0f;
            else        g_kbias[row] = (t != 0.0f) ? 0.0f : NEGB;
        }
    }
}

// ---------------- W transpose + convert: W[k][n] fp32 -> WT[n][k] bf16 -----------
__global__ void __launch_bounds__(256) w_convert(
    const float* __restrict__ Wq, const float* __restrict__ Wk,
    const float* __restrict__ Wv) {
    __shared__ float t[32][33];
    const int which = blockIdx.z;
    const float* W = (which == 0) ? Wq : (which == 1) ? Wk : Wv;
    uint16_t* WT = g_WTbf[which];
    const int x0 = blockIdx.x * 32, y0 = blockIdx.y * 32;  // x: n, y: k
    const int tx = threadIdx.x & 31, ty = threadIdx.x >> 5;
#pragma unroll
    for (int r = ty; r < 32; r += 8)
        t[r][tx] = W[(size_t)(y0 + r) * Uu + x0 + tx];
    __syncthreads();
    const int wt = threadIdx.x & 15, rn0 = threadIdx.x >> 4;
#pragma unroll
    for (int rr = 0; rr < 2; rr++) {
        const int rn = rn0 + rr * 16;
        uint32_t pw = packbf(t[2 * wt][rn], t[2 * wt + 1][rn]);
        *(uint32_t*)(WT + (size_t)(x0 + rn) * Uu + y0 + 2 * wt) = pw;
    }
}

// ---------------- bf16 mma GEMM + bias + ReLU, cp.async double-buffered ----------
#define KB2 64
#define AW 36
#define ABYTES (2 * 128 * AW * 4)
#define GEMM_SMEM (2 * ABYTES)

__global__ void __launch_bounds__(256, 2) gemm_bf16_kernel(
    const float* __restrict__ bi0, const float* __restrict__ bi1,
    const float* __restrict__ bi2) {
    extern __shared__ __align__(16) char gsm[];
    uint32_t (*As)[128][AW] = reinterpret_cast<uint32_t(*)[128][AW]>(gsm);
    uint32_t (*Bs)[128][AW] = reinterpret_cast<uint32_t(*)[128][AW]>(gsm + ABYTES);

    const int which = blockIdx.z;
    const uint16_t* Abf  = g_Abf[which];
    const uint16_t* WTbf = g_WTbf[which];
    const float* bias = (which == 0) ? bi0 : (which == 1) ? bi1 : bi2;

    const int tid = threadIdx.x;
    const int warp = tid >> 5, lane = tid & 31;
    const int g = lane >> 2, t = lane & 3;
    const int warpM = (warp >> 2) * 64, warpN = (warp & 3) * 32;
    const int n0 = blockIdx.x * 128, m0 = blockIdx.y * 128;

    float acc[4][4][4] = {};

    auto load_tiles = [&](int kb, int buf) {
#pragma unroll
        for (int i = 0; i < 4; i++) {
            const int idx = tid + i * 256;
            const int r = idx >> 3, s = idx & 7;
            cp16(&As[buf][r][s * 4], Abf + (size_t)(m0 + r) * Uu + kb + s * 8);
        }
#pragma unroll
        for (int i = 0; i < 4; i++) {
            const int idx = tid + i * 256;
            const int r = idx >> 3, s = idx & 7;
            cp16(&Bs[buf][r][s * 4], WTbf + (size_t)(n0 + r) * Uu + kb + s * 8);
        }
        CP_COMMIT();
    };

    load_tiles(0, 0);
#pragma unroll 1
    for (int it = 0; it < Uu / KB2; ++it) {
        const int buf = it & 1;
        if (it + 1 < Uu / KB2) { load_tiles((it + 1) * KB2, buf ^ 1); CP_WAIT1(); }
        else                   { CP_WAIT0(); }
        __syncthreads();

#pragma unroll
        for (int ks = 0; ks < 4; ks++) {
            uint32_t af[4][4], bf[4][2];
#pragma unroll
            for (int mi = 0; mi < 4; mi++) {
                const int mr = warpM + mi * 16 + g;
                af[mi][0] = As[buf][mr][8 * ks + t];
                af[mi][1] = As[buf][mr + 8][8 * ks + t];
                af[mi][2] = As[buf][mr][8 * ks + t + 4];
                af[mi][3] = As[buf][mr + 8][8 * ks + t + 4];
            }
#pragma unroll
            for (int ni = 0; ni < 4; ni++) {
                const int nc = warpN + ni * 8 + g;
                bf[ni][0] = Bs[buf][nc][8 * ks + t];
                bf[ni][1] = Bs[buf][nc][8 * ks + t + 4];
            }
#pragma unroll
            for (int mi = 0; mi < 4; mi++)
#pragma unroll
                for (int ni = 0; ni < 4; ni++)
                    mma16n8k16(acc[mi][ni], af[mi], bf[ni]);
        }
        __syncthreads();
    }

    if (which != 2) {
        uint16_t* C = (which == 0) ? g_Qbf : g_Kbf;
        const float osc = (which == 0) ? QSC : 1.0f;   // Q pre-scaled for log2 softmax
#pragma unroll
        for (int mi = 0; mi < 4; mi++) {
            const int r0 = m0 + warpM + mi * 16 + g;
#pragma unroll
            for (int ni = 0; ni < 4; ni++) {
                const int cc = n0 + warpN + ni * 8 + 2 * t;
                const float b0 = bias[cc], b1 = bias[cc + 1];
                uint32_t p0 = packbf(fmaxf(acc[mi][ni][0] + b0, 0.0f) * osc,
                                     fmaxf(acc[mi][ni][1] + b1, 0.0f) * osc);
                uint32_t p1 = packbf(fmaxf(acc[mi][ni][2] + b0, 0.0f) * osc,
                                     fmaxf(acc[mi][ni][3] + b1, 0.0f) * osc);
                *(uint32_t*)(C + (size_t)r0 * Uu + cc)       = p0;
                *(uint32_t*)(C + (size_t)(r0 + 8) * Uu + cc) = p1;
            }
        }
    } else {
        float (*tile)[132] = reinterpret_cast<float(*)[132]>(gsm);
#pragma unroll
        for (int mi = 0; mi < 4; mi++) {
            const int rl = warpM + mi * 16 + g;
#pragma unroll
            for (int ni = 0; ni < 4; ni++) {
                const int cl = warpN + ni * 8 + 2 * t;
                const float b0 = bias[n0 + cl], b1 = bias[n0 + cl + 1];
                tile[cl][rl]         = fmaxf(acc[mi][ni][0] + b0, 0.0f);
                tile[cl + 1][rl]     = fmaxf(acc[mi][ni][1] + b1, 0.0f);
                tile[cl][rl + 8]     = fmaxf(acc[mi][ni][2] + b0, 0.0f);
                tile[cl + 1][rl + 8] = fmaxf(acc[mi][ni][3] + b1, 0.0f);
            }
        }
        __syncthreads();
        const int bq = m0 >> 10, tok0 = m0 & 1023, hh = n0 >> 7;
        uint16_t* base = g_Vtbf + (((size_t)bq * Hh + hh) * Dd) * Tt + tok0;
#pragma unroll
        for (int i = 0; i < 8; i++) {
            const int idx = tid + i * 256;
            const int r = idx >> 4, seg = idx & 15;
            float4 a = *(float4*)&tile[r][seg * 8];
            float4 c = *(float4*)&tile[r][seg * 8 + 4];
            uint4 o = { packbf(a.x, a.y), packbf(a.z, a.w),
                        packbf(c.x, c.y), packbf(c.z, c.w) };
            *(uint4*)(base + (size_t)r * Tt + seg * 8) = o;
        }
    }
}

// ---------------- flash attention: bf16 mma, 128-thr CTA, 3 CTAs/SM --------------
// Q tile 64 x 128; K chunks 64; warp owns 16 rows. P kept in registers (mma A-frag
// layout == softmax lane layout). log2-domain softmax; additive key-mask bias.
#define QW 68   /* word pitch (%32==4 -> conflict-free) */
#define VW 36
struct ASmem {
    uint32_t Qs[64][QW];       // 17408 B
    uint32_t Ks[64][QW];       // 17408 B
    uint32_t Vts[128][VW];     // 18432 B  [d][key]
    float kb[2][64];           // 512 B
};                              // 53,760 B -> 3 CTAs/SM

__global__ void __launch_bounds__(128, 3) attn_kernel() {
    extern __shared__ char raw[];
    ASmem& sm = *(ASmem*)raw;
    const int qt = gridDim.x - 1 - blockIdx.x;   // long-first scheduling
    const int b = blockIdx.y, h = blockIdx.z;
    const int tid = threadIdx.x;
    const int warp = tid >> 5, lane = tid & 31;
    const int g = lane >> 2, t = lane & 3;

    const uint16_t* Qg  = g_Qbf + ((size_t)b * Tt + qt * 64) * Uu + h * Dd;
    const uint16_t* Kg  = g_Kbf + (size_t)b * Tt * Uu + h * Dd;
    const uint16_t* Vtg = g_Vtbf + ((size_t)b * Hh + h) * Dd * Tt;
    const float* kbg = g_kbias + b * Tt;

    auto load_k = [&](int kt, int kbuf) {
#pragma unroll
        for (int i = 0; i < 8; i++) {
            const int idx = tid + i * 128;
            const int r = idx >> 4, s = idx & 15;
            cp16(&sm.Ks[r][s * 4], Kg + (size_t)(kt * 64 + r) * Uu + s * 8);
        }
        if (tid < 16) cp16(&sm.kb[kbuf][tid * 4], kbg + kt * 64 + tid * 4);
    };
    auto load_v = [&](int kt) {
#pragma unroll
        for (int i = 0; i < 8; i++) {
            const int idx = tid + i * 128;
            const int r = idx >> 3, s = idx & 7;
            cp16(&sm.Vts[r][s * 4], Vtg + (size_t)r * Tt + kt * 64 + s * 8);
        }
    };

    // prologue: group A0 = {Q, K0, kb0}; group B0 = {V0}
#pragma unroll
    for (int i = 0; i < 8; i++) {
        const int idx = tid + i * 128;
        const int r = idx >> 4, s = idx & 15;
        cp16(&sm.Qs[r][s * 4], Qg + (size_t)r * Uu + s * 8);
    }
    load_k(0, 0);
    CP_COMMIT();
    load_v(0);
    CP_COMMIT();
    CP_WAIT1();          // Q/K0/kb0 landed (V0 may still fly)
    __syncthreads();

    float oacc[16][4] = {};
    float mrow0 = NEGB, mrow1 = NEGB, lrow0 = 0.0f, lrow1 = 0.0f;
    const int qrow0 = qt * 64 + 16 * warp + g;
    const int ktmax = qt;

    for (int kt = 0; kt <= ktmax; kt++) {
        const int kbuf = kt & 1;

        // S = Q K^T (log2-domain scores; Q pre-scaled)
        float sc[8][4] = {};
#pragma unroll
        for (int ks = 0; ks < 8; ks++) {
            uint32_t af[4];
            af[0] = sm.Qs[16 * warp + g][8 * ks + t];
            af[1] = sm.Qs[16 * warp + g + 8][8 * ks + t];
            af[2] = sm.Qs[16 * warp + g][8 * ks + t + 4];
            af[3] = sm.Qs[16 * warp + g + 8][8 * ks + t + 4];
#pragma unroll
            for (int ni = 0; ni < 8; ni++) {
                uint32_t bfr[2];
                bfr[0] = sm.Ks[8 * ni + g][8 * ks + t];
                bfr[1] = sm.Ks[8 * ni + g][8 * ks + t + 4];
                mma16n8k16(sc[ni], af, bfr);
            }
        }
        __syncthreads();                            // Ks consumed
        if (kt < ktmax) { load_k(kt + 1, kbuf ^ 1); CP_COMMIT(); }   // group A_{kt+1}

        // bias + (diagonal-only) causal + row max
        float mx0 = NEGB, mx1 = NEGB;
        if (kt < ktmax) {
#pragma unroll
            for (int ni = 0; ni < 8; ni++) {
                const float b0 = sm.kb[kbuf][8 * ni + 2 * t];
                const float b1 = sm.kb[kbuf][8 * ni + 2 * t + 1];
                sc[ni][0] += b0; sc[ni][1] += b1;
                sc[ni][2] += b0; sc[ni][3] += b1;
                mx0 = fmaxf(mx0, fmaxf(sc[ni][0], sc[ni][1]));
                mx1 = fmaxf(mx1, fmaxf(sc[ni][2], sc[ni][3]));
            }
        } else {
#pragma unroll
            for (int ni = 0; ni < 8; ni++) {
                const int kk = kt * 64 + 8 * ni + 2 * t;
                const float b0 = sm.kb[kbuf][8 * ni + 2 * t];
                const float b1 = sm.kb[kbuf][8 * ni + 2 * t + 1];
                float v0 = sc[ni][0] + b0; if (kk     > qrow0)     v0 = NEGB;
                float v1 = sc[ni][1] + b1; if (kk + 1 > qrow0)     v1 = NEGB;
                float v2 = sc[ni][2] + b0; if (kk     > qrow0 + 8) v2 = NEGB;
                float v3 = sc[ni][3] + b1; if (kk + 1 > qrow0 + 8) v3 = NEGB;
                sc[ni][0] = v0; sc[ni][1] = v1; sc[ni][2] = v2; sc[ni][3] = v3;
                mx0 = fmaxf(mx0, fmaxf(v0, v1));
                mx1 = fmaxf(mx1, fmaxf(v2, v3));
            }
        }
        mx0 = fmaxf(mx0, __shfl_xor_sync(0xffffffffu, mx0, 1));
        mx0 = fmaxf(mx0, __shfl_xor_sync(0xffffffffu, mx0, 2));
        mx1 = fmaxf(mx1, __shfl_xor_sync(0xffffffffu, mx1, 1));
        mx1 = fmaxf(mx1, __shfl_xor_sync(0xffffffffu, mx1, 2));

        const float mn0 = fmaxf(mrow0, mx0), mn1 = fmaxf(mrow1, mx1);
        const float al0 = ex2(mrow0 - mn0), al1 = ex2(mrow1 - mn1);
        float ps0 = 0.0f, ps1 = 0.0f;
        uint32_t pp[8][2];                  // P in registers = PV A-fragments
#pragma unroll
        for (int ni = 0; ni < 8; ni++) {
            float p0 = ex2(sc[ni][0] - mn0);
            float p1 = ex2(sc[ni][1] - mn0);
            float p2 = ex2(sc[ni][2] - mn1);
            float p3 = ex2(sc[ni][3] - mn1);
            ps0 += p0 + p1; ps1 += p2 + p3;
            pp[ni][0] = packbf(p0, p1);
            pp[ni][1] = packbf(p2, p3);
        }
        ps0 += __shfl_xor_sync(0xffffffffu, ps0, 1);
        ps0 += __shfl_xor_sync(0xffffffffu, ps0, 2);
        ps1 += __shfl_xor_sync(0xffffffffu, ps1, 1);
        ps1 += __shfl_xor_sync(0xffffffffu, ps1, 2);
        lrow0 = lrow0 * al0 + ps0;
        lrow1 = lrow1 * al1 + ps1;
        mrow0 = mn0; mrow1 = mn1;
#pragma unroll
        for (int ni = 0; ni < 16; ni++) {
            oacc[ni][0] *= al0; oacc[ni][1] *= al0;
            oacc[ni][2] *= al1; oacc[ni][3] *= al1;
        }

        // V(kt) landed?  (FIFO: B_kt drains before A_{kt+1})
        if (kt < ktmax) CP_WAIT1(); else CP_WAIT0();
        __syncthreads();

        // O += P @ V
#pragma unroll
        for (int ks = 0; ks < 4; ks++) {
            uint32_t af[4] = { pp[2 * ks][0], pp[2 * ks][1],
                               pp[2 * ks + 1][0], pp[2 * ks + 1][1] };
#pragma unroll
            for (int ni = 0; ni < 16; ni++) {
                uint32_t bfr[2];
                bfr[0] = sm.Vts[8 * ni + g][8 * ks + t];
                bfr[1] = sm.Vts[8 * ni + g][8 * ks + t + 4];
                mma16n8k16(oacc[ni], af, bfr);
            }
        }
        __syncthreads();                            // Vts consumed

        if (kt < ktmax) {
            load_v(kt + 1); CP_COMMIT();            // group B_{kt+1}
            CP_WAIT1();                             // A_{kt+1} done (FIFO)
            __syncthreads();                        // K visible to all
        }
    }

    // normalize, query mask, store
    const float inv0 = g_qmask[b * Tt + qrow0] / lrow0;
    const float inv1 = g_qmask[b * Tt + qrow0 + 8] / lrow1;
    float* AOg = g_AO + ((size_t)b * Tt + qrow0) * Uu + h * Dd;
#pragma unroll
    for (int ni = 0; ni < 16; ni++) {
        const int cc = 8 * ni + 2 * t;
        float2 o0, o1;
        o0.x = oacc[ni][0] * inv0; o0.y = oacc[ni][1] * inv0;
        o1.x = oacc[ni][2] * inv1; o1.y = oacc[ni][3] * inv1;
        *(float2*)(AOg + cc)                  = o0;
        *(float2*)(AOg + (size_t)8 * Uu + cc) = o1;
    }
}

// ---------------- residual + LayerNorm ------------------------------------------
__global__ void __launch_bounds__(256) ln_kernel(
    const float* __restrict__ Qin, const float* __restrict__ gamma,
    const float* __restrict__ beta, float* __restrict__ out) {
    __shared__ float red[2][8];
    const int row = blockIdx.x, tid = threadIdx.x;
    float4 a = ((const float4*)(g_AO + (size_t)row * 1024))[tid];
    float4 q = ((const float4*)(Qin + (size_t)row * 1024))[tid];
    float4 x;
    x.x = a.x + q.x; x.y = a.y + q.y; x.z = a.z + q.z; x.w = a.w + q.w;
    float s  = x.x + x.y + x.z + x.w;
    float ss = x.x * x.x + x.y * x.y + x.z * x.z + x.w * x.w;
#pragma unroll
    for (int off = 16; off; off >>= 1) {
        s  += __shfl_xor_sync(0xffffffffu, s, off);
        ss += __shfl_xor_sync(0xffffffffu, ss, off);
    }
    if ((tid & 31) == 0) { red[0][tid >> 5] = s; red[1][tid >> 5] = ss; }
    __syncthreads();
    s = 0.f; ss = 0.f;
#pragma unroll
    for (int w = 0; w < 8; w++) { s += red[0][w]; ss += red[1][w]; }
    const float mu = s * (1.0f / 1024.0f);
    const float var = ss * (1.0f / 1024.0f) - mu * mu;
    const float rstd = rsqrtf(var + 1e-5f);
    float4 g  = ((const float4*)gamma)[tid];
    float4 be = ((const float4*)beta)[tid];
    float4 o;
    o.x = (x.x - mu) * rstd * g.x + be.x;
    o.y = (x.y - mu) * rstd * g.y + be.y;
    o.z = (x.z - mu) * rstd * g.z + be.z;
    o.w = (x.w - mu) * rstd * g.w + be.w;
    ((float4*)(out + (size_t)row * 1024))[tid] = o;
}

// ---------------- launch ---------------------------------------------------------
extern "C" void kernel_launch(void* const* d_in, const int* in_sizes, int n_in,
                              void* d_out, int out_size) {
    const float* queries = (const float*)d_in[0];
    const float* keys    = (const float*)d_in[1];
    const float* values  = (const float*)d_in[2];
    const float* Wq = (const float*)d_in[3];
    const float* bq = (const float*)d_in[4];
    const float* Wk = (const float*)d_in[5];
    const float* bk = (const float*)d_in[6];
    const float* Wv = (const float*)d_in[7];
    const float* bv = (const float*)d_in[8];
    const float* gamma = (const float*)d_in[9];
    const float* beta  = (const float*)d_in[10];
    float* out = (float*)d_out;

    cudaFuncSetAttribute(attn_kernel, cudaFuncAttributeMaxDynamicSharedMemorySize,
                         (int)sizeof(ASmem));
    cudaFuncSetAttribute(gemm_bf16_kernel, cudaFuncAttributeMaxDynamicSharedMemorySize,
                         GEMM_SMEM);

    w_convert<<<dim3(32, 32, 3), 256>>>(Wq, Wk, Wv);
    a_convert<<<dim3(Bb * Tt, 3), 256>>>(queries, keys, values);

    gemm_bf16_kernel<<<dim3(8, 64, 3), 256, GEMM_SMEM>>>(bq, bk, bv);

    attn_kernel<<<dim3(Tt / 64, Bb, Hh), 128, sizeof(ASmem)>>>();

    ln_kernel<<<Bb * Tt, 256>>>(queries, gamma, beta, out);
}

// round 10
// speedup vs baseline: 6.2408x; 1.0086x over previous
#include <cuda_runtime.h>
#include <cstdint>

#define Bb 8
#define Tt 1024
#define Uu 1024
#define Hh 8
#define Dd 128
#define NEGB  -6.0e9f    /* log2-domain "-inf" */
#define QSC   (0.08838834764831845f * 1.44269504088896341f)  /* 1/sqrt(128) * log2(e) */

// ---------------- scratch (static device memory; no allocations) ----------------
__device__ uint16_t g_Abf[3][Bb * Tt * Uu];      // bf16 inputs
__device__ uint16_t g_WTbf[3][Uu * Uu];          // bf16 W^T [n][k]
__device__ uint16_t g_Qbf[Bb * Tt * Uu];         // bf16 Q, pre-scaled by QSC
__device__ uint16_t g_Kbf[Bb * Tt * Uu];         // bf16 K
__device__ uint16_t g_Vtbf[Bb * Hh * Dd * Tt];   // bf16 V^T per (b,h): [d][token]
__device__ float g_AO[Bb * Tt * Uu];
__device__ float g_qmask[Bb * Tt];               // 1/0
__device__ float g_kbias[Bb * Tt];               // 0 or NEGB

// ================= helpers =======================================================
__device__ __forceinline__ uint32_t packbf(float lo, float hi) {
    uint32_t r;
    asm("cvt.rn.bf16x2.f32 %0, %1, %2;" : "=r"(r) : "f"(hi), "f"(lo));
    return r;
}
__device__ __forceinline__ float ex2(float x) {
    float r;
    asm("ex2.approx.ftz.f32 %0, %1;" : "=f"(r) : "f"(x));
    return r;
}
__device__ __forceinline__ void mma16n8k16(float* d, const uint32_t* a, const uint32_t* b) {
    asm volatile(
        "mma.sync.aligned.m16n8k16.row.col.f32.bf16.bf16.f32 "
        "{%0,%1,%2,%3}, {%4,%5,%6,%7}, {%8,%9}, {%0,%1,%2,%3};"
        : "+f"(d[0]), "+f"(d[1]), "+f"(d[2]), "+f"(d[3])
        : "r"(a[0]), "r"(a[1]), "r"(a[2]), "r"(a[3]), "r"(b[0]), "r"(b[1]));
}
__device__ __forceinline__ void cp16(void* s, const void* g) {
    uint32_t sa = (uint32_t)__cvta_generic_to_shared(s);
    asm volatile("cp.async.cg.shared.global [%0], [%1], 16;" :: "r"(sa), "l"(g) : "memory");
}
#define CP_COMMIT() asm volatile("cp.async.commit_group;" ::: "memory")
#define CP_WAIT0()  asm volatile("cp.async.wait_group 0;" ::: "memory")
#define CP_WAIT1()  asm volatile("cp.async.wait_group 1;" ::: "memory")

// ---------------- input convert + row masks --------------------------------------
// grid (8192, 3): y=0 queries(+qmask), y=1 keys(+kbias), y=2 values
__global__ void __launch_bounds__(256) a_convert(
    const float* __restrict__ q, const float* __restrict__ k, const float* __restrict__ v) {
    __shared__ float red[8];
    const int y = blockIdx.y, row = blockIdx.x, tid = threadIdx.x;
    const float* src = (y == 0) ? q : (y == 1) ? k : v;
    float4 val = ((const float4*)(src + (size_t)row * 1024))[tid];
    uint2 p = { packbf(val.x, val.y), packbf(val.z, val.w) };
    ((uint2*)(g_Abf[y] + (size_t)row * 1024))[tid] = p;
    if (y < 2) {
        float s = val.x + val.y + val.z + val.w;
#pragma unroll
        for (int off = 16; off; off >>= 1) s += __shfl_xor_sync(0xffffffffu, s, off);
        if ((tid & 31) == 0) red[tid >> 5] = s;
        __syncthreads();
        if (tid == 0) {
            float t = 0.f;
#pragma unroll
            for (int w = 0; w < 8; w++) t += red[w];
            if (y == 0) g_qmask[row] = (t != 0.0f) ? 1.0f : 0.0f;
            else        g_kbias[row] = (t != 0.0f) ? 0.0f : NEGB;
        }
    }
}

// ---------------- W transpose + convert: W[k][n] fp32 -> WT[n][k] bf16 -----------
__global__ void __launch_bounds__(256) w_convert(
    const float* __restrict__ Wq, const float* __restrict__ Wk,
    const float* __restrict__ Wv) {
    __shared__ float t[32][33];
    const int which = blockIdx.z;
    const float* W = (which == 0) ? Wq : (which == 1) ? Wk : Wv;
    uint16_t* WT = g_WTbf[which];
    const int x0 = blockIdx.x * 32, y0 = blockIdx.y * 32;  // x: n, y: k
    const int tx = threadIdx.x & 31, ty = threadIdx.x >> 5;
#pragma unroll
    for (int r = ty; r < 32; r += 8)
        t[r][tx] = W[(size_t)(y0 + r) * Uu + x0 + tx];
    __syncthreads();
    const int wt = threadIdx.x & 15, rn0 = threadIdx.x >> 4;
#pragma unroll
    for (int rr = 0; rr < 2; rr++) {
        const int rn = rn0 + rr * 16;
        uint32_t pw = packbf(t[2 * wt][rn], t[2 * wt + 1][rn]);
        *(uint32_t*)(WT + (size_t)(x0 + rn) * Uu + y0 + 2 * wt) = pw;
    }
}

// ---------------- bf16 mma GEMM + bias + ReLU, cp.async double-buffered ----------
#define KB2 64
#define AW 36
#define ABYTES (2 * 128 * AW * 4)
#define GEMM_SMEM (2 * ABYTES)

__global__ void __launch_bounds__(256, 2) gemm_bf16_kernel(
    const float* __restrict__ bi0, const float* __restrict__ bi1,
    const float* __restrict__ bi2) {
    extern __shared__ __align__(16) char gsm[];
    uint32_t (*As)[128][AW] = reinterpret_cast<uint32_t(*)[128][AW]>(gsm);
    uint32_t (*Bs)[128][AW] = reinterpret_cast<uint32_t(*)[128][AW]>(gsm + ABYTES);

    const int which = blockIdx.z;
    const uint16_t* Abf  = g_Abf[which];
    const uint16_t* WTbf = g_WTbf[which];
    const float* bias = (which == 0) ? bi0 : (which == 1) ? bi1 : bi2;

    const int tid = threadIdx.x;
    const int warp = tid >> 5, lane = tid & 31;
    const int g = lane >> 2, t = lane & 3;
    const int warpM = (warp >> 2) * 64, warpN = (warp & 3) * 32;
    const int n0 = blockIdx.x * 128, m0 = blockIdx.y * 128;

    float acc[4][4][4] = {};

    auto load_tiles = [&](int kb, int buf) {
#pragma unroll
        for (int i = 0; i < 4; i++) {
            const int idx = tid + i * 256;
            const int r = idx >> 3, s = idx & 7;
            cp16(&As[buf][r][s * 4], Abf + (size_t)(m0 + r) * Uu + kb + s * 8);
        }
#pragma unroll
        for (int i = 0; i < 4; i++) {
            const int idx = tid + i * 256;
            const int r = idx >> 3, s = idx & 7;
            cp16(&Bs[buf][r][s * 4], WTbf + (size_t)(n0 + r) * Uu + kb + s * 8);
        }
        CP_COMMIT();
    };

    load_tiles(0, 0);
#pragma unroll 1
    for (int it = 0; it < Uu / KB2; ++it) {
        const int buf = it & 1;
        if (it + 1 < Uu / KB2) { load_tiles((it + 1) * KB2, buf ^ 1); CP_WAIT1(); }
        else                   { CP_WAIT0(); }
        __syncthreads();

#pragma unroll
        for (int ks = 0; ks < 4; ks++) {
            uint32_t af[4][4], bf[4][2];
#pragma unroll
            for (int mi = 0; mi < 4; mi++) {
                const int mr = warpM + mi * 16 + g;
                af[mi][0] = As[buf][mr][8 * ks + t];
                af[mi][1] = As[buf][mr + 8][8 * ks + t];
                af[mi][2] = As[buf][mr][8 * ks + t + 4];
                af[mi][3] = As[buf][mr + 8][8 * ks + t + 4];
            }
#pragma unroll
            for (int ni = 0; ni < 4; ni++) {
                const int nc = warpN + ni * 8 + g;
                bf[ni][0] = Bs[buf][nc][8 * ks + t];
                bf[ni][1] = Bs[buf][nc][8 * ks + t + 4];
            }
#pragma unroll
            for (int mi = 0; mi < 4; mi++)
#pragma unroll
                for (int ni = 0; ni < 4; ni++)
                    mma16n8k16(acc[mi][ni], af[mi], bf[ni]);
        }
        __syncthreads();
    }

    if (which != 2) {
        uint16_t* C = (which == 0) ? g_Qbf : g_Kbf;
        const float osc = (which == 0) ? QSC : 1.0f;   // Q pre-scaled for log2 softmax
#pragma unroll
        for (int mi = 0; mi < 4; mi++) {
            const int r0 = m0 + warpM + mi * 16 + g;
#pragma unroll
            for (int ni = 0; ni < 4; ni++) {
                const int cc = n0 + warpN + ni * 8 + 2 * t;
                const float b0 = bias[cc], b1 = bias[cc + 1];
                uint32_t p0 = packbf(fmaxf(acc[mi][ni][0] + b0, 0.0f) * osc,
                                     fmaxf(acc[mi][ni][1] + b1, 0.0f) * osc);
                uint32_t p1 = packbf(fmaxf(acc[mi][ni][2] + b0, 0.0f) * osc,
                                     fmaxf(acc[mi][ni][3] + b1, 0.0f) * osc);
                *(uint32_t*)(C + (size_t)r0 * Uu + cc)       = p0;
                *(uint32_t*)(C + (size_t)(r0 + 8) * Uu + cc) = p1;
            }
        }
    } else {
        float (*tile)[132] = reinterpret_cast<float(*)[132]>(gsm);
#pragma unroll
        for (int mi = 0; mi < 4; mi++) {
            const int rl = warpM + mi * 16 + g;
#pragma unroll
            for (int ni = 0; ni < 4; ni++) {
                const int cl = warpN + ni * 8 + 2 * t;
                const float b0 = bias[n0 + cl], b1 = bias[n0 + cl + 1];
                tile[cl][rl]         = fmaxf(acc[mi][ni][0] + b0, 0.0f);
                tile[cl + 1][rl]     = fmaxf(acc[mi][ni][1] + b1, 0.0f);
                tile[cl][rl + 8]     = fmaxf(acc[mi][ni][2] + b0, 0.0f);
                tile[cl + 1][rl + 8] = fmaxf(acc[mi][ni][3] + b1, 0.0f);
            }
        }
        __syncthreads();
        const int bq = m0 >> 10, tok0 = m0 & 1023, hh = n0 >> 7;
        uint16_t* base = g_Vtbf + (((size_t)bq * Hh + hh) * Dd) * Tt + tok0;
#pragma unroll
        for (int i = 0; i < 8; i++) {
            const int idx = tid + i * 256;
            const int r = idx >> 4, seg = idx & 15;
            float4 a = *(float4*)&tile[r][seg * 8];
            float4 c = *(float4*)&tile[r][seg * 8 + 4];
            uint4 o = { packbf(a.x, a.y), packbf(a.z, a.w),
                        packbf(c.x, c.y), packbf(c.z, c.w) };
            *(uint4*)(base + (size_t)r * Tt + seg * 8) = o;
        }
    }
}

// ---------------- flash attention: bf16 mma, fully double-buffered ---------------
// Q tile 64 x 128; K/V chunks of 64 keys, BOTH double-buffered.
// ONE barrier per iteration -> warps skew across QK/softmax/PV, tensor overlap.
#define QW 68   /* word pitch (%32==4 -> conflict-free) */
#define VW 36
struct ASmem {
    uint32_t Qs[64][QW];          // 17408 B
    uint32_t Ks[2][64][QW];       // 34816 B
    uint32_t Vts[2][128][VW];     // 36864 B  [d][key]
    float kb[2][64];              // 512 B
};                                 // 89,600 B -> 2 CTAs/SM

__global__ void __launch_bounds__(128, 2) attn_kernel() {
    extern __shared__ char raw[];
    ASmem& sm = *(ASmem*)raw;
    const int qt = gridDim.x - 1 - blockIdx.x;   // long-first scheduling
    const int b = blockIdx.y, h = blockIdx.z;
    const int tid = threadIdx.x;
    const int warp = tid >> 5, lane = tid & 31;
    const int g = lane >> 2, t = lane & 3;

    const uint16_t* Qg  = g_Qbf + ((size_t)b * Tt + qt * 64) * Uu + h * Dd;
    const uint16_t* Kg  = g_Kbf + (size_t)b * Tt * Uu + h * Dd;
    const uint16_t* Vtg = g_Vtbf + ((size_t)b * Hh + h) * Dd * Tt;
    const float* kbg = g_kbias + b * Tt;

    // one commit group per chunk: {K, V, kb}
    auto load_kv = [&](int kt, int buf) {
#pragma unroll
        for (int i = 0; i < 8; i++) {
            const int idx = tid + i * 128;
            const int r = idx >> 4, s = idx & 15;
            cp16(&sm.Ks[buf][r][s * 4], Kg + (size_t)(kt * 64 + r) * Uu + s * 8);
        }
#pragma unroll
        for (int i = 0; i < 8; i++) {
            const int idx = tid + i * 128;
            const int r = idx >> 3, s = idx & 7;
            cp16(&sm.Vts[buf][r][s * 4], Vtg + (size_t)r * Tt + kt * 64 + s * 8);
        }
        if (tid < 16) cp16(&sm.kb[buf][tid * 4], kbg + kt * 64 + tid * 4);
        CP_COMMIT();
    };

    // prologue: Q + chunk 0 in one group
#pragma unroll
    for (int i = 0; i < 8; i++) {
        const int idx = tid + i * 128;
        const int r = idx >> 4, s = idx & 15;
        cp16(&sm.Qs[r][s * 4], Qg + (size_t)r * Uu + s * 8);
    }
    load_kv(0, 0);
    CP_WAIT0();
    __syncthreads();

    float oacc[16][4] = {};
    float mrow0 = NEGB, mrow1 = NEGB, lrow0 = 0.0f, lrow1 = 0.0f;
    const int qrow0 = qt * 64 + 16 * warp + g;
    const int ktmax = qt;

    for (int kt = 0; kt <= ktmax; kt++) {
        const int buf = kt & 1;

        // issue next chunk's loads FIRST (other buffer; safe: its last readers
        // finished before the previous end-of-iter barrier)
        if (kt < ktmax) load_kv(kt + 1, buf ^ 1);

        // S = Q K^T (log2-domain scores; Q pre-scaled)
        float sc[8][4] = {};
#pragma unroll
        for (int ks = 0; ks < 8; ks++) {
            uint32_t af[4];
            af[0] = sm.Qs[16 * warp + g][8 * ks + t];
            af[1] = sm.Qs[16 * warp + g + 8][8 * ks + t];
            af[2] = sm.Qs[16 * warp + g][8 * ks + t + 4];
            af[3] = sm.Qs[16 * warp + g + 8][8 * ks + t + 4];
#pragma unroll
            for (int ni = 0; ni < 8; ni++) {
                uint32_t bfr[2];
                bfr[0] = sm.Ks[buf][8 * ni + g][8 * ks + t];
                bfr[1] = sm.Ks[buf][8 * ni + g][8 * ks + t + 4];
                mma16n8k16(sc[ni], af, bfr);
            }
        }

        // bias + (diagonal-only) causal + row max
        float mx0 = NEGB, mx1 = NEGB;
        if (kt < ktmax) {
#pragma unroll
            for (int ni = 0; ni < 8; ni++) {
                const float b0 = sm.kb[buf][8 * ni + 2 * t];
                const float b1 = sm.kb[buf][8 * ni + 2 * t + 1];
                sc[ni][0] += b0; sc[ni][1] += b1;
                sc[ni][2] += b0; sc[ni][3] += b1;
                mx0 = fmaxf(mx0, fmaxf(sc[ni][0], sc[ni][1]));
                mx1 = fmaxf(mx1, fmaxf(sc[ni][2], sc[ni][3]));
            }
        } else {
#pragma unroll
            for (int ni = 0; ni < 8; ni++) {
                const int kk = kt * 64 + 8 * ni + 2 * t;
                const float b0 = sm.kb[buf][8 * ni + 2 * t];
                const float b1 = sm.kb[buf][8 * ni + 2 * t + 1];
                float v0 = sc[ni][0] + b0; if (kk     > qrow0)     v0 = NEGB;
                float v1 = sc[ni][1] + b1; if (kk + 1 > qrow0)     v1 = NEGB;
                float v2 = sc[ni][2] + b0; if (kk     > qrow0 + 8) v2 = NEGB;
                float v3 = sc[ni][3] + b1; if (kk + 1 > qrow0 + 8) v3 = NEGB;
                sc[ni][0] = v0; sc[ni][1] = v1; sc[ni][2] = v2; sc[ni][3] = v3;
                mx0 = fmaxf(mx0, fmaxf(v0, v1));
                mx1 = fmaxf(mx1, fmaxf(v2, v3));
            }
        }
        mx0 = fmaxf(mx0, __shfl_xor_sync(0xffffffffu, mx0, 1));
        mx0 = fmaxf(mx0, __shfl_xor_sync(0xffffffffu, mx0, 2));
        mx1 = fmaxf(mx1, __shfl_xor_sync(0xffffffffu, mx1, 1));
        mx1 = fmaxf(mx1, __shfl_xor_sync(0xffffffffu, mx1, 2));

        const float mn0 = fmaxf(mrow0, mx0), mn1 = fmaxf(mrow1, mx1);
        const float al0 = ex2(mrow0 - mn0), al1 = ex2(mrow1 - mn1);
        float ps0 = 0.0f, ps1 = 0.0f;
        uint32_t pp[8][2];                  // P in registers = PV A-fragments
#pragma unroll
        for (int ni = 0; ni < 8; ni++) {
            float p0 = ex2(sc[ni][0] - mn0);
            float p1 = ex2(sc[ni][1] - mn0);
            float p2 = ex2(sc[ni][2] - mn1);
            float p3 = ex2(sc[ni][3] - mn1);
            ps0 += p0 + p1; ps1 += p2 + p3;
            pp[ni][0] = packbf(p0, p1);
            pp[ni][1] = packbf(p2, p3);
        }
        ps0 += __shfl_xor_sync(0xffffffffu, ps0, 1);
        ps0 += __shfl_xor_sync(0xffffffffu, ps0, 2);
        ps1 += __shfl_xor_sync(0xffffffffu, ps1, 1);
        ps1 += __shfl_xor_sync(0xffffffffu, ps1, 2);
        lrow0 = lrow0 * al0 + ps0;
        lrow1 = lrow1 * al1 + ps1;
        mrow0 = mn0; mrow1 = mn1;
#pragma unroll
        for (int ni = 0; ni < 16; ni++) {
            oacc[ni][0] *= al0; oacc[ni][1] *= al0;
            oacc[ni][2] *= al1; oacc[ni][3] *= al1;
        }

        // O += P @ V  (current buffer)
#pragma unroll
        for (int ks = 0; ks < 4; ks++) {
            uint32_t af[4] = { pp[2 * ks][0], pp[2 * ks][1],
                               pp[2 * ks + 1][0], pp[2 * ks + 1][1] };
#pragma unroll
            for (int ni = 0; ni < 16; ni++) {
                uint32_t bfr[2];
                bfr[0] = sm.Vts[buf][8 * ni + g][8 * ks + t];
                bfr[1] = sm.Vts[buf][8 * ni + g][8 * ks + t + 4];
                mma16n8k16(oacc[ni], af, bfr);
            }
        }

        // single per-iter rendezvous: next chunk landed + visible to all
        if (kt < ktmax) {
            CP_WAIT0();
            __syncthreads();
        }
    }

    // normalize, query mask, store
    const float inv0 = g_qmask[b * Tt + qrow0] / lrow0;
    const float inv1 = g_qmask[b * Tt + qrow0 + 8] / lrow1;
    float* AOg = g_AO + ((size_t)b * Tt + qrow0) * Uu + h * Dd;
#pragma unroll
    for (int ni = 0; ni < 16; ni++) {
        const int cc = 8 * ni + 2 * t;
        float2 o0, o1;
        o0.x = oacc[ni][0] * inv0; o0.y = oacc[ni][1] * inv0;
        o1.x = oacc[ni][2] * inv1; o1.y = oacc[ni][3] * inv1;
        *(float2*)(AOg + cc)                  = o0;
        *(float2*)(AOg + (size_t)8 * Uu + cc) = o1;
    }
}

// ---------------- residual + LayerNorm ------------------------------------------
__global__ void __launch_bounds__(256) ln_kernel(
    const float* __restrict__ Qin, const float* __restrict__ gamma,
    const float* __restrict__ beta, float* __restrict__ out) {
    __shared__ float red[2][8];
    const int row = blockIdx.x, tid = threadIdx.x;
    float4 a = ((const float4*)(g_AO + (size_t)row * 1024))[tid];
    float4 q = ((const float4*)(Qin + (size_t)row * 1024))[tid];
    float4 x;
    x.x = a.x + q.x; x.y = a.y + q.y; x.z = a.z + q.z; x.w = a.w + q.w;
    float s  = x.x + x.y + x.z + x.w;
    float ss = x.x * x.x + x.y * x.y + x.z * x.z + x.w * x.w;
#pragma unroll
    for (int off = 16; off; off >>= 1) {
        s  += __shfl_xor_sync(0xffffffffu, s, off);
        ss += __shfl_xor_sync(0xffffffffu, ss, off);
    }
    if ((tid & 31) == 0) { red[0][tid >> 5] = s; red[1][tid >> 5] = ss; }
    __syncthreads();
    s = 0.f; ss = 0.f;
#pragma unroll
    for (int w = 0; w < 8; w++) { s += red[0][w]; ss += red[1][w]; }
    const float mu = s * (1.0f / 1024.0f);
    const float var = ss * (1.0f / 1024.0f) - mu * mu;
    const float rstd = rsqrtf(var + 1e-5f);
    float4 g  = ((const float4*)gamma)[tid];
    float4 be = ((const float4*)beta)[tid];
    float4 o;
    o.x = (x.x - mu) * rstd * g.x + be.x;
    o.y = (x.y - mu) * rstd * g.y + be.y;
    o.z = (x.z - mu) * rstd * g.z + be.z;
    o.w = (x.w - mu) * rstd * g.w + be.w;
    ((float4*)(out + (size_t)row * 1024))[tid] = o;
}

// ---------------- launch ---------------------------------------------------------
extern "C" void kernel_launch(void* const* d_in, const int* in_sizes, int n_in,
                              void* d_out, int out_size) {
    const float* queries = (const float*)d_in[0];
    const float* keys    = (const float*)d_in[1];
    const float* values  = (const float*)d_in[2];
    const float* Wq = (const float*)d_in[3];
    const float* bq = (const float*)d_in[4];
    const float* Wk = (const float*)d_in[5];
    const float* bk = (const float*)d_in[6];
    const float* Wv = (const float*)d_in[7];
    const float* bv = (const float*)d_in[8];
    const float* gamma = (const float*)d_in[9];
    const float* beta  = (const float*)d_in[10];
    float* out = (float*)d_out;

    cudaFuncSetAttribute(attn_kernel, cudaFuncAttributeMaxDynamicSharedMemorySize,
                         (int)sizeof(ASmem));
    cudaFuncSetAttribute(gemm_bf16_kernel, cudaFuncAttributeMaxDynamicSharedMemorySize,
                         GEMM_SMEM);

    w_convert<<<dim3(32, 32, 3), 256>>>(Wq, Wk, Wv);
    a_convert<<<dim3(Bb * Tt, 3), 256>>>(queries, keys, values);

    gemm_bf16_kernel<<<dim3(8, 64, 3), 256, GEMM_SMEM>>>(bq, bk, bv);

    attn_kernel<<<dim3(Tt / 64, Bb, Hh), 128, sizeof(ASmem)>>>();

    ln_kernel<<<Bb * Tt, 256>>>(queries, gamma, beta, out);
}

// round 11
// speedup vs baseline: 6.7194x; 1.0767x over previous
#include <cuda_runtime.h>
#include <cstdint>

#define Bb 8
#define Tt 1024
#define Uu 1024
#define Hh 8
#define Dd 128
#define NEGB  -6.0e9f    /* log2-domain "-inf" */
#define QSC   (0.08838834764831845f * 1.44269504088896341f)  /* 1/sqrt(128) * log2(e) */

// ---------------- scratch (static device memory; no allocations) ----------------
__device__ uint16_t g_Abf[3][Bb * Tt * Uu];      // bf16 inputs
__device__ uint16_t g_WTbf[3][Uu * Uu];          // bf16 W^T [n][k]
__device__ uint16_t g_Qbf[Bb * Tt * Uu];         // bf16 Q, pre-scaled by QSC
__device__ uint16_t g_Kbf[Bb * Tt * Uu];         // bf16 K
__device__ uint16_t g_Vtbf[Bb * Hh * Dd * Tt];   // bf16 V^T per (b,h): [d][token]
__device__ float g_AO[Bb * Tt * Uu];
__device__ float g_qmask[Bb * Tt];               // 1/0
__device__ float g_kbias[Bb * Tt];               // 0 or NEGB

// ================= helpers =======================================================
__device__ __forceinline__ uint32_t packbf(float lo, float hi) {
    uint32_t r;
    asm("cvt.rn.bf16x2.f32 %0, %1, %2;" : "=r"(r) : "f"(hi), "f"(lo));
    return r;
}
__device__ __forceinline__ float ex2(float x) {
    float r;
    asm("ex2.approx.ftz.f32 %0, %1;" : "=f"(r) : "f"(x));
    return r;
}
__device__ __forceinline__ void mma16n8k16(float* d, const uint32_t* a, const uint32_t* b) {
    asm volatile(
        "mma.sync.aligned.m16n8k16.row.col.f32.bf16.bf16.f32 "
        "{%0,%1,%2,%3}, {%4,%5,%6,%7}, {%8,%9}, {%0,%1,%2,%3};"
        : "+f"(d[0]), "+f"(d[1]), "+f"(d[2]), "+f"(d[3])
        : "r"(a[0]), "r"(a[1]), "r"(a[2]), "r"(a[3]), "r"(b[0]), "r"(b[1]));
}
__device__ __forceinline__ void cp16(void* s, const void* g) {
    uint32_t sa = (uint32_t)__cvta_generic_to_shared(s);
    asm volatile("cp.async.cg.shared.global [%0], [%1], 16;" :: "r"(sa), "l"(g) : "memory");
}
__device__ __forceinline__ void ldsm4(uint32_t& r0, uint32_t& r1, uint32_t& r2,
                                      uint32_t& r3, uint32_t addr) {
    asm volatile("ldmatrix.sync.aligned.m8n8.x4.shared.b16 {%0,%1,%2,%3}, [%4];"
                 : "=r"(r0), "=r"(r1), "=r"(r2), "=r"(r3) : "r"(addr));
}
__device__ __forceinline__ uint32_t sptr(const void* p) {
    return (uint32_t)__cvta_generic_to_shared(p);
}
#define CP_COMMIT() asm volatile("cp.async.commit_group;" ::: "memory")
#define CP_WAIT0()  asm volatile("cp.async.wait_group 0;" ::: "memory")
#define CP_WAIT1()  asm volatile("cp.async.wait_group 1;" ::: "memory")

// ldmatrix lane patterns:
//  A-operand (a0..a3): lanes 0-7 rows, 8-15 rows+8, 16-23 words+4, 24-31 rows+8/words+4
//  B-operand (b0,b1 for n-rows, then +8 rows): lanes 0-7 rows, 8-15 words+4,
//  16-23 rows+8, 24-31 rows+8/words+4
#define AROW(l) (((l) & 7) + ((((l) >> 3) & 1) << 3))
#define ACOL(l) ((((l) >> 4) & 1) * 4)
#define BROW(l) (((l) & 7) + (((l) >> 4) << 3))
#define BCOL(l) ((((l) >> 3) & 1) * 4)

// ---------------- input convert + row masks --------------------------------------
__global__ void __launch_bounds__(256) a_convert(
    const float* __restrict__ q, const float* __restrict__ k, const float* __restrict__ v) {
    __shared__ float red[8];
    const int y = blockIdx.y, row = blockIdx.x, tid = threadIdx.x;
    const float* src = (y == 0) ? q : (y == 1) ? k : v;
    float4 val = ((const float4*)(src + (size_t)row * 1024))[tid];
    uint2 p = { packbf(val.x, val.y), packbf(val.z, val.w) };
    ((uint2*)(g_Abf[y] + (size_t)row * 1024))[tid] = p;
    if (y < 2) {
        float s = val.x + val.y + val.z + val.w;
#pragma unroll
        for (int off = 16; off; off >>= 1) s += __shfl_xor_sync(0xffffffffu, s, off);
        if ((tid & 31) == 0) red[tid >> 5] = s;
        __syncthreads();
        if (tid == 0) {
            float t = 0.f;
#pragma unroll
            for (int w = 0; w < 8; w++) t += red[w];
            if (y == 0) g_qmask[row] = (t != 0.0f) ? 1.0f : 0.0f;
            else        g_kbias[row] = (t != 0.0f) ? 0.0f : NEGB;
        }
    }
}

// ---------------- W transpose + convert: W[k][n] fp32 -> WT[n][k] bf16 -----------
__global__ void __launch_bounds__(256) w_convert(
    const float* __restrict__ Wq, const float* __restrict__ Wk,
    const float* __restrict__ Wv) {
    __shared__ float t[32][33];
    const int which = blockIdx.z;
    const float* W = (which == 0) ? Wq : (which == 1) ? Wk : Wv;
    uint16_t* WT = g_WTbf[which];
    const int x0 = blockIdx.x * 32, y0 = blockIdx.y * 32;  // x: n, y: k
    const int tx = threadIdx.x & 31, ty = threadIdx.x >> 5;
#pragma unroll
    for (int r = ty; r < 32; r += 8)
        t[r][tx] = W[(size_t)(y0 + r) * Uu + x0 + tx];
    __syncthreads();
    const int wt = threadIdx.x & 15, rn0 = threadIdx.x >> 4;
#pragma unroll
    for (int rr = 0; rr < 2; rr++) {
        const int rn = rn0 + rr * 16;
        uint32_t pw = packbf(t[2 * wt][rn], t[2 * wt + 1][rn]);
        *(uint32_t*)(WT + (size_t)(x0 + rn) * Uu + y0 + 2 * wt) = pw;
    }
}

// ---------------- bf16 mma GEMM + bias + ReLU, cp.async + ldmatrix ---------------
#define KB2 64
#define AW 36
#define ABYTES (2 * 128 * AW * 4)
#define GEMM_SMEM (2 * ABYTES)

__global__ void __launch_bounds__(256, 2) gemm_bf16_kernel(
    const float* __restrict__ bi0, const float* __restrict__ bi1,
    const float* __restrict__ bi2) {
    extern __shared__ __align__(16) char gsm[];
    uint32_t (*As)[128][AW] = reinterpret_cast<uint32_t(*)[128][AW]>(gsm);
    uint32_t (*Bs)[128][AW] = reinterpret_cast<uint32_t(*)[128][AW]>(gsm + ABYTES);

    const int which = blockIdx.z;
    const uint16_t* Abf  = g_Abf[which];
    const uint16_t* WTbf = g_WTbf[which];
    const float* bias = (which == 0) ? bi0 : (which == 1) ? bi1 : bi2;

    const int tid = threadIdx.x;
    const int warp = tid >> 5, lane = tid & 31;
    const int g = lane >> 2, t = lane & 3;
    const int warpM = (warp >> 2) * 64, warpN = (warp & 3) * 32;
    const int n0 = blockIdx.x * 128, m0 = blockIdx.y * 128;

    const int arow = AROW(lane), acol = ACOL(lane);
    const int brow = BROW(lane), bcol = BCOL(lane);

    float acc[4][4][4] = {};

    auto load_tiles = [&](int kb, int buf) {
#pragma unroll
        for (int i = 0; i < 4; i++) {
            const int idx = tid + i * 256;
            const int r = idx >> 3, s = idx & 7;
            cp16(&As[buf][r][s * 4], Abf + (size_t)(m0 + r) * Uu + kb + s * 8);
        }
#pragma unroll
        for (int i = 0; i < 4; i++) {
            const int idx = tid + i * 256;
            const int r = idx >> 3, s = idx & 7;
            cp16(&Bs[buf][r][s * 4], WTbf + (size_t)(n0 + r) * Uu + kb + s * 8);
        }
        CP_COMMIT();
    };

    load_tiles(0, 0);
#pragma unroll 1
    for (int it = 0; it < Uu / KB2; ++it) {
        const int buf = it & 1;
        if (it + 1 < Uu / KB2) { load_tiles((it + 1) * KB2, buf ^ 1); CP_WAIT1(); }
        else                   { CP_WAIT0(); }
        __syncthreads();

        const uint32_t abase = sptr(&As[buf][warpM + arow][acol]);
        const uint32_t bbase = sptr(&Bs[buf][warpN + brow][bcol]);
#pragma unroll
        for (int ks = 0; ks < 4; ks++) {
            uint32_t af[4][4], bf[4][2];
#pragma unroll
            for (int mi = 0; mi < 4; mi++)
                ldsm4(af[mi][0], af[mi][1], af[mi][2], af[mi][3],
                      abase + mi * (16 * AW * 4) + ks * 32);
#pragma unroll
            for (int n2 = 0; n2 < 2; n2++)
                ldsm4(bf[2 * n2][0], bf[2 * n2][1], bf[2 * n2 + 1][0], bf[2 * n2 + 1][1],
                      bbase + n2 * (16 * AW * 4) + ks * 32);
#pragma unroll
            for (int mi = 0; mi < 4; mi++)
#pragma unroll
                for (int ni = 0; ni < 4; ni++)
                    mma16n8k16(acc[mi][ni], af[mi], bf[ni]);
        }
        __syncthreads();
    }

    if (which != 2) {
        uint16_t* C = (which == 0) ? g_Qbf : g_Kbf;
        const float osc = (which == 0) ? QSC : 1.0f;   // Q pre-scaled for log2 softmax
#pragma unroll
        for (int mi = 0; mi < 4; mi++) {
            const int r0 = m0 + warpM + mi * 16 + g;
#pragma unroll
            for (int ni = 0; ni < 4; ni++) {
                const int cc = n0 + warpN + ni * 8 + 2 * t;
                const float b0 = bias[cc], b1 = bias[cc + 1];
                uint32_t p0 = packbf(fmaxf(acc[mi][ni][0] + b0, 0.0f) * osc,
                                     fmaxf(acc[mi][ni][1] + b1, 0.0f) * osc);
                uint32_t p1 = packbf(fmaxf(acc[mi][ni][2] + b0, 0.0f) * osc,
                                     fmaxf(acc[mi][ni][3] + b1, 0.0f) * osc);
                *(uint32_t*)(C + (size_t)r0 * Uu + cc)       = p0;
                *(uint32_t*)(C + (size_t)(r0 + 8) * Uu + cc) = p1;
            }
        }
    } else {
        float (*tile)[132] = reinterpret_cast<float(*)[132]>(gsm);
#pragma unroll
        for (int mi = 0; mi < 4; mi++) {
            const int rl = warpM + mi * 16 + g;
#pragma unroll
            for (int ni = 0; ni < 4; ni++) {
                const int cl = warpN + ni * 8 + 2 * t;
                const float b0 = bias[n0 + cl], b1 = bias[n0 + cl + 1];
                tile[cl][rl]         = fmaxf(acc[mi][ni][0] + b0, 0.0f);
                tile[cl + 1][rl]     = fmaxf(acc[mi][ni][1] + b1, 0.0f);
                tile[cl][rl + 8]     = fmaxf(acc[mi][ni][2] + b0, 0.0f);
                tile[cl + 1][rl + 8] = fmaxf(acc[mi][ni][3] + b1, 0.0f);
            }
        }
        __syncthreads();
        const int bq = m0 >> 10, tok0 = m0 & 1023, hh = n0 >> 7;
        uint16_t* base = g_Vtbf + (((size_t)bq * Hh + hh) * Dd) * Tt + tok0;
#pragma unroll
        for (int i = 0; i < 8; i++) {
            const int idx = tid + i * 256;
            const int r = idx >> 4, seg = idx & 15;
            float4 a = *(float4*)&tile[r][seg * 8];
            float4 c = *(float4*)&tile[r][seg * 8 + 4];
            uint4 o = { packbf(a.x, a.y), packbf(a.z, a.w),
                        packbf(c.x, c.y), packbf(c.z, c.w) };
            *(uint4*)(base + (size_t)r * Tt + seg * 8) = o;
        }
    }
}

// ---------------- flash attention: bf16 mma + ldmatrix, double-buffered ----------
#define QW 68   /* word pitch (%32==4 -> conflict-free ldmatrix phases) */
#define VW 36
struct ASmem {
    uint32_t Qs[64][QW];          // 17408 B
    uint32_t Ks[2][64][QW];       // 34816 B
    uint32_t Vts[2][128][VW];     // 36864 B  [d][key]
    float kb[2][64];              // 512 B
};                                 // 89,600 B -> 2 CTAs/SM

__global__ void __launch_bounds__(128, 2) attn_kernel() {
    extern __shared__ char raw[];
    ASmem& sm = *(ASmem*)raw;
    const int qt = gridDim.x - 1 - blockIdx.x;   // long-first scheduling
    const int b = blockIdx.y, h = blockIdx.z;
    const int tid = threadIdx.x;
    const int warp = tid >> 5, lane = tid & 31;
    const int g = lane >> 2, t = lane & 3;

    const uint16_t* Qg  = g_Qbf + ((size_t)b * Tt + qt * 64) * Uu + h * Dd;
    const uint16_t* Kg  = g_Kbf + (size_t)b * Tt * Uu + h * Dd;
    const uint16_t* Vtg = g_Vtbf + ((size_t)b * Hh + h) * Dd * Tt;
    const float* kbg = g_kbias + b * Tt;

    const int arow = AROW(lane), acol = ACOL(lane);
    const int brow = BROW(lane), bcol = BCOL(lane);

    // one commit group per chunk: {K, V, kb}
    auto load_kv = [&](int kt, int buf) {
#pragma unroll
        for (int i = 0; i < 8; i++) {
            const int idx = tid + i * 128;
            const int r = idx >> 4, s = idx & 15;
            cp16(&sm.Ks[buf][r][s * 4], Kg + (size_t)(kt * 64 + r) * Uu + s * 8);
        }
#pragma unroll
        for (int i = 0; i < 8; i++) {
            const int idx = tid + i * 128;
            const int r = idx >> 3, s = idx & 7;
            cp16(&sm.Vts[buf][r][s * 4], Vtg + (size_t)r * Tt + kt * 64 + s * 8);
        }
        if (tid < 16) cp16(&sm.kb[buf][tid * 4], kbg + kt * 64 + tid * 4);
        CP_COMMIT();
    };

    // prologue: Q + chunk 0 in one group
#pragma unroll
    for (int i = 0; i < 8; i++) {
        const int idx = tid + i * 128;
        const int r = idx >> 4, s = idx & 15;
        cp16(&sm.Qs[r][s * 4], Qg + (size_t)r * Uu + s * 8);
    }
    load_kv(0, 0);
    CP_WAIT0();
    __syncthreads();

    // hoist Q fragments via ldmatrix (8 ks x 4 regs)
    uint32_t qf[8][4];
    {
        const uint32_t qbase = sptr(&sm.Qs[16 * warp + arow][acol]);
#pragma unroll
        for (int ks = 0; ks < 8; ks++)
            ldsm4(qf[ks][0], qf[ks][1], qf[ks][2], qf[ks][3], qbase + ks * 32);
    }

    float oacc[16][4] = {};
    float mrow0 = NEGB, mrow1 = NEGB, lrow0 = 0.0f, lrow1 = 0.0f;
    const int qrow0 = qt * 64 + 16 * warp + g;
    const int ktmax = qt;

    for (int kt = 0; kt <= ktmax; kt++) {
        const int buf = kt & 1;

        // issue next chunk's loads first (other buffer)
        if (kt < ktmax) load_kv(kt + 1, buf ^ 1);

        // S = Q K^T via ldmatrix B-frags (each ldsm4 covers 2 ni)
        float sc[8][4] = {};
        {
            const uint32_t kbase = sptr(&sm.Ks[buf][brow][bcol]);
#pragma unroll
            for (int ks = 0; ks < 8; ks++) {
#pragma unroll
                for (int n2 = 0; n2 < 4; n2++) {
                    uint32_t b0, b1, b2, b3;
                    ldsm4(b0, b1, b2, b3, kbase + n2 * (16 * QW * 4) + ks * 32);
                    uint32_t bfA[2] = { b0, b1 };
                    uint32_t bfB[2] = { b2, b3 };
                    mma16n8k16(sc[2 * n2],     qf[ks], bfA);
                    mma16n8k16(sc[2 * n2 + 1], qf[ks], bfB);
                }
            }
        }

        // bias + (diagonal-only) causal + row max
        float mx0 = NEGB, mx1 = NEGB;
        if (kt < ktmax) {
#pragma unroll
            for (int ni = 0; ni < 8; ni++) {
                const float b0 = sm.kb[buf][8 * ni + 2 * t];
                const float b1 = sm.kb[buf][8 * ni + 2 * t + 1];
                sc[ni][0] += b0; sc[ni][1] += b1;
                sc[ni][2] += b0; sc[ni][3] += b1;
                mx0 = fmaxf(mx0, fmaxf(sc[ni][0], sc[ni][1]));
                mx1 = fmaxf(mx1, fmaxf(sc[ni][2], sc[ni][3]));
            }
        } else {
#pragma unroll
            for (int ni = 0; ni < 8; ni++) {
                const int kk = kt * 64 + 8 * ni + 2 * t;
                const float b0 = sm.kb[buf][8 * ni + 2 * t];
                const float b1 = sm.kb[buf][8 * ni + 2 * t + 1];
                float v0 = sc[ni][0] + b0; if (kk     > qrow0)     v0 = NEGB;
                float v1 = sc[ni][1] + b1; if (kk + 1 > qrow0)     v1 = NEGB;
                float v2 = sc[ni][2] + b0; if (kk     > qrow0 + 8) v2 = NEGB;
                float v3 = sc[ni][3] + b1; if (kk + 1 > qrow0 + 8) v3 = NEGB;
                sc[ni][0] = v0; sc[ni][1] = v1; sc[ni][2] = v2; sc[ni][3] = v3;
                mx0 = fmaxf(mx0, fmaxf(v0, v1));
                mx1 = fmaxf(mx1, fmaxf(v2, v3));
            }
        }
        mx0 = fmaxf(mx0, __shfl_xor_sync(0xffffffffu, mx0, 1));
        mx0 = fmaxf(mx0, __shfl_xor_sync(0xffffffffu, mx0, 2));
        mx1 = fmaxf(mx1, __shfl_xor_sync(0xffffffffu, mx1, 1));
        mx1 = fmaxf(mx1, __shfl_xor_sync(0xffffffffu, mx1, 2));

        const float mn0 = fmaxf(mrow0, mx0), mn1 = fmaxf(mrow1, mx1);
        const float al0 = ex2(mrow0 - mn0), al1 = ex2(mrow1 - mn1);
        float ps0 = 0.0f, ps1 = 0.0f;
        uint32_t pp[8][2];                  // P in registers = PV A-fragments
#pragma unroll
        for (int ni = 0; ni < 8; ni++) {
            float p0 = ex2(sc[ni][0] - mn0);
            float p1 = ex2(sc[ni][1] - mn0);
            float p2 = ex2(sc[ni][2] - mn1);
            float p3 = ex2(sc[ni][3] - mn1);
            ps0 += p0 + p1; ps1 += p2 + p3;
            pp[ni][0] = packbf(p0, p1);
            pp[ni][1] = packbf(p2, p3);
        }
        ps0 += __shfl_xor_sync(0xffffffffu, ps0, 1);
        ps0 += __shfl_xor_sync(0xffffffffu, ps0, 2);
        ps1 += __shfl_xor_sync(0xffffffffu, ps1, 1);
        ps1 += __shfl_xor_sync(0xffffffffu, ps1, 2);
        lrow0 = lrow0 * al0 + ps0;
        lrow1 = lrow1 * al1 + ps1;
        mrow0 = mn0; mrow1 = mn1;
#pragma unroll
        for (int ni = 0; ni < 16; ni++) {
            oacc[ni][0] *= al0; oacc[ni][1] *= al0;
            oacc[ni][2] *= al1; oacc[ni][3] *= al1;
        }

        // O += P @ V via ldmatrix B-frags (each ldsm4 covers 2 d-frags)
        {
            const uint32_t vbase = sptr(&sm.Vts[buf][brow][bcol]);
#pragma unroll
            for (int ks = 0; ks < 4; ks++) {
                uint32_t af[4] = { pp[2 * ks][0], pp[2 * ks][1],
                                   pp[2 * ks + 1][0], pp[2 * ks + 1][1] };
#pragma unroll
                for (int n2 = 0; n2 < 8; n2++) {
                    uint32_t b0, b1, b2, b3;
                    ldsm4(b0, b1, b2, b3, vbase + n2 * (16 * VW * 4) + ks * 32);
                    uint32_t bfA[2] = { b0, b1 };
                    uint32_t bfB[2] = { b2, b3 };
                    mma16n8k16(oacc[2 * n2],     af, bfA);
                    mma16n8k16(oacc[2 * n2 + 1], af, bfB);
                }
            }
        }

        // single per-iter rendezvous: next chunk landed + visible to all
        if (kt < ktmax) {
            CP_WAIT0();
            __syncthreads();
        }
    }

    // normalize, query mask, store
    const float inv0 = g_qmask[b * Tt + qrow0] / lrow0;
    const float inv1 = g_qmask[b * Tt + qrow0 + 8] / lrow1;
    float* AOg = g_AO + ((size_t)b * Tt + qrow0) * Uu + h * Dd;
#pragma unroll
    for (int ni = 0; ni < 16; ni++) {
        const int cc = 8 * ni + 2 * t;
        float2 o0, o1;
        o0.x = oacc[ni][0] * inv0; o0.y = oacc[ni][1] * inv0;
        o1.x = oacc[ni][2] * inv1; o1.y = oacc[ni][3] * inv1;
        *(float2*)(AOg + cc)                  = o0;
        *(float2*)(AOg + (size_t)8 * Uu + cc) = o1;
    }
}

// ---------------- residual + LayerNorm ------------------------------------------
__global__ void __launch_bounds__(256) ln_kernel(
    const float* __restrict__ Qin, const float* __restrict__ gamma,
    const float* __restrict__ beta, float* __restrict__ out) {
    __shared__ float red[2][8];
    const int row = blockIdx.x, tid = threadIdx.x;
    float4 a = ((const float4*)(g_AO + (size_t)row * 1024))[tid];
    float4 q = ((const float4*)(Qin + (size_t)row * 1024))[tid];
    float4 x;
    x.x = a.x + q.x; x.y = a.y + q.y; x.z = a.z + q.z; x.w = a.w + q.w;
    float s  = x.x + x.y + x.z + x.w;
    float ss = x.x * x.x + x.y * x.y + x.z * x.z + x.w * x.w;
#pragma unroll
    for (int off = 16; off; off >>= 1) {
        s  += __shfl_xor_sync(0xffffffffu, s, off);
        ss += __shfl_xor_sync(0xffffffffu, ss, off);
    }
    if ((tid & 31) == 0) { red[0][tid >> 5] = s; red[1][tid >> 5] = ss; }
    __syncthreads();
    s = 0.f; ss = 0.f;
#pragma unroll
    for (int w = 0; w < 8; w++) { s += red[0][w]; ss += red[1][w]; }
    const float mu = s * (1.0f / 1024.0f);
    const float var = ss * (1.0f / 1024.0f) - mu * mu;
    const float rstd = rsqrtf(var + 1e-5f);
    float4 g  = ((const float4*)gamma)[tid];
    float4 be = ((const float4*)beta)[tid];
    float4 o;
    o.x = (x.x - mu) * rstd * g.x + be.x;
    o.y = (x.y - mu) * rstd * g.y + be.y;
    o.z = (x.z - mu) * rstd * g.z + be.z;
    o.w = (x.w - mu) * rstd * g.w + be.w;
    ((float4*)(out + (size_t)row * 1024))[tid] = o;
}

// ---------------- launch ---------------------------------------------------------
extern "C" void kernel_launch(void* const* d_in, const int* in_sizes, int n_in,
                              void* d_out, int out_size) {
    const float* queries = (const float*)d_in[0];
    const float* keys    = (const float*)d_in[1];
    const float* values  = (const float*)d_in[2];
    const float* Wq = (const float*)d_in[3];
    const float* bq = (const float*)d_in[4];
    const float* Wk = (const float*)d_in[5];
    const float* bk = (const float*)d_in[6];
    const float* Wv = (const float*)d_in[7];
    const float* bv = (const float*)d_in[8];
    const float* gamma = (const float*)d_in[9];
    const float* beta  = (const float*)d_in[10];
    float* out = (float*)d_out;

    cudaFuncSetAttribute(attn_kernel, cudaFuncAttributeMaxDynamicSharedMemorySize,
                         (int)sizeof(ASmem));
    cudaFuncSetAttribute(gemm_bf16_kernel, cudaFuncAttributeMaxDynamicSharedMemorySize,
                         GEMM_SMEM);

    w_convert<<<dim3(32, 32, 3), 256>>>(Wq, Wk, Wv);
    a_convert<<<dim3(Bb * Tt, 3), 256>>>(queries, keys, values);

    gemm_bf16_kernel<<<dim3(8, 64, 3), 256, GEMM_SMEM>>>(bq, bk, bv);

    attn_kernel<<<dim3(Tt / 64, Bb, Hh), 128, sizeof(ASmem)>>>();

    ln_kernel<<<Bb * Tt, 256>>>(queries, gamma, beta, out);
}

// round 12
// speedup vs baseline: 6.8253x; 1.0158x over previous
#include <cuda_runtime.h>
#include <cstdint>

#define Bb 8
#define Tt 1024
#define Uu 1024
#define Hh 8
#define Dd 128
#define NEGB  -6.0e9f    /* log2-domain "-inf" */
#define QSC   (0.08838834764831845f * 1.44269504088896341f)  /* 1/sqrt(128) * log2(e) */

// ---------------- scratch (static device memory; no allocations) ----------------
__device__ uint16_t g_Abf[3][Bb * Tt * Uu];      // bf16 inputs
__device__ uint16_t g_WTbf[3][Uu * Uu];          // bf16 W^T [n][k]
__device__ uint16_t g_Qbf[Bb * Tt * Uu];         // bf16 Q, pre-scaled by QSC
__device__ uint16_t g_Kbf[Bb * Tt * Uu];         // bf16 K
__device__ uint16_t g_Vtbf[Bb * Hh * Dd * Tt];   // bf16 V^T per (b,h): [d][token]
__device__ float g_AO[Bb * Tt * Uu];
__device__ float g_qmask[Bb * Tt];               // 1/0
__device__ float g_kbias[Bb * Tt];               // 0 or NEGB

// ================= helpers =======================================================
__device__ __forceinline__ uint32_t packbf(float lo, float hi) {
    uint32_t r;
    asm("cvt.rn.bf16x2.f32 %0, %1, %2;" : "=r"(r) : "f"(hi), "f"(lo));
    return r;
}
__device__ __forceinline__ float ex2(float x) {
    float r;
    asm("ex2.approx.ftz.f32 %0, %1;" : "=f"(r) : "f"(x));
    return r;
}
__device__ __forceinline__ void mma16n8k16(float* d, const uint32_t* a, const uint32_t* b) {
    asm volatile(
        "mma.sync.aligned.m16n8k16.row.col.f32.bf16.bf16.f32 "
        "{%0,%1,%2,%3}, {%4,%5,%6,%7}, {%8,%9}, {%0,%1,%2,%3};"
        : "+f"(d[0]), "+f"(d[1]), "+f"(d[2]), "+f"(d[3])
        : "r"(a[0]), "r"(a[1]), "r"(a[2]), "r"(a[3]), "r"(b[0]), "r"(b[1]));
}
__device__ __forceinline__ void cp16(void* s, const void* g) {
    uint32_t sa = (uint32_t)__cvta_generic_to_shared(s);
    asm volatile("cp.async.cg.shared.global [%0], [%1], 16;" :: "r"(sa), "l"(g) : "memory");
}
__device__ __forceinline__ void ldsm4(uint32_t& r0, uint32_t& r1, uint32_t& r2,
                                      uint32_t& r3, uint32_t addr) {
    asm volatile("ldmatrix.sync.aligned.m8n8.x4.shared.b16 {%0,%1,%2,%3}, [%4];"
                 : "=r"(r0), "=r"(r1), "=r"(r2), "=r"(r3) : "r"(addr));
}
__device__ __forceinline__ uint32_t sptr(const void* p) {
    return (uint32_t)__cvta_generic_to_shared(p);
}
#define CP_COMMIT() asm volatile("cp.async.commit_group;" ::: "memory")
#define CP_WAIT0()  asm volatile("cp.async.wait_group 0;" ::: "memory")
#define CP_WAIT1()  asm volatile("cp.async.wait_group 1;" ::: "memory")

// ldmatrix lane address patterns
#define AROW(l) (((l) & 7) + ((((l) >> 3) & 1) << 3))
#define ACOL(l) ((((l) >> 4) & 1) * 4)
#define BROW(l) (((l) & 7) + (((l) >> 4) << 3))
#define BCOL(l) ((((l) >> 3) & 1) * 4)

// ---------------- input convert + row masks --------------------------------------
__global__ void __launch_bounds__(256) a_convert(
    const float* __restrict__ q, const float* __restrict__ k, const float* __restrict__ v) {
    __shared__ float red[8];
    const int y = blockIdx.y, row = blockIdx.x, tid = threadIdx.x;
    const float* src = (y == 0) ? q : (y == 1) ? k : v;
    float4 val = ((const float4*)(src + (size_t)row * 1024))[tid];
    uint2 p = { packbf(val.x, val.y), packbf(val.z, val.w) };
    ((uint2*)(g_Abf[y] + (size_t)row * 1024))[tid] = p;
    if (y < 2) {
        float s = val.x + val.y + val.z + val.w;
#pragma unroll
        for (int off = 16; off; off >>= 1) s += __shfl_xor_sync(0xffffffffu, s, off);
        if ((tid & 31) == 0) red[tid >> 5] = s;
        __syncthreads();
        if (tid == 0) {
            float t = 0.f;
#pragma unroll
            for (int w = 0; w < 8; w++) t += red[w];
            if (y == 0) g_qmask[row] = (t != 0.0f) ? 1.0f : 0.0f;
            else        g_kbias[row] = (t != 0.0f) ? 0.0f : NEGB;
        }
    }
}

// ---------------- W transpose + convert: W[k][n] fp32 -> WT[n][k] bf16 -----------
__global__ void __launch_bounds__(256) w_convert(
    const float* __restrict__ Wq, const float* __restrict__ Wk,
    const float* __restrict__ Wv) {
    __shared__ float t[32][33];
    const int which = blockIdx.z;
    const float* W = (which == 0) ? Wq : (which == 1) ? Wk : Wv;
    uint16_t* WT = g_WTbf[which];
    const int x0 = blockIdx.x * 32, y0 = blockIdx.y * 32;  // x: n, y: k
    const int tx = threadIdx.x & 31, ty = threadIdx.x >> 5;
#pragma unroll
    for (int r = ty; r < 32; r += 8)
        t[r][tx] = W[(size_t)(y0 + r) * Uu + x0 + tx];
    __syncthreads();
    const int wt = threadIdx.x & 15, rn0 = threadIdx.x >> 4;
#pragma unroll
    for (int rr = 0; rr < 2; rr++) {
        const int rn = rn0 + rr * 16;
        uint32_t pw = packbf(t[2 * wt][rn], t[2 * wt + 1][rn]);
        *(uint32_t*)(WT + (size_t)(x0 + rn) * Uu + y0 + 2 * wt) = pw;
    }
}

// ---------------- bf16 mma GEMM, 3-stage cp.async pipeline + ldmatrix ------------
#define KB2 64
#define AW 36
#define HALF_ST (128 * AW * 4)          /* 18432: one operand tile */
#define STB (2 * HALF_ST)               /* 36864: A+B per stage */
#define NSTAGE 3
#define GEMM_SMEM (NSTAGE * STB)        /* 110592 */
#define NKB (Uu / KB2)                  /* 16 */

__global__ void __launch_bounds__(256, 2) gemm_bf16_kernel(
    const float* __restrict__ bi0, const float* __restrict__ bi1,
    const float* __restrict__ bi2) {
    extern __shared__ __align__(16) char gsm[];

    const int which = blockIdx.z;
    const uint16_t* Abf  = g_Abf[which];
    const uint16_t* WTbf = g_WTbf[which];
    const float* bias = (which == 0) ? bi0 : (which == 1) ? bi1 : bi2;

    const int tid = threadIdx.x;
    const int warp = tid >> 5, lane = tid & 31;
    const int g = lane >> 2, t = lane & 3;
    const int warpM = (warp >> 2) * 64, warpN = (warp & 3) * 32;
    const int n0 = blockIdx.x * 128, m0 = blockIdx.y * 128;

    const int arow = AROW(lane), acol = ACOL(lane);
    const int brow = BROW(lane), bcol = BCOL(lane);

    float acc[4][4][4] = {};

    auto load_tiles = [&](int kb, int st) {
        uint32_t (*As)[AW] = reinterpret_cast<uint32_t(*)[AW]>(gsm + st * STB);
        uint32_t (*Bs)[AW] = reinterpret_cast<uint32_t(*)[AW]>(gsm + st * STB + HALF_ST);
#pragma unroll
        for (int i = 0; i < 4; i++) {
            const int idx = tid + i * 256;
            const int r = idx >> 3, s = idx & 7;
            cp16(&As[r][s * 4], Abf + (size_t)(m0 + r) * Uu + kb + s * 8);
        }
#pragma unroll
        for (int i = 0; i < 4; i++) {
            const int idx = tid + i * 256;
            const int r = idx >> 3, s = idx & 7;
            cp16(&Bs[r][s * 4], WTbf + (size_t)(n0 + r) * Uu + kb + s * 8);
        }
        CP_COMMIT();
    };

    // prologue: 2 stages in flight
    load_tiles(0, 0);
    load_tiles(KB2, 1);

#pragma unroll 1
    for (int it = 0; it < NKB; ++it) {
        const int st = it % NSTAGE;
        // drain this stage's group; barrier also releases stage (it+2)%3 for rewrite
        if (it + 1 < NKB) CP_WAIT1(); else CP_WAIT0();
        __syncthreads();
        if (it + 2 < NKB) load_tiles((it + 2) * KB2, (it + 2) % NSTAGE);

        const uint32_t abase = sptr(gsm + st * STB) +
                               (warpM + arow) * (AW * 4) + acol * 4;
        const uint32_t bbase = sptr(gsm + st * STB + HALF_ST) +
                               (warpN + brow) * (AW * 4) + bcol * 4;
#pragma unroll
        for (int ks = 0; ks < 4; ks++) {
            uint32_t af[4][4], bf[4][2];
#pragma unroll
            for (int mi = 0; mi < 4; mi++)
                ldsm4(af[mi][0], af[mi][1], af[mi][2], af[mi][3],
                      abase + mi * (16 * AW * 4) + ks * 32);
#pragma unroll
            for (int n2 = 0; n2 < 2; n2++)
                ldsm4(bf[2 * n2][0], bf[2 * n2][1], bf[2 * n2 + 1][0], bf[2 * n2 + 1][1],
                      bbase + n2 * (16 * AW * 4) + ks * 32);
#pragma unroll
            for (int mi = 0; mi < 4; mi++)
#pragma unroll
                for (int ni = 0; ni < 4; ni++)
                    mma16n8k16(acc[mi][ni], af[mi], bf[ni]);
        }
    }
    __syncthreads();   // all compute done before epilogue may reuse gsm (V path)

    if (which != 2) {
        uint16_t* C = (which == 0) ? g_Qbf : g_Kbf;
        const float osc = (which == 0) ? QSC : 1.0f;   // Q pre-scaled for log2 softmax
#pragma unroll
        for (int mi = 0; mi < 4; mi++) {
            const int r0 = m0 + warpM + mi * 16 + g;
#pragma unroll
            for (int ni = 0; ni < 4; ni++) {
                const int cc = n0 + warpN + ni * 8 + 2 * t;
                const float b0 = bias[cc], b1 = bias[cc + 1];
                uint32_t p0 = packbf(fmaxf(acc[mi][ni][0] + b0, 0.0f) * osc,
                                     fmaxf(acc[mi][ni][1] + b1, 0.0f) * osc);
                uint32_t p1 = packbf(fmaxf(acc[mi][ni][2] + b0, 0.0f) * osc,
                                     fmaxf(acc[mi][ni][3] + b1, 0.0f) * osc);
                *(uint32_t*)(C + (size_t)r0 * Uu + cc)       = p0;
                *(uint32_t*)(C + (size_t)(r0 + 8) * Uu + cc) = p1;
            }
        }
    } else {
        float (*tile)[132] = reinterpret_cast<float(*)[132]>(gsm);
#pragma unroll
        for (int mi = 0; mi < 4; mi++) {
            const int rl = warpM + mi * 16 + g;
#pragma unroll
            for (int ni = 0; ni < 4; ni++) {
                const int cl = warpN + ni * 8 + 2 * t;
                const float b0 = bias[n0 + cl], b1 = bias[n0 + cl + 1];
                tile[cl][rl]         = fmaxf(acc[mi][ni][0] + b0, 0.0f);
                tile[cl + 1][rl]     = fmaxf(acc[mi][ni][1] + b1, 0.0f);
                tile[cl][rl + 8]     = fmaxf(acc[mi][ni][2] + b0, 0.0f);
                tile[cl + 1][rl + 8] = fmaxf(acc[mi][ni][3] + b1, 0.0f);
            }
        }
        __syncthreads();
        const int bq = m0 >> 10, tok0 = m0 & 1023, hh = n0 >> 7;
        uint16_t* base = g_Vtbf + (((size_t)bq * Hh + hh) * Dd) * Tt + tok0;
#pragma unroll
        for (int i = 0; i < 8; i++) {
            const int idx = tid + i * 256;
            const int r = idx >> 4, seg = idx & 15;
            float4 a = *(float4*)&tile[r][seg * 8];
            float4 c = *(float4*)&tile[r][seg * 8 + 4];
            uint4 o = { packbf(a.x, a.y), packbf(a.z, a.w),
                        packbf(c.x, c.y), packbf(c.z, c.w) };
            *(uint4*)(base + (size_t)r * Tt + seg * 8) = o;
        }
    }
}

// ---------------- flash attention: bf16 mma + ldmatrix, double-buffered ----------
#define QW 68   /* word pitch (%32==4 -> conflict-free ldmatrix phases) */
#define VW 36
struct ASmem {
    uint32_t Qs[64][QW];          // 17408 B
    uint32_t Ks[2][64][QW];       // 34816 B
    uint32_t Vts[2][128][VW];     // 36864 B  [d][key]
    float kb[2][64];              // 512 B
};                                 // 89,600 B -> 2 CTAs/SM

__global__ void __launch_bounds__(128, 2) attn_kernel() {
    extern __shared__ char raw[];
    ASmem& sm = *(ASmem*)raw;
    const int qt = gridDim.x - 1 - blockIdx.x;   // long-first scheduling
    const int b = blockIdx.y, h = blockIdx.z;
    const int tid = threadIdx.x;
    const int warp = tid >> 5, lane = tid & 31;
    const int g = lane >> 2, t = lane & 3;

    const uint16_t* Qg  = g_Qbf + ((size_t)b * Tt + qt * 64) * Uu + h * Dd;
    const uint16_t* Kg  = g_Kbf + (size_t)b * Tt * Uu + h * Dd;
    const uint16_t* Vtg = g_Vtbf + ((size_t)b * Hh + h) * Dd * Tt;
    const float* kbg = g_kbias + b * Tt;

    const int arow = AROW(lane), acol = ACOL(lane);
    const int brow = BROW(lane), bcol = BCOL(lane);

    auto load_kv = [&](int kt, int buf) {
#pragma unroll
        for (int i = 0; i < 8; i++) {
            const int idx = tid + i * 128;
            const int r = idx >> 4, s = idx & 15;
            cp16(&sm.Ks[buf][r][s * 4], Kg + (size_t)(kt * 64 + r) * Uu + s * 8);
        }
#pragma unroll
        for (int i = 0; i < 8; i++) {
            const int idx = tid + i * 128;
            const int r = idx >> 3, s = idx & 7;
            cp16(&sm.Vts[buf][r][s * 4], Vtg + (size_t)r * Tt + kt * 64 + s * 8);
        }
        if (tid < 16) cp16(&sm.kb[buf][tid * 4], kbg + kt * 64 + tid * 4);
        CP_COMMIT();
    };

    // prologue: Q + chunk 0 in one group
#pragma unroll
    for (int i = 0; i < 8; i++) {
        const int idx = tid + i * 128;
        const int r = idx >> 4, s = idx & 15;
        cp16(&sm.Qs[r][s * 4], Qg + (size_t)r * Uu + s * 8);
    }
    load_kv(0, 0);
    CP_WAIT0();
    __syncthreads();

    // hoist Q fragments via ldmatrix (8 ks x 4 regs)
    uint32_t qf[8][4];
    {
        const uint32_t qbase = sptr(&sm.Qs[16 * warp + arow][acol]);
#pragma unroll
        for (int ks = 0; ks < 8; ks++)
            ldsm4(qf[ks][0], qf[ks][1], qf[ks][2], qf[ks][3], qbase + ks * 32);
    }

    float oacc[16][4] = {};
    float mrow0 = NEGB, mrow1 = NEGB, lrow0 = 0.0f, lrow1 = 0.0f;
    const int qrow0 = qt * 64 + 16 * warp + g;
    const int ktmax = qt;

    for (int kt = 0; kt <= ktmax; kt++) {
        const int buf = kt & 1;

        if (kt < ktmax) load_kv(kt + 1, buf ^ 1);

        // S = Q K^T via ldmatrix B-frags
        float sc[8][4] = {};
        {
            const uint32_t kbase = sptr(&sm.Ks[buf][brow][bcol]);
#pragma unroll
            for (int ks = 0; ks < 8; ks++) {
#pragma unroll
                for (int n2 = 0; n2 < 4; n2++) {
                    uint32_t b0, b1, b2, b3;
                    ldsm4(b0, b1, b2, b3, kbase + n2 * (16 * QW * 4) + ks * 32);
                    uint32_t bfA[2] = { b0, b1 };
                    uint32_t bfB[2] = { b2, b3 };
                    mma16n8k16(sc[2 * n2],     qf[ks], bfA);
                    mma16n8k16(sc[2 * n2 + 1], qf[ks], bfB);
                }
            }
        }

        // bias + (diagonal-only) causal + row max
        float mx0 = NEGB, mx1 = NEGB;
        if (kt < ktmax) {
#pragma unroll
            for (int ni = 0; ni < 8; ni++) {
                const float b0 = sm.kb[buf][8 * ni + 2 * t];
                const float b1 = sm.kb[buf][8 * ni + 2 * t + 1];
                sc[ni][0] += b0; sc[ni][1] += b1;
                sc[ni][2] += b0; sc[ni][3] += b1;
                mx0 = fmaxf(mx0, fmaxf(sc[ni][0], sc[ni][1]));
                mx1 = fmaxf(mx1, fmaxf(sc[ni][2], sc[ni][3]));
            }
        } else {
#pragma unroll
            for (int ni = 0; ni < 8; ni++) {
                const int kk = kt * 64 + 8 * ni + 2 * t;
                const float b0 = sm.kb[buf][8 * ni + 2 * t];
                const float b1 = sm.kb[buf][8 * ni + 2 * t + 1];
                float v0 = sc[ni][0] + b0; if (kk     > qrow0)     v0 = NEGB;
                float v1 = sc[ni][1] + b1; if (kk + 1 > qrow0)     v1 = NEGB;
                float v2 = sc[ni][2] + b0; if (kk     > qrow0 + 8) v2 = NEGB;
                float v3 = sc[ni][3] + b1; if (kk + 1 > qrow0 + 8) v3 = NEGB;
                sc[ni][0] = v0; sc[ni][1] = v1; sc[ni][2] = v2; sc[ni][3] = v3;
                mx0 = fmaxf(mx0, fmaxf(v0, v1));
                mx1 = fmaxf(mx1, fmaxf(v2, v3));
            }
        }
        mx0 = fmaxf(mx0, __shfl_xor_sync(0xffffffffu, mx0, 1));
        mx0 = fmaxf(mx0, __shfl_xor_sync(0xffffffffu, mx0, 2));
        mx1 = fmaxf(mx1, __shfl_xor_sync(0xffffffffu, mx1, 1));
        mx1 = fmaxf(mx1, __shfl_xor_sync(0xffffffffu, mx1, 2));

        const float mn0 = fmaxf(mrow0, mx0), mn1 = fmaxf(mrow1, mx1);
        const float al0 = ex2(mrow0 - mn0), al1 = ex2(mrow1 - mn1);
        float ps0 = 0.0f, ps1 = 0.0f;
        uint32_t pp[8][2];                  // P in registers = PV A-fragments
#pragma unroll
        for (int ni = 0; ni < 8; ni++) {
            float p0 = ex2(sc[ni][0] - mn0);
            float p1 = ex2(sc[ni][1] - mn0);
            float p2 = ex2(sc[ni][2] - mn1);
            float p3 = ex2(sc[ni][3] - mn1);
            ps0 += p0 + p1; ps1 += p2 + p3;
            pp[ni][0] = packbf(p0, p1);
            pp[ni][1] = packbf(p2, p3);
        }
        ps0 += __shfl_xor_sync(0xffffffffu, ps0, 1);
        ps0 += __shfl_xor_sync(0xffffffffu, ps0, 2);
        ps1 += __shfl_xor_sync(0xffffffffu, ps1, 1);
        ps1 += __shfl_xor_sync(0xffffffffu, ps1, 2);
        lrow0 = lrow0 * al0 + ps0;
        lrow1 = lrow1 * al1 + ps1;
        mrow0 = mn0; mrow1 = mn1;
#pragma unroll
        for (int ni = 0; ni < 16; ni++) {
            oacc[ni][0] *= al0; oacc[ni][1] *= al0;
            oacc[ni][2] *= al1; oacc[ni][3] *= al1;
        }

        // O += P @ V via ldmatrix B-frags
        {
            const uint32_t vbase = sptr(&sm.Vts[buf][brow][bcol]);
#pragma unroll
            for (int ks = 0; ks < 4; ks++) {
                uint32_t af[4] = { pp[2 * ks][0], pp[2 * ks][1],
                                   pp[2 * ks + 1][0], pp[2 * ks + 1][1] };
#pragma unroll
                for (int n2 = 0; n2 < 8; n2++) {
                    uint32_t b0, b1, b2, b3;
                    ldsm4(b0, b1, b2, b3, vbase + n2 * (16 * VW * 4) + ks * 32);
                    uint32_t bfA[2] = { b0, b1 };
                    uint32_t bfB[2] = { b2, b3 };
                    mma16n8k16(oacc[2 * n2],     af, bfA);
                    mma16n8k16(oacc[2 * n2 + 1], af, bfB);
                }
            }
        }

        if (kt < ktmax) {
            CP_WAIT0();
            __syncthreads();
        }
    }

    // normalize, query mask, store
    const float inv0 = g_qmask[b * Tt + qrow0] / lrow0;
    const float inv1 = g_qmask[b * Tt + qrow0 + 8] / lrow1;
    float* AOg = g_AO + ((size_t)b * Tt + qrow0) * Uu + h * Dd;
#pragma unroll
    for (int ni = 0; ni < 16; ni++) {
        const int cc = 8 * ni + 2 * t;
        float2 o0, o1;
        o0.x = oacc[ni][0] * inv0; o0.y = oacc[ni][1] * inv0;
        o1.x = oacc[ni][2] * inv1; o1.y = oacc[ni][3] * inv1;
        *(float2*)(AOg + cc)                  = o0;
        *(float2*)(AOg + (size_t)8 * Uu + cc) = o1;
    }
}

// ---------------- residual + LayerNorm ------------------------------------------
__global__ void __launch_bounds__(256) ln_kernel(
    const float* __restrict__ Qin, const float* __restrict__ gamma,
    const float* __restrict__ beta, float* __restrict__ out) {
    __shared__ float red[2][8];
    const int row = blockIdx.x, tid = threadIdx.x;
    float4 a = ((const float4*)(g_AO + (size_t)row * 1024))[tid];
    float4 q = ((const float4*)(Qin + (size_t)row * 1024))[tid];
    float4 x;
    x.x = a.x + q.x; x.y = a.y + q.y; x.z = a.z + q.z; x.w = a.w + q.w;
    float s  = x.x + x.y + x.z + x.w;
    float ss = x.x * x.x + x.y * x.y + x.z * x.z + x.w * x.w;
#pragma unroll
    for (int off = 16; off; off >>= 1) {
        s  += __shfl_xor_sync(0xffffffffu, s, off);
        ss += __shfl_xor_sync(0xffffffffu, ss, off);
    }
    if ((tid & 31) == 0) { red[0][tid >> 5] = s; red[1][tid >> 5] = ss; }
    __syncthreads();
    s = 0.f; ss = 0.f;
#pragma unroll
    for (int w = 0; w < 8; w++) { s += red[0][w]; ss += red[1][w]; }
    const float mu = s * (1.0f / 1024.0f);
    const float var = ss * (1.0f / 1024.0f) - mu * mu;
    const float rstd = rsqrtf(var + 1e-5f);
    float4 g  = ((const float4*)gamma)[tid];
    float4 be = ((const float4*)beta)[tid];
    float4 o;
    o.x = (x.x - mu) * rstd * g.x + be.x;
    o.y = (x.y - mu) * rstd * g.y + be.y;
    o.z = (x.z - mu) * rstd * g.z + be.z;
    o.w = (x.w - mu) * rstd * g.w + be.w;
    ((float4*)(out + (size_t)row * 1024))[tid] = o;
}

// ---------------- launch ---------------------------------------------------------
extern "C" void kernel_launch(void* const* d_in, const int* in_sizes, int n_in,
                              void* d_out, int out_size) {
    const float* queries = (const float*)d_in[0];
    const float* keys    = (const float*)d_in[1];
    const float* values  = (const float*)d_in[2];
    const float* Wq = (const float*)d_in[3];
    const float* bq = (const float*)d_in[4];
    const float* Wk = (const float*)d_in[5];
    const float* bk = (const float*)d_in[6];
    const float* Wv = (const float*)d_in[7];
    const float* bv = (const float*)d_in[8];
    const float* gamma = (const float*)d_in[9];
    const float* beta  = (const float*)d_in[10];
    float* out = (float*)d_out;

    cudaFuncSetAttribute(attn_kernel, cudaFuncAttributeMaxDynamicSharedMemorySize,
                         (int)sizeof(ASmem));
    cudaFuncSetAttribute(gemm_bf16_kernel, cudaFuncAttributeMaxDynamicSharedMemorySize,
                         GEMM_SMEM);

    w_convert<<<dim3(32, 32, 3), 256>>>(Wq, Wk, Wv);
    a_convert<<<dim3(Bb * Tt, 3), 256>>>(queries, keys, values);

    gemm_bf16_kernel<<<dim3(8, 64, 3), 256, GEMM_SMEM>>>(bq, bk, bv);

    attn_kernel<<<dim3(Tt / 64, Bb, Hh), 128, sizeof(ASmem)>>>();

    ln_kernel<<<Bb * Tt, 256>>>(queries, gamma, beta, out);
}